// round 10
// baseline (speedup 1.0000x reference)
#include <cuda_runtime.h>
#include <cuda_bf16.h>
#include <mma.h>
#include <math.h>

using namespace nvcuda;

#define NN 50000
#define MP 50048   // padded rows: 391 * 128
#define NE 800000
#define NB1 196    // ceil(NN/256)
#define NBC 3125   // aggC grid = NN*16/256

// ---------------- scratch ----------------
static __device__ int   d_cnt[NN];
static __device__ int   d_rowptr[NN + 1];
static __device__ int   d_cursor[NN];
static __device__ int   d_csrc[NE];
static __device__ int   d_part[256];
static __device__ float d_xp[(size_t)NN * 32];
static __device__ float d_mx[(size_t)MP * 48];
static __device__ float d_wc1[256 * 48];
static __device__ float d_h1[(size_t)MP * 256];
static __device__ float d_wc2[256 * 256];
static __device__ float d_pq2[(size_t)MP * 256];  // [p(128)|q(128)] fp32
static __device__ unsigned int d_p2h[(size_t)NN * 64];  // p as packed bf16x2
static __device__ float d_h2[(size_t)MP * 128];
static __device__ float d_wc3[128 * 128];
static __device__ float d_pq3[(size_t)MP * 128];  // [p(64)|q(64)]
static __device__ float d_h3[(size_t)MP * 64];
static __device__ float d_w1p[128 * 64];
static __device__ float d_y1[(size_t)MP * 128];
static __device__ float d_m1[256 * 13 * 11 * 11];
static __device__ float d_xcol[(size_t)896 * 6912];
static __device__ float d_cg[896 * 128];
static __device__ float d_m2[128 * 891];
static __device__ float d_wmpart[8][64];
static __device__ float d_mnorm[64];
static __device__ float d_pmin[NBC];
static __device__ float d_pmax[NBC];
static __device__ float d_hstats[4];
static __device__ int   d_koff[6912];
static __device__ int   d_poff[896];

// ---------------- merged weight packing + im2col tables ----------------
__global__ void k_packAll(const float* __restrict__ Wl1, const float* __restrict__ Wr1,
                          const float* __restrict__ Wl2, const float* __restrict__ Wr2,
                          const float* __restrict__ Wl3, const float* __restrict__ Wr3,
                          const float* __restrict__ W1) {
    int i = blockIdx.x * blockDim.x + threadIdx.x;
    if (i < 12288) {
        int n = i / 48, f = i % 48;
        float v = 0.f;
        if (f < 21) v = Wl1[n * 21 + f];
        else if (f < 42) v = Wr1[n * 21 + (f - 21)];
        d_wc1[i] = v;
    } else if (i < 77824) {
        int j = i - 12288;
        int n = j / 256, f = j % 256;
        d_wc2[j] = (n < 128) ? Wl2[n * 256 + f] : Wr2[(n - 128) * 256 + f];
    } else if (i < 94208) {
        int j = i - 77824;
        int n = j / 128, f = j % 128;
        d_wc3[j] = (n < 64) ? Wl3[n * 128 + f] : Wr3[(n - 64) * 128 + f];
    } else if (i < 102400) {
        int j = i - 94208;
        int n = j / 64;
        d_w1p[j] = (n < 64) ? W1[j] : 0.f;
    } else if (i < 109312) {
        int j = i - 102400;
        int ic = j / 27, tap = j % 27;
        int kd = tap / 9, r = tap % 9, kh = r / 3, kw = r % 3;
        d_koff[j] = ic * 1573 + kd * 121 + kh * 11 + kw;
    } else if (i < 110208) {
        int j = i - 109312;
        int v = 0;
        if (j < 891) {
            int od = j / 81, r2 = j % 81, oh = r2 / 9, ow = r2 % 9;
            v = od * 121 + oh * 11 + ow;
        }
        d_poff[j] = v;
    }
}

// ---------------- CSR build ----------------
__global__ void k_degcnt(const int* __restrict__ ei) {
    int e = blockIdx.x * blockDim.x + threadIdx.x;
    if (e < NE) atomicAdd(&d_cnt[ei[NE + e]], 1);
}
__global__ void k_scan1() {
    __shared__ int sh[256];
    int t = threadIdx.x;
    int i = blockIdx.x * 256 + t;
    int v = (i < NN) ? d_cnt[i] : 0;
    sh[t] = v;
    __syncthreads();
#pragma unroll
    for (int off = 1; off < 256; off <<= 1) {
        int a = (t >= off) ? sh[t - off] : 0;
        __syncthreads();
        sh[t] += a;
        __syncthreads();
    }
    if (i < NN) d_rowptr[i] = sh[t] - v;
    if (t == 255) d_part[blockIdx.x] = sh[255];
}
__global__ void k_scan3() {
    __shared__ int sh[256];
    int t = threadIdx.x;
    int v = (t < NB1) ? d_part[t] : 0;
    sh[t] = v;
    __syncthreads();
#pragma unroll
    for (int off = 1; off < 256; off <<= 1) {
        int a = (t >= off) ? sh[t - off] : 0;
        __syncthreads();
        sh[t] += a;
        __syncthreads();
    }
    int base = (blockIdx.x > 0) ? sh[blockIdx.x - 1] : 0;
    int i = blockIdx.x * 256 + t;
    if (i < NN) {
        int r = d_rowptr[i] + base;
        d_rowptr[i] = r;
        d_cursor[i] = r;
    }
    if (i == 0) d_rowptr[NN] = NE;
}
__global__ void k_scatter(const int* __restrict__ ei) {
    int e = blockIdx.x * blockDim.x + threadIdx.x;
    if (e >= NE) return;
    int s = ei[e], d = ei[NE + e];
    int pos = atomicAdd(&d_cursor[d], 1);
    d_csrc[pos] = s;
}

// ---------------- node feature pad + aggregation ----------------
__global__ void k_xpad(const float* __restrict__ x) {
    int idx = blockIdx.x * blockDim.x + threadIdx.x;
    if (idx >= NN * 32) return;
    int n = idx >> 5, f = idx & 31;
    d_xp[idx] = (f < 21) ? x[n * 21 + f] : 0.f;
}
__global__ void k_aggA() {
    int w = (blockIdx.x * blockDim.x + threadIdx.x) >> 5;
    int lane = threadIdx.x & 31;
    if (w >= NN) return;
    int beg = d_rowptr[w], end = d_rowptr[w + 1];
    float acc = 0.f;
    int e = beg;
    for (; e + 4 <= end; e += 4) {
        int s0 = __ldg(&d_csrc[e]);
        int s1 = __ldg(&d_csrc[e + 1]);
        int s2 = __ldg(&d_csrc[e + 2]);
        int s3 = __ldg(&d_csrc[e + 3]);
        acc += d_xp[(size_t)s0 * 32 + lane] + d_xp[(size_t)s1 * 32 + lane] +
               d_xp[(size_t)s2 * 32 + lane] + d_xp[(size_t)s3 * 32 + lane];
    }
    for (; e < end; e++) acc += d_xp[(size_t)__ldg(&d_csrc[e]) * 32 + lane];
    float inv = 1.f / fmaxf((float)(end - beg), 1.0f);
    if (lane < 21) {
        d_mx[(size_t)w * 48 + lane] = acc * inv;
        d_mx[(size_t)w * 48 + 21 + lane] = d_xp[(size_t)w * 32 + lane];
    } else if (lane < 27) {
        d_mx[(size_t)w * 48 + 21 + lane] = 0.f;
    }
}
// convert p-half of pq2 to packed bf16 pairs
__global__ void k_cvtP() {
    int i = blockIdx.x * blockDim.x + threadIdx.x;
    if (i >= NN * 64) return;
    int n = i >> 6, j = i & 63;
    float2 v = *(const float2*)&d_pq2[(size_t)n * 256 + j * 2];
    __nv_bfloat162 h = __floats2bfloat162_rn(v.x, v.y);
    d_p2h[i] = *(unsigned int*)&h;
}
// warp per node; gathers bf16 p (256B/edge), fp32 q residual
__global__ void k_aggB(const float* __restrict__ bl) {
    int w = (blockIdx.x * blockDim.x + threadIdx.x) >> 5;
    int lane = threadIdx.x & 31;
    if (w >= NN) return;
    int beg = d_rowptr[w], end = d_rowptr[w + 1];
    float4 acc = make_float4(0.f, 0.f, 0.f, 0.f);
#pragma unroll 4
    for (int e = beg; e < end; e++) {
        int s = __ldg(&d_csrc[e]);
        uint2 v = *(const uint2*)&d_p2h[(size_t)s * 64 + (lane << 1)];
        float2 f0 = __bfloat1622float2(*(__nv_bfloat162*)&v.x);
        float2 f1 = __bfloat1622float2(*(__nv_bfloat162*)&v.y);
        acc.x += f0.x; acc.y += f0.y; acc.z += f1.x; acc.w += f1.y;
    }
    float inv = 1.f / fmaxf((float)(end - beg), 1.0f);
    const float4* pq = (const float4*)d_pq2;
    float4 q = pq[(size_t)w * 64 + 32 + lane];
    float4 b = ((const float4*)bl)[lane];
    float4 o;
    o.x = fmaxf(acc.x * inv + b.x + q.x, 0.f);
    o.y = fmaxf(acc.y * inv + b.y + q.y, 0.f);
    o.z = fmaxf(acc.z * inv + b.z + q.z, 0.f);
    o.w = fmaxf(acc.w * inv + b.w + q.w, 0.f);
    ((float4*)d_h2)[(size_t)w * 32 + lane] = o;
}
// 16 lanes per node + fused per-block min/max of h3
__global__ void k_aggC(const float* __restrict__ bl) {
    __shared__ float smn[256], smx[256];
    int tid = threadIdx.x;
    int g = (blockIdx.x * 256 + tid) >> 4;
    int lane = tid & 15;
    float lmn = 3.4e38f, lmx = -3.4e38f;
    if (g < NN) {
        int beg = d_rowptr[g], end = d_rowptr[g + 1];
        const float4* pq = (const float4*)d_pq3;
        float4 acc = make_float4(0.f, 0.f, 0.f, 0.f);
#pragma unroll 4
        for (int e = beg; e < end; e++) {
            int s = __ldg(&d_csrc[e]);
            float4 v = pq[(size_t)s * 32 + lane];
            acc.x += v.x; acc.y += v.y; acc.z += v.z; acc.w += v.w;
        }
        float inv = 1.f / fmaxf((float)(end - beg), 1.0f);
        float4 q = pq[(size_t)g * 32 + 16 + lane];
        float4 b = ((const float4*)bl)[lane];
        float4 o;
        o.x = acc.x * inv + b.x + q.x;
        o.y = acc.y * inv + b.y + q.y;
        o.z = acc.z * inv + b.z + q.z;
        o.w = acc.w * inv + b.w + q.w;
        ((float4*)d_h3)[(size_t)g * 16 + lane] = o;
        lmn = fminf(fminf(o.x, o.y), fminf(o.z, o.w));
        lmx = fmaxf(fmaxf(o.x, o.y), fmaxf(o.z, o.w));
    }
    smn[tid] = lmn; smx[tid] = lmx;
    __syncthreads();
    for (int st = 128; st > 0; st >>= 1) {
        if (tid < st) {
            smn[tid] = fminf(smn[tid], smn[tid + st]);
            smx[tid] = fmaxf(smx[tid], smx[tid + st]);
        }
        __syncthreads();
    }
    if (tid == 0) { d_pmin[blockIdx.x] = smn[0]; d_pmax[blockIdx.x] = smx[0]; }
}

// ---------------- tf32 tensor-core GEMM (round-6 proven version) ----------------
__global__ void __launch_bounds__(256, 2) k_tgemm(
    const float* __restrict__ A, const float* __restrict__ B, float* __restrict__ C,
    int N, int K, const float* __restrict__ abias,
    const float* __restrict__ xstats, const float* __restrict__ madd, int split) {
    __shared__ float As[2][128][20];
    __shared__ float Bs[2][128][20];
    int tid = threadIdx.x;
    int wid = tid >> 5;
    int lane = tid & 31;
    int bm = blockIdx.y * 128;
    int bn = blockIdx.x * 128;
    int wm = (wid >> 2) * 64;
    int wn = (wid & 3) * 32;
    int lrow = tid >> 1;
    int lcol = (tid & 1) * 8;
    int nkz = (K / 16) / gridDim.z;
    int kbase = blockIdx.z * nkz * 16;

    float hs0 = 0.f, hs1 = 0.f;
    if (xstats) { hs0 = xstats[0]; hs1 = xstats[1]; }

    wmma::fragment<wmma::accumulator, 16, 16, 8, float> cf[4][2];
#pragma unroll
    for (int i = 0; i < 4; i++)
#pragma unroll
        for (int j = 0; j < 2; j++) wmma::fill_fragment(cf[i][j], 0.f);

    const float* Arow = A + (size_t)(bm + lrow) * K + kbase + lcol;
    const float* Brow = B + (size_t)(bn + lrow) * K + kbase + lcol;

    float4 a0, a1, b0v, b1v;

#define CVT4(v)                                                                 \
    do {                                                                        \
        v.x = wmma::__float_to_tf32(v.x); v.y = wmma::__float_to_tf32(v.y);     \
        v.z = wmma::__float_to_tf32(v.z); v.w = wmma::__float_to_tf32(v.w);     \
    } while (0)

#define LOADTILE(koff)                                                          \
    do {                                                                        \
        a0 = *(const float4*)(Arow + (koff));                                   \
        a1 = *(const float4*)(Arow + (koff) + 4);                               \
        b0v = *(const float4*)(Brow + (koff));                                  \
        b1v = *(const float4*)(Brow + (koff) + 4);                              \
        if (abias) {                                                            \
            const float* bp = abias + kbase + (koff) + lcol;                    \
            a0.x = fmaxf(a0.x + bp[0], 0.f); a0.y = fmaxf(a0.y + bp[1], 0.f);   \
            a0.z = fmaxf(a0.z + bp[2], 0.f); a0.w = fmaxf(a0.w + bp[3], 0.f);   \
            a1.x = fmaxf(a1.x + bp[4], 0.f); a1.y = fmaxf(a1.y + bp[5], 0.f);   \
            a1.z = fmaxf(a1.z + bp[6], 0.f); a1.w = fmaxf(a1.w + bp[7], 0.f);   \
        } else if (xstats) {                                                    \
            const float* mp = madd + kbase + (koff) + lcol;                     \
            a0.x = hs0 * a0.x + hs1 + mp[0]; a0.y = hs0 * a0.y + hs1 + mp[1];   \
            a0.z = hs0 * a0.z + hs1 + mp[2]; a0.w = hs0 * a0.w + hs1 + mp[3];   \
            a1.x = hs0 * a1.x + hs1 + mp[4]; a1.y = hs0 * a1.y + hs1 + mp[5];   \
            a1.z = hs0 * a1.z + hs1 + mp[6]; a1.w = hs0 * a1.w + hs1 + mp[7];   \
        }                                                                       \
        CVT4(a0); CVT4(a1); CVT4(b0v); CVT4(b1v);                               \
    } while (0)

#define STORETILE(bi)                                                           \
    do {                                                                        \
        *(float4*)&As[bi][lrow][lcol] = a0;                                     \
        *(float4*)&As[bi][lrow][lcol + 4] = a1;                                 \
        *(float4*)&Bs[bi][lrow][lcol] = b0v;                                    \
        *(float4*)&Bs[bi][lrow][lcol + 4] = b1v;                                \
    } while (0)

    LOADTILE(0);
    STORETILE(0);
    __syncthreads();

    for (int it = 0; it < nkz; it++) {
        int buf = it & 1;
        bool more = (it + 1) < nkz;
        if (more) LOADTILE((it + 1) * 16);
#pragma unroll
        for (int ks = 0; ks < 16; ks += 8) {
            wmma::fragment<wmma::matrix_a, 16, 16, 8, wmma::precision::tf32, wmma::row_major> af[4];
            wmma::fragment<wmma::matrix_b, 16, 16, 8, wmma::precision::tf32, wmma::col_major> bf[2];
#pragma unroll
            for (int i = 0; i < 4; i++)
                wmma::load_matrix_sync(af[i], &As[buf][wm + i * 16][ks], 20);
#pragma unroll
            for (int j = 0; j < 2; j++)
                wmma::load_matrix_sync(bf[j], &Bs[buf][wn + j * 16][ks], 20);
#pragma unroll
            for (int i = 0; i < 4; i++)
#pragma unroll
                for (int j = 0; j < 2; j++)
                    wmma::mma_sync(cf[i][j], af[i], bf[j], cf[i][j]);
        }
        if (more) STORETILE(1 - buf);
        __syncthreads();
    }

    if (!split) {
#pragma unroll
        for (int i = 0; i < 4; i++)
#pragma unroll
            for (int j = 0; j < 2; j++)
                wmma::store_matrix_sync(&C[(size_t)(bm + wm + i * 16) * N + bn + wn + j * 16],
                                        cf[i][j], N, wmma::mem_row_major);
    } else {
        float* stage = &As[0][0][0] + wid * 320;
#pragma unroll
        for (int i = 0; i < 4; i++)
#pragma unroll
            for (int j = 0; j < 2; j++) {
                wmma::store_matrix_sync(stage, cf[i][j], 20, wmma::mem_row_major);
                __syncwarp();
                float* cp = &C[(size_t)(bm + wm + i * 16) * N + bn + wn + j * 16];
#pragma unroll
                for (int e = 0; e < 8; e++) {
                    int idx = lane * 8 + e;
                    int r = idx >> 4, c = idx & 15;
                    atomicAdd(&cp[(size_t)r * N + c], stage[r * 20 + c]);
                }
                __syncwarp();
            }
    }
#undef LOADTILE
#undef STORETILE
#undef CVT4
}

// ---------------- map encoder ----------------
__global__ void k_conv1(const float* __restrict__ in, const float* __restrict__ w,
                        const float* __restrict__ b) {
    int idx = blockIdx.x * blockDim.x + threadIdx.x;
    if (idx >= 256 * 1573) return;
    int oc = idx / 1573, p = idx % 1573;
    int od = p / 121, r = p % 121, oh = r / 11, ow = r % 11;
    const float* wp = w + oc * 75;
    float acc = 0.f;
#pragma unroll
    for (int kd = 0; kd < 3; kd++)
#pragma unroll
        for (int kh = 0; kh < 5; kh++)
#pragma unroll
            for (int kw = 0; kw < 5; kw++)
                acc += in[(od + kd) * 225 + (oh + kh) * 15 + (ow + kw)] *
                       wp[kd * 25 + kh * 5 + kw];
    d_m1[idx] = fmaxf(acc + b[oc], 0.f);
}

__global__ void k_im2col() {
    int k = blockIdx.x * 256 + threadIdx.x;
    int pos = blockIdx.y;
    d_xcol[(size_t)pos * 6912 + k] = d_m1[d_koff[k] + d_poff[pos]];
}

__global__ void k_m2fin(const float* __restrict__ cb2) {
    int idx = blockIdx.x * blockDim.x + threadIdx.x;
    if (idx >= 128 * 891) return;
    int oc = idx / 891, pos = idx % 891;
    d_m2[idx] = fmaxf(d_cg[(size_t)pos * 128 + oc] + cb2[oc], 0.f);
}

__global__ void k_wm(const float* __restrict__ Wm) {
    __shared__ float red[256];
    int o = blockIdx.x;
    int chunk = blockIdx.y;
    const int CH = 114048 / 8;
    int base = chunk * CH;
    const float* wr = Wm + (size_t)o * 114048 + base;
    const float* mv = d_m2 + base;
    float s = 0.f;
    for (int i = threadIdx.x * 4; i < CH; i += 256 * 4) {
        float4 a = *(const float4*)(wr + i);
        float4 v = *(const float4*)(mv + i);
        s += a.x * v.x + a.y * v.y + a.z * v.z + a.w * v.w;
    }
    red[threadIdx.x] = s;
    __syncthreads();
    for (int st = 128; st > 0; st >>= 1) {
        if (threadIdx.x < st) red[threadIdx.x] += red[threadIdx.x + st];
        __syncthreads();
    }
    if (threadIdx.x == 0) d_wmpart[chunk][o] = red[0];
}

// ---------------- final stats (h3 minmax from aggC partials + m norm) ---------
__global__ void k_finstats(const float* __restrict__ bm) {
    __shared__ float smn[256], smx[256];
    int t = threadIdx.x;
    float mn = 3.4e38f, mx = -3.4e38f;
    for (int i = t; i < NBC; i += 256) {
        mn = fminf(mn, d_pmin[i]);
        mx = fmaxf(mx, d_pmax[i]);
    }
    smn[t] = mn; smx[t] = mx;
    __syncthreads();
    for (int st = 128; st > 0; st >>= 1) {
        if (t < st) {
            smn[t] = fminf(smn[t], smn[t + st]);
            smx[t] = fmaxf(smx[t], smx[t + st]);
        }
        __syncthreads();
    }
    if (t == 0) {
        float lo = smn[0], hi = smx[0];
        float a = 0.35f / (hi - lo);
        d_hstats[0] = a;
        d_hstats[1] = -lo * a;
    }
    __syncthreads();
    float v = 0.f;
    if (t < 64) {
        v = bm[t];
#pragma unroll
        for (int c = 0; c < 8; c++) v += d_wmpart[c][t];
    }
    smn[t] = (t < 64) ? v : 3.4e38f;
    smx[t] = (t < 64) ? v : -3.4e38f;
    __syncthreads();
    for (int st = 128; st > 0; st >>= 1) {
        if (t < st) {
            smn[t] = fminf(smn[t], smn[t + st]);
            smx[t] = fmaxf(smx[t], smx[t + st]);
        }
        __syncthreads();
    }
    if (t < 64) {
        float lo = smn[0], hi = smx[0];
        d_mnorm[t] = 0.65f * (v - lo) / (hi - lo);
    }
}

// ---------------- final layer + softmax ----------------
__global__ void k_head(const float* __restrict__ W2, const float* __restrict__ b2,
                       const float* __restrict__ b1, float* __restrict__ out) {
    __shared__ float w2s[3][64];
    __shared__ float b2s[3];
    __shared__ float b1s[64];
    int tid = threadIdx.x;
    if (tid < 192) w2s[tid / 64][tid % 64] = W2[tid];
    if (tid < 3) b2s[tid] = b2[tid];
    if (tid >= 192 && tid < 256) b1s[tid - 192] = b1[tid - 192];
    __syncthreads();
    int i = blockIdx.x * blockDim.x + tid;
    if (i >= NN) return;
    const float* y = d_y1 + (size_t)i * 128;
    float s0 = b2s[0], s1 = b2s[1], s2 = b2s[2];
#pragma unroll
    for (int f = 0; f < 64; f += 4) {
        float4 v = *(const float4*)(y + f);
        v.x = fmaxf(v.x + b1s[f], 0.f);
        v.y = fmaxf(v.y + b1s[f + 1], 0.f);
        v.z = fmaxf(v.z + b1s[f + 2], 0.f);
        v.w = fmaxf(v.w + b1s[f + 3], 0.f);
        s0 += v.x * w2s[0][f] + v.y * w2s[0][f + 1] + v.z * w2s[0][f + 2] + v.w * w2s[0][f + 3];
        s1 += v.x * w2s[1][f] + v.y * w2s[1][f + 1] + v.z * w2s[1][f + 2] + v.w * w2s[1][f + 3];
        s2 += v.x * w2s[2][f] + v.y * w2s[2][f + 1] + v.z * w2s[2][f + 2] + v.w * w2s[2][f + 3];
    }
    float m = fmaxf(s0, fmaxf(s1, s2));
    float e0 = expf(s0 - m), e1 = expf(s1 - m), e2 = expf(s2 - m);
    float inv = 1.f / (e0 + e1 + e2);
    out[(size_t)i * 3 + 0] = e0 * inv;
    out[(size_t)i * 3 + 1] = e1 * inv;
    out[(size_t)i * 3 + 2] = e2 * inv;
}

// ---------------- launch ----------------
extern "C" void kernel_launch(void* const* d_in, const int* in_sizes, int n_in,
                              void* d_out, int out_size) {
    (void)in_sizes; (void)n_in; (void)out_size;
    const float* node = (const float*)d_in[0];
    const int* ei = (const int*)d_in[1];
    const float* mapd = (const float*)d_in[2];
    const float* bl1 = (const float*)d_in[4];
    const float* bl2 = (const float*)d_in[7];
    const float* bl3 = (const float*)d_in[10];
    const float* k1 = (const float*)d_in[12];
    const float* cb1 = (const float*)d_in[13];
    const float* k2 = (const float*)d_in[14];
    const float* cb2 = (const float*)d_in[15];
    const float* Wm = (const float*)d_in[16];
    const float* bm = (const float*)d_in[17];
    const float* b1 = (const float*)d_in[19];
    const float* W2 = (const float*)d_in[20];
    const float* b2 = (const float*)d_in[21];
    float* out = (float*)d_out;

    void *p_cnt, *p_cg;
    void *p_mx, *p_wc1, *p_h1, *p_wc2, *p_pq2, *p_h2, *p_wc3, *p_pq3, *p_h3;
    void *p_w1p, *p_y1, *p_xcol, *p_hstats, *p_mnorm;
    cudaGetSymbolAddress(&p_cnt, d_cnt);
    cudaGetSymbolAddress(&p_cg, d_cg);
    cudaGetSymbolAddress(&p_mx, d_mx);
    cudaGetSymbolAddress(&p_wc1, d_wc1);
    cudaGetSymbolAddress(&p_h1, d_h1);
    cudaGetSymbolAddress(&p_wc2, d_wc2);
    cudaGetSymbolAddress(&p_pq2, d_pq2);
    cudaGetSymbolAddress(&p_h2, d_h2);
    cudaGetSymbolAddress(&p_wc3, d_wc3);
    cudaGetSymbolAddress(&p_pq3, d_pq3);
    cudaGetSymbolAddress(&p_h3, d_h3);
    cudaGetSymbolAddress(&p_w1p, d_w1p);
    cudaGetSymbolAddress(&p_y1, d_y1);
    cudaGetSymbolAddress(&p_xcol, d_xcol);
    cudaGetSymbolAddress(&p_hstats, d_hstats);
    cudaGetSymbolAddress(&p_mnorm, d_mnorm);

    cudaStream_t s2;
    cudaStreamCreateWithFlags(&s2, cudaStreamNonBlocking);
    cudaEvent_t evFork, evJoin;
    cudaEventCreateWithFlags(&evFork, cudaEventDisableTiming);
    cudaEventCreateWithFlags(&evJoin, cudaEventDisableTiming);

    // 1: memset(cnt)  2: memset(cg)  3: packAll
    cudaMemsetAsync(p_cnt, 0, NN * sizeof(int));
    cudaMemsetAsync(p_cg, 0, 896 * 128 * sizeof(float));
    k_packAll<<<431, 256>>>((const float*)d_in[3], (const float*)d_in[5],
                            (const float*)d_in[6], (const float*)d_in[8],
                            (const float*)d_in[9], (const float*)d_in[11],
                            (const float*)d_in[18]);

    // fork conv path onto s2
    cudaEventRecord(evFork, 0);
    cudaStreamWaitEvent(s2, evFork, 0);

    // conv path on s2: 4 conv1, 5 im2col, 6 conv2 tgemm (ncu target), 7 m2fin, 8 wm
    k_conv1<<<(256 * 1573 + 255) / 256, 256, 0, s2>>>(mapd, k1, cb1);
    k_im2col<<<dim3(27, 891), 256, 0, s2>>>();
    k_tgemm<<<dim3(1, 7, 16), 256, 0, s2>>>((const float*)p_xcol, k2, (float*)p_cg,
                                            128, 6912, nullptr, nullptr, nullptr, 1);
    k_m2fin<<<(128 * 891 + 255) / 256, 256, 0, s2>>>(cb2);
    k_wm<<<dim3(64, 8), 256, 0, s2>>>(Wm);
    cudaEventRecord(evJoin, s2);

    // GNN path on main stream (overlaps with s2)
    k_degcnt<<<(NE + 255) / 256, 256>>>(ei);
    k_scan1<<<NB1, 256>>>();
    k_scan3<<<NB1, 256>>>();
    k_scatter<<<(NE + 255) / 256, 256>>>(ei);

    k_xpad<<<(NN * 32 + 255) / 256, 256>>>(node);
    k_aggA<<<(NN * 32 + 255) / 256, 256>>>();
    k_tgemm<<<dim3(2, 391, 1), 256>>>((const float*)p_mx, (const float*)p_wc1,
                                      (float*)p_h1, 256, 48,
                                      nullptr, nullptr, nullptr, 0);
    k_tgemm<<<dim3(2, 391, 1), 256>>>((const float*)p_h1, (const float*)p_wc2,
                                      (float*)p_pq2, 256, 256,
                                      bl1, nullptr, nullptr, 0);
    k_cvtP<<<(NN * 64 + 255) / 256, 256>>>();
    k_aggB<<<(NN * 32 + 255) / 256, 256>>>(bl2);
    k_tgemm<<<dim3(1, 391, 1), 256>>>((const float*)p_h2, (const float*)p_wc3,
                                      (float*)p_pq3, 128, 128,
                                      nullptr, nullptr, nullptr, 0);
    k_aggC<<<NBC, 256>>>(bl3);

    // join conv path before finstats (needs d_wmpart)
    cudaStreamWaitEvent(0, evJoin, 0);
    k_finstats<<<1, 256>>>(bm);
    k_tgemm<<<dim3(1, 391, 1), 256>>>((const float*)p_h3, (const float*)p_w1p,
                                      (float*)p_y1, 128, 64,
                                      nullptr, (const float*)p_hstats,
                                      (const float*)p_mnorm, 0);
    k_head<<<(NN + 255) / 256, 256>>>(W2, b2, b1, out);

    cudaEventDestroy(evFork);
    cudaEventDestroy(evJoin);
    cudaStreamDestroy(s2);
}

// round 12
// speedup vs baseline: 1.0249x; 1.0249x over previous
#include <cuda_runtime.h>
#include <cuda_bf16.h>
#include <mma.h>
#include <math.h>

using namespace nvcuda;

#define NN 50000
#define MP 50048   // padded rows: 391 * 128
#define NE 800000
#define NB1 196    // ceil(NN/256)
#define NBC 3125   // aggC grid = NN*16/256

// ---------------- scratch ----------------
static __device__ int   d_cnt[NN];
static __device__ int   d_rowptr[NN + 1];
static __device__ int   d_cursor[NN];
static __device__ int   d_csrc[NE];
static __device__ int   d_part[256];
static __device__ float d_xp[(size_t)NN * 32];
static __device__ float d_mx[(size_t)MP * 48];
static __device__ float d_wc1[256 * 48];
static __device__ float d_h1[(size_t)MP * 256];
static __device__ float d_wc2[256 * 256];
static __device__ float d_pq2[(size_t)MP * 256];        // q half (128..255) fp32; p half unused
static __device__ unsigned int d_p2h[(size_t)MP * 64];  // p as packed bf16x2 (written by GEMM2)
static __device__ float d_h2[(size_t)MP * 128];
static __device__ float d_wc3[128 * 128];
static __device__ float d_pq3[(size_t)MP * 128];  // [p(64)|q(64)]
static __device__ float d_h3[(size_t)MP * 64];
static __device__ float d_w1p[128 * 64];
static __device__ float d_y1[(size_t)MP * 128];
static __device__ float d_m1[256 * 13 * 11 * 11];
static __device__ float d_xcol[(size_t)896 * 6912];
static __device__ float d_cg[896 * 128];
static __device__ float d_m2[128 * 891];
static __device__ float d_wmpart[8][64];
static __device__ float d_mnorm[64];
static __device__ float d_pmin[NBC];
static __device__ float d_pmax[NBC];
static __device__ float d_hstats[4];
static __device__ int   d_koff[6912];
static __device__ int   d_poff[896];

// ---------------- merged weight packing + im2col tables ----------------
__global__ void k_packAll(const float* __restrict__ Wl1, const float* __restrict__ Wr1,
                          const float* __restrict__ Wl2, const float* __restrict__ Wr2,
                          const float* __restrict__ Wl3, const float* __restrict__ Wr3,
                          const float* __restrict__ W1) {
    int i = blockIdx.x * blockDim.x + threadIdx.x;
    if (i < 12288) {
        int n = i / 48, f = i % 48;
        float v = 0.f;
        if (f < 21) v = Wl1[n * 21 + f];
        else if (f < 42) v = Wr1[n * 21 + (f - 21)];
        d_wc1[i] = v;
    } else if (i < 77824) {
        int j = i - 12288;
        int n = j / 256, f = j % 256;
        d_wc2[j] = (n < 128) ? Wl2[n * 256 + f] : Wr2[(n - 128) * 256 + f];
    } else if (i < 94208) {
        int j = i - 77824;
        int n = j / 128, f = j % 128;
        d_wc3[j] = (n < 64) ? Wl3[n * 128 + f] : Wr3[(n - 64) * 128 + f];
    } else if (i < 102400) {
        int j = i - 94208;
        int n = j / 64;
        d_w1p[j] = (n < 64) ? W1[j] : 0.f;
    } else if (i < 109312) {
        int j = i - 102400;
        int ic = j / 27, tap = j % 27;
        int kd = tap / 9, r = tap % 9, kh = r / 3, kw = r % 3;
        d_koff[j] = ic * 1573 + kd * 121 + kh * 11 + kw;
    } else if (i < 110208) {
        int j = i - 109312;
        int v = 0;
        if (j < 891) {
            int od = j / 81, r2 = j % 81, oh = r2 / 9, ow = r2 % 9;
            v = od * 121 + oh * 11 + ow;
        }
        d_poff[j] = v;
    }
}

// ---------------- CSR build ----------------
__global__ void k_degcnt(const int* __restrict__ ei) {
    int e = blockIdx.x * blockDim.x + threadIdx.x;
    if (e < NE) atomicAdd(&d_cnt[ei[NE + e]], 1);
}
__global__ void k_scan1() {
    __shared__ int sh[256];
    int t = threadIdx.x;
    int i = blockIdx.x * 256 + t;
    int v = (i < NN) ? d_cnt[i] : 0;
    sh[t] = v;
    __syncthreads();
#pragma unroll
    for (int off = 1; off < 256; off <<= 1) {
        int a = (t >= off) ? sh[t - off] : 0;
        __syncthreads();
        sh[t] += a;
        __syncthreads();
    }
    if (i < NN) d_rowptr[i] = sh[t] - v;
    if (t == 255) d_part[blockIdx.x] = sh[255];
}
__global__ void k_scan3() {
    __shared__ int sh[256];
    int t = threadIdx.x;
    int v = (t < NB1) ? d_part[t] : 0;
    sh[t] = v;
    __syncthreads();
#pragma unroll
    for (int off = 1; off < 256; off <<= 1) {
        int a = (t >= off) ? sh[t - off] : 0;
        __syncthreads();
        sh[t] += a;
        __syncthreads();
    }
    int base = (blockIdx.x > 0) ? sh[blockIdx.x - 1] : 0;
    int i = blockIdx.x * 256 + t;
    if (i < NN) {
        int r = d_rowptr[i] + base;
        d_rowptr[i] = r;
        d_cursor[i] = r;
    }
    if (i == 0) d_rowptr[NN] = NE;
}
__global__ void k_scatter(const int* __restrict__ ei) {
    int e = blockIdx.x * blockDim.x + threadIdx.x;
    if (e >= NE) return;
    int s = ei[e], d = ei[NE + e];
    int pos = atomicAdd(&d_cursor[d], 1);
    d_csrc[pos] = s;
}

// ---------------- node feature pad + aggregation ----------------
__global__ void k_xpad(const float* __restrict__ x) {
    int idx = blockIdx.x * blockDim.x + threadIdx.x;
    if (idx >= NN * 32) return;
    int n = idx >> 5, f = idx & 31;
    d_xp[idx] = (f < 21) ? x[n * 21 + f] : 0.f;
}
// warp per node; 8 lanes per edge (float4/lane), 4 edges in flight
__global__ void k_aggA() {
    int w = (blockIdx.x * blockDim.x + threadIdx.x) >> 5;
    int lane = threadIdx.x & 31;
    int sub = lane >> 3;     // edge slot 0..3
    int sl = lane & 7;       // 4-feat group within row
    if (w >= NN) return;
    int beg = d_rowptr[w], end = d_rowptr[w + 1];
    float4 acc = make_float4(0.f, 0.f, 0.f, 0.f);
#pragma unroll 2
    for (int e = beg + sub; e < end; e += 4) {
        int s = __ldg(&d_csrc[e]);
        float4 v = *(const float4*)&d_xp[(size_t)s * 32 + sl * 4];
        acc.x += v.x; acc.y += v.y; acc.z += v.z; acc.w += v.w;
    }
    // reduce 4 edge-slots
    acc.x += __shfl_xor_sync(0xffffffffu, acc.x, 8);
    acc.y += __shfl_xor_sync(0xffffffffu, acc.y, 8);
    acc.z += __shfl_xor_sync(0xffffffffu, acc.z, 8);
    acc.w += __shfl_xor_sync(0xffffffffu, acc.w, 8);
    acc.x += __shfl_xor_sync(0xffffffffu, acc.x, 16);
    acc.y += __shfl_xor_sync(0xffffffffu, acc.y, 16);
    acc.z += __shfl_xor_sync(0xffffffffu, acc.z, 16);
    acc.w += __shfl_xor_sync(0xffffffffu, acc.w, 16);
    float inv = 1.f / fmaxf((float)(end - beg), 1.0f);
    if (sub == 0) {  // lanes 0..7 hold feats [4sl, 4sl+4)
        float m[4] = {acc.x * inv, acc.y * inv, acc.z * inv, acc.w * inv};
#pragma unroll
        for (int c = 0; c < 4; c++) {
            int f = sl * 4 + c;
            if (f < 21) d_mx[(size_t)w * 48 + f] = m[c];
        }
    }
    float xo = d_xp[(size_t)w * 32 + lane];
    if (lane < 21) d_mx[(size_t)w * 48 + 21 + lane] = xo;
    else if (lane < 27) d_mx[(size_t)w * 48 + 21 + lane] = 0.f;
}
// warp per node; half-warp per edge, uint4 (8 bf16 feats)/lane, 2 edges in flight
__global__ void k_aggB(const float* __restrict__ bl) {
    int w = (blockIdx.x * blockDim.x + threadIdx.x) >> 5;
    int lane = threadIdx.x & 31;
    int half = lane >> 4;
    int sl = lane & 15;      // 8-feat group [8sl, 8sl+8)
    if (w >= NN) return;
    int beg = d_rowptr[w], end = d_rowptr[w + 1];
    float4 a0 = make_float4(0.f, 0.f, 0.f, 0.f);
    float4 a1 = make_float4(0.f, 0.f, 0.f, 0.f);
#pragma unroll 2
    for (int e = beg + half; e < end; e += 2) {
        int s = __ldg(&d_csrc[e]);
        uint4 v = *(const uint4*)&d_p2h[(size_t)s * 64 + sl * 4];
        float2 f0 = __bfloat1622float2(*(__nv_bfloat162*)&v.x);
        float2 f1 = __bfloat1622float2(*(__nv_bfloat162*)&v.y);
        float2 f2 = __bfloat1622float2(*(__nv_bfloat162*)&v.z);
        float2 f3 = __bfloat1622float2(*(__nv_bfloat162*)&v.w);
        a0.x += f0.x; a0.y += f0.y; a0.z += f1.x; a0.w += f1.y;
        a1.x += f2.x; a1.y += f2.y; a1.z += f3.x; a1.w += f3.y;
    }
    // combine the two half-warps
    a0.x += __shfl_xor_sync(0xffffffffu, a0.x, 16);
    a0.y += __shfl_xor_sync(0xffffffffu, a0.y, 16);
    a0.z += __shfl_xor_sync(0xffffffffu, a0.z, 16);
    a0.w += __shfl_xor_sync(0xffffffffu, a0.w, 16);
    a1.x += __shfl_xor_sync(0xffffffffu, a1.x, 16);
    a1.y += __shfl_xor_sync(0xffffffffu, a1.y, 16);
    a1.z += __shfl_xor_sync(0xffffffffu, a1.z, 16);
    a1.w += __shfl_xor_sync(0xffffffffu, a1.w, 16);
    if (half == 0) {
        float inv = 1.f / fmaxf((float)(end - beg), 1.0f);
        const float4* pq = (const float4*)d_pq2;
        float4 q0 = pq[(size_t)w * 64 + 32 + sl * 2];
        float4 q1 = pq[(size_t)w * 64 + 32 + sl * 2 + 1];
        float4 b0 = ((const float4*)bl)[sl * 2];
        float4 b1 = ((const float4*)bl)[sl * 2 + 1];
        float4 o0, o1;
        o0.x = fmaxf(a0.x * inv + b0.x + q0.x, 0.f);
        o0.y = fmaxf(a0.y * inv + b0.y + q0.y, 0.f);
        o0.z = fmaxf(a0.z * inv + b0.z + q0.z, 0.f);
        o0.w = fmaxf(a0.w * inv + b0.w + q0.w, 0.f);
        o1.x = fmaxf(a1.x * inv + b1.x + q1.x, 0.f);
        o1.y = fmaxf(a1.y * inv + b1.y + q1.y, 0.f);
        o1.z = fmaxf(a1.z * inv + b1.z + q1.z, 0.f);
        o1.w = fmaxf(a1.w * inv + b1.w + q1.w, 0.f);
        ((float4*)d_h2)[(size_t)w * 32 + sl * 2] = o0;
        ((float4*)d_h2)[(size_t)w * 32 + sl * 2 + 1] = o1;
    }
}
// 16 lanes per node + fused per-block min/max of h3
__global__ void k_aggC(const float* __restrict__ bl) {
    __shared__ float smn[256], smx[256];
    int tid = threadIdx.x;
    int g = (blockIdx.x * 256 + tid) >> 4;
    int lane = tid & 15;
    float lmn = 3.4e38f, lmx = -3.4e38f;
    if (g < NN) {
        int beg = d_rowptr[g], end = d_rowptr[g + 1];
        const float4* pq = (const float4*)d_pq3;
        float4 acc = make_float4(0.f, 0.f, 0.f, 0.f);
#pragma unroll 4
        for (int e = beg; e < end; e++) {
            int s = __ldg(&d_csrc[e]);
            float4 v = pq[(size_t)s * 32 + lane];
            acc.x += v.x; acc.y += v.y; acc.z += v.z; acc.w += v.w;
        }
        float inv = 1.f / fmaxf((float)(end - beg), 1.0f);
        float4 q = pq[(size_t)g * 32 + 16 + lane];
        float4 b = ((const float4*)bl)[lane];
        float4 o;
        o.x = acc.x * inv + b.x + q.x;
        o.y = acc.y * inv + b.y + q.y;
        o.z = acc.z * inv + b.z + q.z;
        o.w = acc.w * inv + b.w + q.w;
        ((float4*)d_h3)[(size_t)g * 16 + lane] = o;
        lmn = fminf(fminf(o.x, o.y), fminf(o.z, o.w));
        lmx = fmaxf(fmaxf(o.x, o.y), fmaxf(o.z, o.w));
    }
    smn[tid] = lmn; smx[tid] = lmx;
    __syncthreads();
    for (int st = 128; st > 0; st >>= 1) {
        if (tid < st) {
            smn[tid] = fminf(smn[tid], smn[tid + st]);
            smx[tid] = fmaxf(smx[tid], smx[tid + st]);
        }
        __syncthreads();
    }
    if (tid == 0) { d_pmin[blockIdx.x] = smn[0]; d_pmax[blockIdx.x] = smx[0]; }
}

// ---------------- tf32 tensor-core GEMM ----------------
// bfp!=0: tiles with blockIdx.x==0 (cols 0..127) are packed to bf16 pairs into
// d_p2h (fp32 store skipped); other tiles store fp32 to C.
__global__ void __launch_bounds__(256, 2) k_tgemm(
    const float* __restrict__ A, const float* __restrict__ B, float* __restrict__ C,
    int N, int K, const float* __restrict__ abias,
    const float* __restrict__ xstats, const float* __restrict__ madd,
    int split, int bfp) {
    __shared__ float As[2][128][20];
    __shared__ float Bs[2][128][20];
    int tid = threadIdx.x;
    int wid = tid >> 5;
    int lane = tid & 31;
    int bm = blockIdx.y * 128;
    int bn = blockIdx.x * 128;
    int wm = (wid >> 2) * 64;
    int wn = (wid & 3) * 32;
    int lrow = tid >> 1;
    int lcol = (tid & 1) * 8;
    int nkz = (K / 16) / gridDim.z;
    int kbase = blockIdx.z * nkz * 16;

    float hs0 = 0.f, hs1 = 0.f;
    if (xstats) { hs0 = xstats[0]; hs1 = xstats[1]; }

    wmma::fragment<wmma::accumulator, 16, 16, 8, float> cf[4][2];
#pragma unroll
    for (int i = 0; i < 4; i++)
#pragma unroll
        for (int j = 0; j < 2; j++) wmma::fill_fragment(cf[i][j], 0.f);

    const float* Arow = A + (size_t)(bm + lrow) * K + kbase + lcol;
    const float* Brow = B + (size_t)(bn + lrow) * K + kbase + lcol;

    float4 a0, a1, b0v, b1v;

#define CVT4(v)                                                                 \
    do {                                                                        \
        v.x = wmma::__float_to_tf32(v.x); v.y = wmma::__float_to_tf32(v.y);     \
        v.z = wmma::__float_to_tf32(v.z); v.w = wmma::__float_to_tf32(v.w);     \
    } while (0)

#define LOADTILE(koff)                                                          \
    do {                                                                        \
        a0 = *(const float4*)(Arow + (koff));                                   \
        a1 = *(const float4*)(Arow + (koff) + 4);                               \
        b0v = *(const float4*)(Brow + (koff));                                  \
        b1v = *(const float4*)(Brow + (koff) + 4);                              \
        if (abias) {                                                            \
            const float* bp = abias + kbase + (koff) + lcol;                    \
            a0.x = fmaxf(a0.x + bp[0], 0.f); a0.y = fmaxf(a0.y + bp[1], 0.f);   \
            a0.z = fmaxf(a0.z + bp[2], 0.f); a0.w = fmaxf(a0.w + bp[3], 0.f);   \
            a1.x = fmaxf(a1.x + bp[4], 0.f); a1.y = fmaxf(a1.y + bp[5], 0.f);   \
            a1.z = fmaxf(a1.z + bp[6], 0.f); a1.w = fmaxf(a1.w + bp[7], 0.f);   \
        } else if (xstats) {                                                    \
            const float* mp = madd + kbase + (koff) + lcol;                     \
            a0.x = hs0 * a0.x + hs1 + mp[0]; a0.y = hs0 * a0.y + hs1 + mp[1];   \
            a0.z = hs0 * a0.z + hs1 + mp[2]; a0.w = hs0 * a0.w + hs1 + mp[3];   \
            a1.x = hs0 * a1.x + hs1 + mp[4]; a1.y = hs0 * a1.y + hs1 + mp[5];   \
            a1.z = hs0 * a1.z + hs1 + mp[6]; a1.w = hs0 * a1.w + hs1 + mp[7];   \
        }                                                                       \
        CVT4(a0); CVT4(a1); CVT4(b0v); CVT4(b1v);                               \
    } while (0)

#define STORETILE(bi)                                                           \
    do {                                                                        \
        *(float4*)&As[bi][lrow][lcol] = a0;                                     \
        *(float4*)&As[bi][lrow][lcol + 4] = a1;                                 \
        *(float4*)&Bs[bi][lrow][lcol] = b0v;                                    \
        *(float4*)&Bs[bi][lrow][lcol + 4] = b1v;                                \
    } while (0)

    LOADTILE(0);
    STORETILE(0);
    __syncthreads();

    for (int it = 0; it < nkz; it++) {
        int buf = it & 1;
        bool more = (it + 1) < nkz;
        if (more) LOADTILE((it + 1) * 16);
#pragma unroll
        for (int ks = 0; ks < 16; ks += 8) {
            wmma::fragment<wmma::matrix_a, 16, 16, 8, wmma::precision::tf32, wmma::row_major> af[4];
            wmma::fragment<wmma::matrix_b, 16, 16, 8, wmma::precision::tf32, wmma::col_major> bf[2];
#pragma unroll
            for (int i = 0; i < 4; i++)
                wmma::load_matrix_sync(af[i], &As[buf][wm + i * 16][ks], 20);
#pragma unroll
            for (int j = 0; j < 2; j++)
                wmma::load_matrix_sync(bf[j], &Bs[buf][wn + j * 16][ks], 20);
#pragma unroll
            for (int i = 0; i < 4; i++)
#pragma unroll
                for (int j = 0; j < 2; j++)
                    wmma::mma_sync(cf[i][j], af[i], bf[j], cf[i][j]);
        }
        if (more) STORETILE(1 - buf);
        __syncthreads();
    }

    if (!split) {
        if (bfp && blockIdx.x == 0) {
            // pack p-half to bf16 pairs into d_p2h via smem staging
            float* stage = &As[0][0][0] + wid * 320;
            int r = lane >> 1, cu = (lane & 1) * 4;
#pragma unroll
            for (int i = 0; i < 4; i++)
#pragma unroll
                for (int j = 0; j < 2; j++) {
                    wmma::store_matrix_sync(stage, cf[i][j], 20, wmma::mem_row_major);
                    __syncwarp();
                    const float* sp = stage + r * 20 + cu * 2;
                    unsigned int o[4];
#pragma unroll
                    for (int t = 0; t < 4; t++) {
                        __nv_bfloat162 h = __floats2bfloat162_rn(sp[2 * t], sp[2 * t + 1]);
                        o[t] = *(unsigned int*)&h;
                    }
                    *(uint4*)&d_p2h[(size_t)(bm + wm + i * 16 + r) * 64 +
                                    ((wn + j * 16) >> 1) + cu] =
                        make_uint4(o[0], o[1], o[2], o[3]);
                    __syncwarp();
                }
        } else {
#pragma unroll
            for (int i = 0; i < 4; i++)
#pragma unroll
                for (int j = 0; j < 2; j++)
                    wmma::store_matrix_sync(&C[(size_t)(bm + wm + i * 16) * N + bn + wn + j * 16],
                                            cf[i][j], N, wmma::mem_row_major);
        }
    } else {
        float* stage = &As[0][0][0] + wid * 320;
#pragma unroll
        for (int i = 0; i < 4; i++)
#pragma unroll
            for (int j = 0; j < 2; j++) {
                wmma::store_matrix_sync(stage, cf[i][j], 20, wmma::mem_row_major);
                __syncwarp();
                float* cp = &C[(size_t)(bm + wm + i * 16) * N + bn + wn + j * 16];
#pragma unroll
                for (int e = 0; e < 8; e++) {
                    int idx = lane * 8 + e;
                    int r2 = idx >> 4, c2 = idx & 15;
                    atomicAdd(&cp[(size_t)r2 * N + c2], stage[r2 * 20 + c2]);
                }
                __syncwarp();
            }
    }
#undef LOADTILE
#undef STORETILE
#undef CVT4
}

// ---------------- map encoder ----------------
__global__ void k_conv1(const float* __restrict__ in, const float* __restrict__ w,
                        const float* __restrict__ b) {
    int idx = blockIdx.x * blockDim.x + threadIdx.x;
    if (idx >= 256 * 1573) return;
    int oc = idx / 1573, p = idx % 1573;
    int od = p / 121, r = p % 121, oh = r / 11, ow = r % 11;
    const float* wp = w + oc * 75;
    float acc = 0.f;
#pragma unroll
    for (int kd = 0; kd < 3; kd++)
#pragma unroll
        for (int kh = 0; kh < 5; kh++)
#pragma unroll
            for (int kw = 0; kw < 5; kw++)
                acc += in[(od + kd) * 225 + (oh + kh) * 15 + (ow + kw)] *
                       wp[kd * 25 + kh * 5 + kw];
    d_m1[idx] = fmaxf(acc + b[oc], 0.f);
}

__global__ void k_im2col() {
    int k = blockIdx.x * 256 + threadIdx.x;
    int pos = blockIdx.y;
    d_xcol[(size_t)pos * 6912 + k] = d_m1[d_koff[k] + d_poff[pos]];
}

__global__ void k_m2fin(const float* __restrict__ cb2) {
    int idx = blockIdx.x * blockDim.x + threadIdx.x;
    if (idx >= 128 * 891) return;
    int oc = idx / 891, pos = idx % 891;
    d_m2[idx] = fmaxf(d_cg[(size_t)pos * 128 + oc] + cb2[oc], 0.f);
}

__global__ void k_wm(const float* __restrict__ Wm) {
    __shared__ float red[256];
    int o = blockIdx.x;
    int chunk = blockIdx.y;
    const int CH = 114048 / 8;
    int base = chunk * CH;
    const float* wr = Wm + (size_t)o * 114048 + base;
    const float* mv = d_m2 + base;
    float s = 0.f;
    for (int i = threadIdx.x * 4; i < CH; i += 256 * 4) {
        float4 a = *(const float4*)(wr + i);
        float4 v = *(const float4*)(mv + i);
        s += a.x * v.x + a.y * v.y + a.z * v.z + a.w * v.w;
    }
    red[threadIdx.x] = s;
    __syncthreads();
    for (int st = 128; st > 0; st >>= 1) {
        if (threadIdx.x < st) red[threadIdx.x] += red[threadIdx.x + st];
        __syncthreads();
    }
    if (threadIdx.x == 0) d_wmpart[chunk][o] = red[0];
}

// ---------------- final stats ----------------
__global__ void k_finstats(const float* __restrict__ bm) {
    __shared__ float smn[256], smx[256];
    int t = threadIdx.x;
    float mn = 3.4e38f, mx = -3.4e38f;
    for (int i = t; i < NBC; i += 256) {
        mn = fminf(mn, d_pmin[i]);
        mx = fmaxf(mx, d_pmax[i]);
    }
    smn[t] = mn; smx[t] = mx;
    __syncthreads();
    for (int st = 128; st > 0; st >>= 1) {
        if (t < st) {
            smn[t] = fminf(smn[t], smn[t + st]);
            smx[t] = fmaxf(smx[t], smx[t + st]);
        }
        __syncthreads();
    }
    if (t == 0) {
        float lo = smn[0], hi = smx[0];
        float a = 0.35f / (hi - lo);
        d_hstats[0] = a;
        d_hstats[1] = -lo * a;
    }
    __syncthreads();
    float v = 0.f;
    if (t < 64) {
        v = bm[t];
#pragma unroll
        for (int c = 0; c < 8; c++) v += d_wmpart[c][t];
    }
    smn[t] = (t < 64) ? v : 3.4e38f;
    smx[t] = (t < 64) ? v : -3.4e38f;
    __syncthreads();
    for (int st = 128; st > 0; st >>= 1) {
        if (t < st) {
            smn[t] = fminf(smn[t], smn[t + st]);
            smx[t] = fmaxf(smx[t], smx[t + st]);
        }
        __syncthreads();
    }
    if (t < 64) {
        float lo = smn[0], hi = smx[0];
        d_mnorm[t] = 0.65f * (v - lo) / (hi - lo);
    }
}

// ---------------- final layer + softmax ----------------
__global__ void k_head(const float* __restrict__ W2, const float* __restrict__ b2,
                       const float* __restrict__ b1, float* __restrict__ out) {
    __shared__ float w2s[3][64];
    __shared__ float b2s[3];
    __shared__ float b1s[64];
    int tid = threadIdx.x;
    if (tid < 192) w2s[tid / 64][tid % 64] = W2[tid];
    if (tid < 3) b2s[tid] = b2[tid];
    if (tid >= 192 && tid < 256) b1s[tid - 192] = b1[tid - 192];
    __syncthreads();
    int i = blockIdx.x * blockDim.x + tid;
    if (i >= NN) return;
    const float* y = d_y1 + (size_t)i * 128;
    float s0 = b2s[0], s1 = b2s[1], s2 = b2s[2];
#pragma unroll
    for (int f = 0; f < 64; f += 4) {
        float4 v = *(const float4*)(y + f);
        v.x = fmaxf(v.x + b1s[f], 0.f);
        v.y = fmaxf(v.y + b1s[f + 1], 0.f);
        v.z = fmaxf(v.z + b1s[f + 2], 0.f);
        v.w = fmaxf(v.w + b1s[f + 3], 0.f);
        s0 += v.x * w2s[0][f] + v.y * w2s[0][f + 1] + v.z * w2s[0][f + 2] + v.w * w2s[0][f + 3];
        s1 += v.x * w2s[1][f] + v.y * w2s[1][f + 1] + v.z * w2s[1][f + 2] + v.w * w2s[1][f + 3];
        s2 += v.x * w2s[2][f] + v.y * w2s[2][f + 1] + v.z * w2s[2][f + 2] + v.w * w2s[2][f + 3];
    }
    float m = fmaxf(s0, fmaxf(s1, s2));
    float e0 = expf(s0 - m), e1 = expf(s1 - m), e2 = expf(s2 - m);
    float inv = 1.f / (e0 + e1 + e2);
    out[(size_t)i * 3 + 0] = e0 * inv;
    out[(size_t)i * 3 + 1] = e1 * inv;
    out[(size_t)i * 3 + 2] = e2 * inv;
}

// ---------------- launch ----------------
extern "C" void kernel_launch(void* const* d_in, const int* in_sizes, int n_in,
                              void* d_out, int out_size) {
    (void)in_sizes; (void)n_in; (void)out_size;
    const float* node = (const float*)d_in[0];
    const int* ei = (const int*)d_in[1];
    const float* mapd = (const float*)d_in[2];
    const float* bl1 = (const float*)d_in[4];
    const float* bl2 = (const float*)d_in[7];
    const float* bl3 = (const float*)d_in[10];
    const float* k1 = (const float*)d_in[12];
    const float* cb1 = (const float*)d_in[13];
    const float* k2 = (const float*)d_in[14];
    const float* cb2 = (const float*)d_in[15];
    const float* Wm = (const float*)d_in[16];
    const float* bm = (const float*)d_in[17];
    const float* b1 = (const float*)d_in[19];
    const float* W2 = (const float*)d_in[20];
    const float* b2 = (const float*)d_in[21];
    float* out = (float*)d_out;

    void *p_cnt, *p_cg;
    void *p_mx, *p_wc1, *p_h1, *p_wc2, *p_pq2, *p_h2, *p_wc3, *p_pq3, *p_h3;
    void *p_w1p, *p_y1, *p_xcol, *p_hstats, *p_mnorm;
    cudaGetSymbolAddress(&p_cnt, d_cnt);
    cudaGetSymbolAddress(&p_cg, d_cg);
    cudaGetSymbolAddress(&p_mx, d_mx);
    cudaGetSymbolAddress(&p_wc1, d_wc1);
    cudaGetSymbolAddress(&p_h1, d_h1);
    cudaGetSymbolAddress(&p_wc2, d_wc2);
    cudaGetSymbolAddress(&p_pq2, d_pq2);
    cudaGetSymbolAddress(&p_h2, d_h2);
    cudaGetSymbolAddress(&p_wc3, d_wc3);
    cudaGetSymbolAddress(&p_pq3, d_pq3);
    cudaGetSymbolAddress(&p_h3, d_h3);
    cudaGetSymbolAddress(&p_w1p, d_w1p);
    cudaGetSymbolAddress(&p_y1, d_y1);
    cudaGetSymbolAddress(&p_xcol, d_xcol);
    cudaGetSymbolAddress(&p_hstats, d_hstats);
    cudaGetSymbolAddress(&p_mnorm, d_mnorm);

    cudaStream_t s2;
    cudaStreamCreateWithFlags(&s2, cudaStreamNonBlocking);
    cudaEvent_t evFork, evJoin;
    cudaEventCreateWithFlags(&evFork, cudaEventDisableTiming);
    cudaEventCreateWithFlags(&evJoin, cudaEventDisableTiming);

    // 1: memset(cnt)  2: memset(cg)  3: packAll
    cudaMemsetAsync(p_cnt, 0, NN * sizeof(int));
    cudaMemsetAsync(p_cg, 0, 896 * 128 * sizeof(float));
    k_packAll<<<431, 256>>>((const float*)d_in[3], (const float*)d_in[5],
                            (const float*)d_in[6], (const float*)d_in[8],
                            (const float*)d_in[9], (const float*)d_in[11],
                            (const float*)d_in[18]);

    // fork conv path onto s2
    cudaEventRecord(evFork, 0);
    cudaStreamWaitEvent(s2, evFork, 0);

    // conv path on s2: 4 conv1, 5 im2col, 6 conv2 tgemm (ncu target), 7 m2fin, 8 wm
    k_conv1<<<(256 * 1573 + 255) / 256, 256, 0, s2>>>(mapd, k1, cb1);
    k_im2col<<<dim3(27, 891), 256, 0, s2>>>();
    k_tgemm<<<dim3(1, 7, 16), 256, 0, s2>>>((const float*)p_xcol, k2, (float*)p_cg,
                                            128, 6912, nullptr, nullptr, nullptr, 1, 0);
    k_m2fin<<<(128 * 891 + 255) / 256, 256, 0, s2>>>(cb2);
    k_wm<<<dim3(64, 8), 256, 0, s2>>>(Wm);
    cudaEventRecord(evJoin, s2);

    // GNN path on main stream (overlaps with s2)
    k_degcnt<<<(NE + 255) / 256, 256>>>(ei);
    k_scan1<<<NB1, 256>>>();
    k_scan3<<<NB1, 256>>>();
    k_scatter<<<(NE + 255) / 256, 256>>>(ei);

    k_xpad<<<(NN * 32 + 255) / 256, 256>>>(node);
    k_aggA<<<(NN * 32 + 255) / 256, 256>>>();
    k_tgemm<<<dim3(2, 391, 1), 256>>>((const float*)p_mx, (const float*)p_wc1,
                                      (float*)p_h1, 256, 48,
                                      nullptr, nullptr, nullptr, 0, 0);
    // GEMM2: p-half written directly as packed bf16 into d_p2h; q-half fp32
    k_tgemm<<<dim3(2, 391, 1), 256>>>((const float*)p_h1, (const float*)p_wc2,
                                      (float*)p_pq2, 256, 256,
                                      bl1, nullptr, nullptr, 0, 1);
    k_aggB<<<(NN * 32 + 255) / 256, 256>>>(bl2);
    k_tgemm<<<dim3(1, 391, 1), 256>>>((const float*)p_h2, (const float*)p_wc3,
                                      (float*)p_pq3, 128, 128,
                                      nullptr, nullptr, nullptr, 0, 0);
    k_aggC<<<NBC, 256>>>(bl3);

    // join conv path before finstats (needs d_wmpart)
    cudaStreamWaitEvent(0, evJoin, 0);
    k_finstats<<<1, 256>>>(bm);
    k_tgemm<<<dim3(1, 391, 1), 256>>>((const float*)p_h3, (const float*)p_w1p,
                                      (float*)p_y1, 128, 64,
                                      nullptr, (const float*)p_hstats,
                                      (const float*)p_mnorm, 0, 0);
    k_head<<<(NN + 255) / 256, 256>>>(W2, b2, b1, out);

    cudaEventDestroy(evFork);
    cudaEventDestroy(evJoin);
    cudaStreamDestroy(s2);
}

// round 13
// speedup vs baseline: 1.0972x; 1.0706x over previous
#include <cuda_runtime.h>
#include <cuda_bf16.h>
#include <mma.h>
#include <math.h>

using namespace nvcuda;

#define NN 50000
#define MP 50048   // padded rows: 391 * 128
#define NE 800000
#define NB1 196    // ceil(NN/256)
#define NBC 3125   // aggC grid = NN*16/256
#define TGA_SMEM 61440  // 3 stages * (A+B) * 128*20 floats * 4B

// ---------------- scratch ----------------
static __device__ int   d_cnt[NN];
static __device__ int   d_rowptr[NN + 1];
static __device__ int   d_cursor[NN];
static __device__ int   d_csrc[NE];
static __device__ int   d_part[256];
static __device__ float d_xp[(size_t)NN * 32];
static __device__ float d_mx[(size_t)MP * 48];
static __device__ float d_wc1[256 * 48];
static __device__ float d_h1[(size_t)MP * 256];
static __device__ float d_wc2[256 * 256];
static __device__ float d_pq2[(size_t)MP * 256];        // q half (128..255) fp32
static __device__ unsigned int d_p2h[(size_t)MP * 64];  // p as packed bf16x2
static __device__ float d_h2[(size_t)MP * 128];
static __device__ float d_wc3[128 * 128];
static __device__ float d_pq3[(size_t)MP * 128];  // [p(64)|q(64)]
static __device__ float d_h3[(size_t)MP * 64];
static __device__ float d_w1p[128 * 64];
static __device__ float d_y1[(size_t)MP * 128];
static __device__ float d_m1[256 * 13 * 11 * 11];
static __device__ float d_xcol[(size_t)896 * 6912];
static __device__ float d_cg[896 * 128];
static __device__ float d_m2[128 * 891];
static __device__ float d_wmpart[8][64];
static __device__ float d_mnorm[64];
static __device__ float d_pmin[NBC];
static __device__ float d_pmax[NBC];
static __device__ float d_hstats[4];
static __device__ int   d_koff[6912];
static __device__ int   d_poff[896];

// ---------------- merged weight packing + im2col tables ----------------
__global__ void k_packAll(const float* __restrict__ Wl1, const float* __restrict__ Wr1,
                          const float* __restrict__ Wl2, const float* __restrict__ Wr2,
                          const float* __restrict__ Wl3, const float* __restrict__ Wr3,
                          const float* __restrict__ W1) {
    int i = blockIdx.x * blockDim.x + threadIdx.x;
    if (i < 12288) {
        int n = i / 48, f = i % 48;
        float v = 0.f;
        if (f < 21) v = Wl1[n * 21 + f];
        else if (f < 42) v = Wr1[n * 21 + (f - 21)];
        d_wc1[i] = v;
    } else if (i < 77824) {
        int j = i - 12288;
        int n = j / 256, f = j % 256;
        d_wc2[j] = (n < 128) ? Wl2[n * 256 + f] : Wr2[(n - 128) * 256 + f];
    } else if (i < 94208) {
        int j = i - 77824;
        int n = j / 128, f = j % 128;
        d_wc3[j] = (n < 64) ? Wl3[n * 128 + f] : Wr3[(n - 64) * 128 + f];
    } else if (i < 102400) {
        int j = i - 94208;
        int n = j / 64;
        d_w1p[j] = (n < 64) ? W1[j] : 0.f;
    } else if (i < 109312) {
        int j = i - 102400;
        int ic = j / 27, tap = j % 27;
        int kd = tap / 9, r = tap % 9, kh = r / 3, kw = r % 3;
        d_koff[j] = ic * 1573 + kd * 121 + kh * 11 + kw;
    } else if (i < 110208) {
        int j = i - 109312;
        int v = 0;
        if (j < 891) {
            int od = j / 81, r2 = j % 81, oh = r2 / 9, ow = r2 % 9;
            v = od * 121 + oh * 11 + ow;
        }
        d_poff[j] = v;
    }
}

// ---------------- CSR build (xpad fused) ----------------
__global__ void k_degcnt(const int* __restrict__ ei, const float* __restrict__ x) {
    int e = blockIdx.x * blockDim.x + threadIdx.x;
    if (e < NE) atomicAdd(&d_cnt[ei[NE + e]], 1);
    if (e < NN * 32) {
        int n = e >> 5, f = e & 31;
        d_xp[e] = (f < 21) ? x[n * 21 + f] : 0.f;
    }
}
__global__ void k_scan1() {
    __shared__ int sh[256];
    int t = threadIdx.x;
    int i = blockIdx.x * 256 + t;
    int v = (i < NN) ? d_cnt[i] : 0;
    sh[t] = v;
    __syncthreads();
#pragma unroll
    for (int off = 1; off < 256; off <<= 1) {
        int a = (t >= off) ? sh[t - off] : 0;
        __syncthreads();
        sh[t] += a;
        __syncthreads();
    }
    if (i < NN) d_rowptr[i] = sh[t] - v;
    if (t == 255) d_part[blockIdx.x] = sh[255];
}
__global__ void k_scan3() {
    __shared__ int sh[256];
    int t = threadIdx.x;
    int v = (t < NB1) ? d_part[t] : 0;
    sh[t] = v;
    __syncthreads();
#pragma unroll
    for (int off = 1; off < 256; off <<= 1) {
        int a = (t >= off) ? sh[t - off] : 0;
        __syncthreads();
        sh[t] += a;
        __syncthreads();
    }
    int base = (blockIdx.x > 0) ? sh[blockIdx.x - 1] : 0;
    int i = blockIdx.x * 256 + t;
    if (i < NN) {
        int r = d_rowptr[i] + base;
        d_rowptr[i] = r;
        d_cursor[i] = r;
    }
    if (i == 0) d_rowptr[NN] = NE;
}
__global__ void k_scatter(const int* __restrict__ ei) {
    int e = blockIdx.x * blockDim.x + threadIdx.x;
    if (e >= NE) return;
    int s = ei[e], d = ei[NE + e];
    int pos = atomicAdd(&d_cursor[d], 1);
    d_csrc[pos] = s;
}

// ---------------- aggregation ----------------
__global__ void k_aggA() {
    int w = (blockIdx.x * blockDim.x + threadIdx.x) >> 5;
    int lane = threadIdx.x & 31;
    int sub = lane >> 3;
    int sl = lane & 7;
    if (w >= NN) return;
    int beg = d_rowptr[w], end = d_rowptr[w + 1];
    float4 acc = make_float4(0.f, 0.f, 0.f, 0.f);
#pragma unroll 2
    for (int e = beg + sub; e < end; e += 4) {
        int s = __ldg(&d_csrc[e]);
        float4 v = *(const float4*)&d_xp[(size_t)s * 32 + sl * 4];
        acc.x += v.x; acc.y += v.y; acc.z += v.z; acc.w += v.w;
    }
    acc.x += __shfl_xor_sync(0xffffffffu, acc.x, 8);
    acc.y += __shfl_xor_sync(0xffffffffu, acc.y, 8);
    acc.z += __shfl_xor_sync(0xffffffffu, acc.z, 8);
    acc.w += __shfl_xor_sync(0xffffffffu, acc.w, 8);
    acc.x += __shfl_xor_sync(0xffffffffu, acc.x, 16);
    acc.y += __shfl_xor_sync(0xffffffffu, acc.y, 16);
    acc.z += __shfl_xor_sync(0xffffffffu, acc.z, 16);
    acc.w += __shfl_xor_sync(0xffffffffu, acc.w, 16);
    float inv = 1.f / fmaxf((float)(end - beg), 1.0f);
    if (sub == 0) {
        float m[4] = {acc.x * inv, acc.y * inv, acc.z * inv, acc.w * inv};
#pragma unroll
        for (int c = 0; c < 4; c++) {
            int f = sl * 4 + c;
            if (f < 21) d_mx[(size_t)w * 48 + f] = m[c];
        }
    }
    float xo = d_xp[(size_t)w * 32 + lane];
    if (lane < 21) d_mx[(size_t)w * 48 + 21 + lane] = xo;
    else if (lane < 27) d_mx[(size_t)w * 48 + 21 + lane] = 0.f;
}
__global__ void k_aggB(const float* __restrict__ bl) {
    int w = (blockIdx.x * blockDim.x + threadIdx.x) >> 5;
    int lane = threadIdx.x & 31;
    int half = lane >> 4;
    int sl = lane & 15;
    if (w >= NN) return;
    int beg = d_rowptr[w], end = d_rowptr[w + 1];
    float4 a0 = make_float4(0.f, 0.f, 0.f, 0.f);
    float4 a1 = make_float4(0.f, 0.f, 0.f, 0.f);
#pragma unroll 2
    for (int e = beg + half; e < end; e += 2) {
        int s = __ldg(&d_csrc[e]);
        uint4 v = *(const uint4*)&d_p2h[(size_t)s * 64 + sl * 4];
        float2 f0 = __bfloat1622float2(*(__nv_bfloat162*)&v.x);
        float2 f1 = __bfloat1622float2(*(__nv_bfloat162*)&v.y);
        float2 f2 = __bfloat1622float2(*(__nv_bfloat162*)&v.z);
        float2 f3 = __bfloat1622float2(*(__nv_bfloat162*)&v.w);
        a0.x += f0.x; a0.y += f0.y; a0.z += f1.x; a0.w += f1.y;
        a1.x += f2.x; a1.y += f2.y; a1.z += f3.x; a1.w += f3.y;
    }
    a0.x += __shfl_xor_sync(0xffffffffu, a0.x, 16);
    a0.y += __shfl_xor_sync(0xffffffffu, a0.y, 16);
    a0.z += __shfl_xor_sync(0xffffffffu, a0.z, 16);
    a0.w += __shfl_xor_sync(0xffffffffu, a0.w, 16);
    a1.x += __shfl_xor_sync(0xffffffffu, a1.x, 16);
    a1.y += __shfl_xor_sync(0xffffffffu, a1.y, 16);
    a1.z += __shfl_xor_sync(0xffffffffu, a1.z, 16);
    a1.w += __shfl_xor_sync(0xffffffffu, a1.w, 16);
    if (half == 0) {
        float inv = 1.f / fmaxf((float)(end - beg), 1.0f);
        const float4* pq = (const float4*)d_pq2;
        float4 q0 = pq[(size_t)w * 64 + 32 + sl * 2];
        float4 q1 = pq[(size_t)w * 64 + 32 + sl * 2 + 1];
        float4 b0 = ((const float4*)bl)[sl * 2];
        float4 b1 = ((const float4*)bl)[sl * 2 + 1];
        float4 o0, o1;
        o0.x = fmaxf(a0.x * inv + b0.x + q0.x, 0.f);
        o0.y = fmaxf(a0.y * inv + b0.y + q0.y, 0.f);
        o0.z = fmaxf(a0.z * inv + b0.z + q0.z, 0.f);
        o0.w = fmaxf(a0.w * inv + b0.w + q0.w, 0.f);
        o1.x = fmaxf(a1.x * inv + b1.x + q1.x, 0.f);
        o1.y = fmaxf(a1.y * inv + b1.y + q1.y, 0.f);
        o1.z = fmaxf(a1.z * inv + b1.z + q1.z, 0.f);
        o1.w = fmaxf(a1.w * inv + b1.w + q1.w, 0.f);
        ((float4*)d_h2)[(size_t)w * 32 + sl * 2] = o0;
        ((float4*)d_h2)[(size_t)w * 32 + sl * 2 + 1] = o1;
    }
}
__global__ void k_aggC(const float* __restrict__ bl) {
    __shared__ float smn[256], smx[256];
    int tid = threadIdx.x;
    int g = (blockIdx.x * 256 + tid) >> 4;
    int lane = tid & 15;
    float lmn = 3.4e38f, lmx = -3.4e38f;
    if (g < NN) {
        int beg = d_rowptr[g], end = d_rowptr[g + 1];
        const float4* pq = (const float4*)d_pq3;
        float4 acc = make_float4(0.f, 0.f, 0.f, 0.f);
#pragma unroll 4
        for (int e = beg; e < end; e++) {
            int s = __ldg(&d_csrc[e]);
            float4 v = pq[(size_t)s * 32 + lane];
            acc.x += v.x; acc.y += v.y; acc.z += v.z; acc.w += v.w;
        }
        float inv = 1.f / fmaxf((float)(end - beg), 1.0f);
        float4 q = pq[(size_t)g * 32 + 16 + lane];
        float4 b = ((const float4*)bl)[lane];
        float4 o;
        o.x = acc.x * inv + b.x + q.x;
        o.y = acc.y * inv + b.y + q.y;
        o.z = acc.z * inv + b.z + q.z;
        o.w = acc.w * inv + b.w + q.w;
        ((float4*)d_h3)[(size_t)g * 16 + lane] = o;
        lmn = fminf(fminf(o.x, o.y), fminf(o.z, o.w));
        lmx = fmaxf(fmaxf(o.x, o.y), fmaxf(o.z, o.w));
    }
    smn[tid] = lmn; smx[tid] = lmx;
    __syncthreads();
    for (int st = 128; st > 0; st >>= 1) {
        if (tid < st) {
            smn[tid] = fminf(smn[tid], smn[tid + st]);
            smx[tid] = fmaxf(smx[tid], smx[tid + st]);
        }
        __syncthreads();
    }
    if (tid == 0) { d_pmin[blockIdx.x] = smn[0]; d_pmax[blockIdx.x] = smx[0]; }
}

// ---------------- cp.async pipelined tf32 GEMM (3-stage) ----------------
// C[.,N] = A[.,K] @ B[N,K]^T, K % 16 == 0, raw fp32 bits fed to tf32 mma.
// mode 0: plain store   mode 1: bias+relu staged store
// mode 2: bfp (blockIdx.x==0 -> bf16 pack to d_p2h, else plain)
// mode 3: split-K atomicAdd epilogue
#define CPA(dst, src) \
    asm volatile("cp.async.cg.shared.global [%0], [%1], 16;" :: "r"(dst), "l"(src))
#define CPCOMMIT() asm volatile("cp.async.commit_group;" ::: "memory")
#define CPWAIT1() asm volatile("cp.async.wait_group 1;" ::: "memory")
#define CPWAIT0() asm volatile("cp.async.wait_group 0;" ::: "memory")

__global__ void __launch_bounds__(256, 2) k_tgemmA(
    const float* __restrict__ A, const float* __restrict__ B, float* __restrict__ C,
    int N, int K, const float* __restrict__ bias, int mode) {
    extern __shared__ float sm[];
    float* Asm = sm;                 // [3][128][20]
    float* Bsm = sm + 3 * 2560;      // [3][128][20]
    int tid = threadIdx.x;
    int wid = tid >> 5;
    int lane = tid & 31;
    int bm = blockIdx.y * 128;
    int bn = blockIdx.x * 128;
    int wm = (wid >> 2) * 64;
    int wn = (wid & 3) * 32;
    int lrow = tid >> 1;
    int lcol = (tid & 1) * 8;
    int nkz = (K / 16) / gridDim.z;
    int kbase = blockIdx.z * nkz * 16;

    const float* Ap = A + (size_t)(bm + lrow) * K + kbase + lcol;
    const float* Bp = B + (size_t)(bn + lrow) * K + kbase + lcol;
    unsigned aS = (unsigned)__cvta_generic_to_shared(Asm + lrow * 20 + lcol);
    unsigned bS = (unsigned)__cvta_generic_to_shared(Bsm + lrow * 20 + lcol);

#define ISSUE(s, koff)                                      \
    do {                                                    \
        unsigned _ao = aS + (s) * 10240;                    \
        unsigned _bo = bS + (s) * 10240;                    \
        CPA(_ao, Ap + (koff)); CPA(_ao + 16, Ap + (koff) + 4); \
        CPA(_bo, Bp + (koff)); CPA(_bo + 16, Bp + (koff) + 4); \
    } while (0)

    wmma::fragment<wmma::accumulator, 16, 16, 8, float> cf[4][2];
#pragma unroll
    for (int i = 0; i < 4; i++)
#pragma unroll
        for (int j = 0; j < 2; j++) wmma::fill_fragment(cf[i][j], 0.f);

    ISSUE(0, 0); CPCOMMIT();
    if (nkz > 1) { ISSUE(1, 16); CPCOMMIT(); }
    else CPCOMMIT();

    for (int it = 0; it < nkz; it++) {
        CPWAIT1();
        __syncthreads();
        if (it + 2 < nkz) ISSUE((it + 2) % 3, (it + 2) * 16);
        CPCOMMIT();
        int buf = it % 3;
        float* Ab = Asm + buf * 2560;
        float* Bb = Bsm + buf * 2560;
#pragma unroll
        for (int ks = 0; ks < 16; ks += 8) {
            wmma::fragment<wmma::matrix_a, 16, 16, 8, wmma::precision::tf32, wmma::row_major> af[4];
            wmma::fragment<wmma::matrix_b, 16, 16, 8, wmma::precision::tf32, wmma::col_major> bf[2];
#pragma unroll
            for (int i = 0; i < 4; i++)
                wmma::load_matrix_sync(af[i], Ab + (wm + i * 16) * 20 + ks, 20);
#pragma unroll
            for (int j = 0; j < 2; j++)
                wmma::load_matrix_sync(bf[j], Bb + (wn + j * 16) * 20 + ks, 20);
#pragma unroll
            for (int i = 0; i < 4; i++)
#pragma unroll
                for (int j = 0; j < 2; j++)
                    wmma::mma_sync(cf[i][j], af[i], bf[j], cf[i][j]);
        }
    }
    CPWAIT0();
    __syncthreads();

    if (mode == 0 || (mode == 2 && blockIdx.x != 0)) {
#pragma unroll
        for (int i = 0; i < 4; i++)
#pragma unroll
            for (int j = 0; j < 2; j++)
                wmma::store_matrix_sync(&C[(size_t)(bm + wm + i * 16) * N + bn + wn + j * 16],
                                        cf[i][j], N, wmma::mem_row_major);
    } else if (mode == 1) {
        float* stage = Asm + wid * 320;
        int r = lane >> 1, c0 = (lane & 1) * 8;
#pragma unroll
        for (int i = 0; i < 4; i++)
#pragma unroll
            for (int j = 0; j < 2; j++) {
                wmma::store_matrix_sync(stage, cf[i][j], 20, wmma::mem_row_major);
                __syncwarp();
                const float* sp = stage + r * 20 + c0;
                const float* bp = bias + bn + wn + j * 16 + c0;
                float4 v0, v1;
                v0.x = fmaxf(sp[0] + bp[0], 0.f); v0.y = fmaxf(sp[1] + bp[1], 0.f);
                v0.z = fmaxf(sp[2] + bp[2], 0.f); v0.w = fmaxf(sp[3] + bp[3], 0.f);
                v1.x = fmaxf(sp[4] + bp[4], 0.f); v1.y = fmaxf(sp[5] + bp[5], 0.f);
                v1.z = fmaxf(sp[6] + bp[6], 0.f); v1.w = fmaxf(sp[7] + bp[7], 0.f);
                size_t off = (size_t)(bm + wm + i * 16 + r) * N + bn + wn + j * 16 + c0;
                *(float4*)&C[off] = v0;
                *(float4*)&C[off + 4] = v1;
                __syncwarp();
            }
    } else if (mode == 2) {
        float* stage = Asm + wid * 320;
        int r = lane >> 1, cu = (lane & 1) * 4;
#pragma unroll
        for (int i = 0; i < 4; i++)
#pragma unroll
            for (int j = 0; j < 2; j++) {
                wmma::store_matrix_sync(stage, cf[i][j], 20, wmma::mem_row_major);
                __syncwarp();
                const float* sp = stage + r * 20 + cu * 2;
                unsigned int o[4];
#pragma unroll
                for (int t = 0; t < 4; t++) {
                    __nv_bfloat162 h = __floats2bfloat162_rn(sp[2 * t], sp[2 * t + 1]);
                    o[t] = *(unsigned int*)&h;
                }
                *(uint4*)&d_p2h[(size_t)(bm + wm + i * 16 + r) * 64 +
                                ((wn + j * 16) >> 1) + cu] =
                    make_uint4(o[0], o[1], o[2], o[3]);
                __syncwarp();
            }
    } else {  // mode 3: split-K atomic
        float* stage = Asm + wid * 320;
#pragma unroll
        for (int i = 0; i < 4; i++)
#pragma unroll
            for (int j = 0; j < 2; j++) {
                wmma::store_matrix_sync(stage, cf[i][j], 20, wmma::mem_row_major);
                __syncwarp();
                float* cp = &C[(size_t)(bm + wm + i * 16) * N + bn + wn + j * 16];
#pragma unroll
                for (int e = 0; e < 8; e++) {
                    int idx = lane * 8 + e;
                    int r2 = idx >> 4, c2 = idx & 15;
                    atomicAdd(&cp[(size_t)r2 * N + c2], stage[r2 * 20 + c2]);
                }
                __syncwarp();
            }
    }
#undef ISSUE
}

// ---------------- old GEMM (xstats prolog path, used for GEMM4 only) ---------
__global__ void __launch_bounds__(256, 2) k_tgemm(
    const float* __restrict__ A, const float* __restrict__ B, float* __restrict__ C,
    int N, int K, const float* __restrict__ xstats, const float* __restrict__ madd) {
    __shared__ float As[2][128][20];
    __shared__ float Bs[2][128][20];
    int tid = threadIdx.x;
    int wid = tid >> 5;
    int bm = blockIdx.y * 128;
    int bn = blockIdx.x * 128;
    int wm = (wid >> 2) * 64;
    int wn = (wid & 3) * 32;
    int lrow = tid >> 1;
    int lcol = (tid & 1) * 8;
    int nkz = K / 16;

    float hs0 = xstats[0], hs1 = xstats[1];

    wmma::fragment<wmma::accumulator, 16, 16, 8, float> cf[4][2];
#pragma unroll
    for (int i = 0; i < 4; i++)
#pragma unroll
        for (int j = 0; j < 2; j++) wmma::fill_fragment(cf[i][j], 0.f);

    const float* Arow = A + (size_t)(bm + lrow) * K + lcol;
    const float* Brow = B + (size_t)(bn + lrow) * K + lcol;

    float4 a0, a1, b0v, b1v;

#define LOADTILE(koff)                                                          \
    do {                                                                        \
        a0 = *(const float4*)(Arow + (koff));                                   \
        a1 = *(const float4*)(Arow + (koff) + 4);                               \
        b0v = *(const float4*)(Brow + (koff));                                  \
        b1v = *(const float4*)(Brow + (koff) + 4);                              \
        const float* mp = madd + (koff) + lcol;                                 \
        a0.x = hs0 * a0.x + hs1 + mp[0]; a0.y = hs0 * a0.y + hs1 + mp[1];       \
        a0.z = hs0 * a0.z + hs1 + mp[2]; a0.w = hs0 * a0.w + hs1 + mp[3];       \
        a1.x = hs0 * a1.x + hs1 + mp[4]; a1.y = hs0 * a1.y + hs1 + mp[5];       \
        a1.z = hs0 * a1.z + hs1 + mp[6]; a1.w = hs0 * a1.w + hs1 + mp[7];       \
    } while (0)

#define STORETILE(bi)                                                           \
    do {                                                                        \
        *(float4*)&As[bi][lrow][lcol] = a0;                                     \
        *(float4*)&As[bi][lrow][lcol + 4] = a1;                                 \
        *(float4*)&Bs[bi][lrow][lcol] = b0v;                                    \
        *(float4*)&Bs[bi][lrow][lcol + 4] = b1v;                                \
    } while (0)

    LOADTILE(0);
    STORETILE(0);
    __syncthreads();

    for (int it = 0; it < nkz; it++) {
        int buf = it & 1;
        bool more = (it + 1) < nkz;
        if (more) LOADTILE((it + 1) * 16);
#pragma unroll
        for (int ks = 0; ks < 16; ks += 8) {
            wmma::fragment<wmma::matrix_a, 16, 16, 8, wmma::precision::tf32, wmma::row_major> af[4];
            wmma::fragment<wmma::matrix_b, 16, 16, 8, wmma::precision::tf32, wmma::col_major> bf[2];
#pragma unroll
            for (int i = 0; i < 4; i++)
                wmma::load_matrix_sync(af[i], &As[buf][wm + i * 16][ks], 20);
#pragma unroll
            for (int j = 0; j < 2; j++)
                wmma::load_matrix_sync(bf[j], &Bs[buf][wn + j * 16][ks], 20);
#pragma unroll
            for (int i = 0; i < 4; i++)
#pragma unroll
                for (int j = 0; j < 2; j++)
                    wmma::mma_sync(cf[i][j], af[i], bf[j], cf[i][j]);
        }
        if (more) STORETILE(1 - buf);
        __syncthreads();
    }
#pragma unroll
    for (int i = 0; i < 4; i++)
#pragma unroll
        for (int j = 0; j < 2; j++)
            wmma::store_matrix_sync(&C[(size_t)(bm + wm + i * 16) * N + bn + wn + j * 16],
                                    cf[i][j], N, wmma::mem_row_major);
#undef LOADTILE
#undef STORETILE
}

// ---------------- map encoder ----------------
__global__ void k_conv1(const float* __restrict__ in, const float* __restrict__ w,
                        const float* __restrict__ b) {
    int idx = blockIdx.x * blockDim.x + threadIdx.x;
    if (idx >= 256 * 1573) return;
    int oc = idx / 1573, p = idx % 1573;
    int od = p / 121, r = p % 121, oh = r / 11, ow = r % 11;
    const float* wp = w + oc * 75;
    float acc = 0.f;
#pragma unroll
    for (int kd = 0; kd < 3; kd++)
#pragma unroll
        for (int kh = 0; kh < 5; kh++)
#pragma unroll
            for (int kw = 0; kw < 5; kw++)
                acc += in[(od + kd) * 225 + (oh + kh) * 15 + (ow + kw)] *
                       wp[kd * 25 + kh * 5 + kw];
    d_m1[idx] = fmaxf(acc + b[oc], 0.f);
}

__global__ void k_im2col() {
    int k = blockIdx.x * 256 + threadIdx.x;
    int pos = blockIdx.y;
    d_xcol[(size_t)pos * 6912 + k] = d_m1[d_koff[k] + d_poff[pos]];
}

__global__ void k_m2fin(const float* __restrict__ cb2) {
    int idx = blockIdx.x * blockDim.x + threadIdx.x;
    if (idx >= 128 * 891) return;
    int oc = idx / 891, pos = idx % 891;
    d_m2[idx] = fmaxf(d_cg[(size_t)pos * 128 + oc] + cb2[oc], 0.f);
}

__global__ void k_wm(const float* __restrict__ Wm) {
    __shared__ float red[256];
    int o = blockIdx.x;
    int chunk = blockIdx.y;
    const int CH = 114048 / 8;
    int base = chunk * CH;
    const float* wr = Wm + (size_t)o * 114048 + base;
    const float* mv = d_m2 + base;
    float s = 0.f;
    for (int i = threadIdx.x * 4; i < CH; i += 256 * 4) {
        float4 a = *(const float4*)(wr + i);
        float4 v = *(const float4*)(mv + i);
        s += a.x * v.x + a.y * v.y + a.z * v.z + a.w * v.w;
    }
    red[threadIdx.x] = s;
    __syncthreads();
    for (int st = 128; st > 0; st >>= 1) {
        if (threadIdx.x < st) red[threadIdx.x] += red[threadIdx.x + st];
        __syncthreads();
    }
    if (threadIdx.x == 0) d_wmpart[chunk][o] = red[0];
}

// ---------------- final stats ----------------
__global__ void k_finstats(const float* __restrict__ bm) {
    __shared__ float smn[256], smx[256];
    int t = threadIdx.x;
    float mn = 3.4e38f, mx = -3.4e38f;
    for (int i = t; i < NBC; i += 256) {
        mn = fminf(mn, d_pmin[i]);
        mx = fmaxf(mx, d_pmax[i]);
    }
    smn[t] = mn; smx[t] = mx;
    __syncthreads();
    for (int st = 128; st > 0; st >>= 1) {
        if (t < st) {
            smn[t] = fminf(smn[t], smn[t + st]);
            smx[t] = fmaxf(smx[t], smx[t + st]);
        }
        __syncthreads();
    }
    if (t == 0) {
        float lo = smn[0], hi = smx[0];
        float a = 0.35f / (hi - lo);
        d_hstats[0] = a;
        d_hstats[1] = -lo * a;
    }
    __syncthreads();
    float v = 0.f;
    if (t < 64) {
        v = bm[t];
#pragma unroll
        for (int c = 0; c < 8; c++) v += d_wmpart[c][t];
    }
    smn[t] = (t < 64) ? v : 3.4e38f;
    smx[t] = (t < 64) ? v : -3.4e38f;
    __syncthreads();
    for (int st = 128; st > 0; st >>= 1) {
        if (t < st) {
            smn[t] = fminf(smn[t], smn[t + st]);
            smx[t] = fmaxf(smx[t], smx[t + st]);
        }
        __syncthreads();
    }
    if (t < 64) {
        float lo = smn[0], hi = smx[0];
        d_mnorm[t] = 0.65f * (v - lo) / (hi - lo);
    }
}

// ---------------- final layer + softmax ----------------
__global__ void k_head(const float* __restrict__ W2, const float* __restrict__ b2,
                       const float* __restrict__ b1, float* __restrict__ out) {
    __shared__ float w2s[3][64];
    __shared__ float b2s[3];
    __shared__ float b1s[64];
    int tid = threadIdx.x;
    if (tid < 192) w2s[tid / 64][tid % 64] = W2[tid];
    if (tid < 3) b2s[tid] = b2[tid];
    if (tid >= 192 && tid < 256) b1s[tid - 192] = b1[tid - 192];
    __syncthreads();
    int i = blockIdx.x * blockDim.x + tid;
    if (i >= NN) return;
    const float* y = d_y1 + (size_t)i * 128;
    float s0 = b2s[0], s1 = b2s[1], s2 = b2s[2];
#pragma unroll
    for (int f = 0; f < 64; f += 4) {
        float4 v = *(const float4*)(y + f);
        v.x = fmaxf(v.x + b1s[f], 0.f);
        v.y = fmaxf(v.y + b1s[f + 1], 0.f);
        v.z = fmaxf(v.z + b1s[f + 2], 0.f);
        v.w = fmaxf(v.w + b1s[f + 3], 0.f);
        s0 += v.x * w2s[0][f] + v.y * w2s[0][f + 1] + v.z * w2s[0][f + 2] + v.w * w2s[0][f + 3];
        s1 += v.x * w2s[1][f] + v.y * w2s[1][f + 1] + v.z * w2s[1][f + 2] + v.w * w2s[1][f + 3];
        s2 += v.x * w2s[2][f] + v.y * w2s[2][f + 1] + v.z * w2s[2][f + 2] + v.w * w2s[2][f + 3];
    }
    float m = fmaxf(s0, fmaxf(s1, s2));
    float e0 = expf(s0 - m), e1 = expf(s1 - m), e2 = expf(s2 - m);
    float inv = 1.f / (e0 + e1 + e2);
    out[(size_t)i * 3 + 0] = e0 * inv;
    out[(size_t)i * 3 + 1] = e1 * inv;
    out[(size_t)i * 3 + 2] = e2 * inv;
}

// ---------------- launch ----------------
extern "C" void kernel_launch(void* const* d_in, const int* in_sizes, int n_in,
                              void* d_out, int out_size) {
    (void)in_sizes; (void)n_in; (void)out_size;
    const float* node = (const float*)d_in[0];
    const int* ei = (const int*)d_in[1];
    const float* mapd = (const float*)d_in[2];
    const float* bl1 = (const float*)d_in[4];
    const float* bl2 = (const float*)d_in[7];
    const float* bl3 = (const float*)d_in[10];
    const float* k1 = (const float*)d_in[12];
    const float* cb1 = (const float*)d_in[13];
    const float* k2 = (const float*)d_in[14];
    const float* cb2 = (const float*)d_in[15];
    const float* Wm = (const float*)d_in[16];
    const float* bm = (const float*)d_in[17];
    const float* b1 = (const float*)d_in[19];
    const float* W2 = (const float*)d_in[20];
    const float* b2 = (const float*)d_in[21];
    float* out = (float*)d_out;

    cudaFuncSetAttribute(k_tgemmA, cudaFuncAttributeMaxDynamicSharedMemorySize, TGA_SMEM);

    void *p_cnt, *p_cg;
    void *p_mx, *p_wc1, *p_h1, *p_wc2, *p_pq2, *p_h2, *p_wc3, *p_pq3, *p_h3;
    void *p_w1p, *p_y1, *p_xcol, *p_hstats, *p_mnorm;
    cudaGetSymbolAddress(&p_cnt, d_cnt);
    cudaGetSymbolAddress(&p_cg, d_cg);
    cudaGetSymbolAddress(&p_mx, d_mx);
    cudaGetSymbolAddress(&p_wc1, d_wc1);
    cudaGetSymbolAddress(&p_h1, d_h1);
    cudaGetSymbolAddress(&p_wc2, d_wc2);
    cudaGetSymbolAddress(&p_pq2, d_pq2);
    cudaGetSymbolAddress(&p_h2, d_h2);
    cudaGetSymbolAddress(&p_wc3, d_wc3);
    cudaGetSymbolAddress(&p_pq3, d_pq3);
    cudaGetSymbolAddress(&p_h3, d_h3);
    cudaGetSymbolAddress(&p_w1p, d_w1p);
    cudaGetSymbolAddress(&p_y1, d_y1);
    cudaGetSymbolAddress(&p_xcol, d_xcol);
    cudaGetSymbolAddress(&p_hstats, d_hstats);
    cudaGetSymbolAddress(&p_mnorm, d_mnorm);

    cudaStream_t s2;
    cudaStreamCreateWithFlags(&s2, cudaStreamNonBlocking);
    cudaEvent_t evFork, evJoin;
    cudaEventCreateWithFlags(&evFork, cudaEventDisableTiming);
    cudaEventCreateWithFlags(&evJoin, cudaEventDisableTiming);

    // 1: memset(cnt)  2: memset(cg)  3: packAll
    cudaMemsetAsync(p_cnt, 0, NN * sizeof(int));
    cudaMemsetAsync(p_cg, 0, 896 * 128 * sizeof(float));
    k_packAll<<<431, 256>>>((const float*)d_in[3], (const float*)d_in[5],
                            (const float*)d_in[6], (const float*)d_in[8],
                            (const float*)d_in[9], (const float*)d_in[11],
                            (const float*)d_in[18]);

    // fork conv path onto s2
    cudaEventRecord(evFork, 0);
    cudaStreamWaitEvent(s2, evFork, 0);

    // conv path on s2: 4 conv1, 5 im2col, 6 conv2 tgemmA (ncu target), 7 m2fin, 8 wm
    k_conv1<<<(256 * 1573 + 255) / 256, 256, 0, s2>>>(mapd, k1, cb1);
    k_im2col<<<dim3(27, 891), 256, 0, s2>>>();
    k_tgemmA<<<dim3(1, 7, 16), 256, TGA_SMEM, s2>>>((const float*)p_xcol, k2,
                                                    (float*)p_cg, 128, 6912,
                                                    nullptr, 3);
    k_m2fin<<<(128 * 891 + 255) / 256, 256, 0, s2>>>(cb2);
    k_wm<<<dim3(64, 8), 256, 0, s2>>>(Wm);
    cudaEventRecord(evJoin, s2);

    // GNN path on main stream
    k_degcnt<<<(NN * 32 + 255) / 256, 256>>>(ei, node);
    k_scan1<<<NB1, 256>>>();
    k_scan3<<<NB1, 256>>>();
    k_scatter<<<(NE + 255) / 256, 256>>>(ei);

    k_aggA<<<(NN * 32 + 255) / 256, 256>>>();
    // GEMM1: epilogue bias+relu -> h1 holds activated values
    k_tgemmA<<<dim3(2, 391, 1), 256, TGA_SMEM>>>((const float*)p_mx, (const float*)p_wc1,
                                                 (float*)p_h1, 256, 48, bl1, 1);
    // GEMM2: clean A; p-half packed to bf16 (mode 2), q-half fp32
    k_tgemmA<<<dim3(2, 391, 1), 256, TGA_SMEM>>>((const float*)p_h1, (const float*)p_wc2,
                                                 (float*)p_pq2, 256, 256, nullptr, 2);
    k_aggB<<<(NN * 32 + 255) / 256, 256>>>(bl2);
    k_tgemmA<<<dim3(1, 391, 1), 256, TGA_SMEM>>>((const float*)p_h2, (const float*)p_wc3,
                                                 (float*)p_pq3, 128, 128, nullptr, 0);
    k_aggC<<<NBC, 256>>>(bl3);

    // join conv path before finstats
    cudaStreamWaitEvent(0, evJoin, 0);
    k_finstats<<<1, 256>>>(bm);
    k_tgemm<<<dim3(1, 391, 1), 256>>>((const float*)p_h3, (const float*)p_w1p,
                                      (float*)p_y1, 128, 64,
                                      (const float*)p_hstats, (const float*)p_mnorm);
    k_head<<<(NN + 255) / 256, 256>>>(W2, b2, b1, out);

    cudaEventDestroy(evFork);
    cudaEventDestroy(evJoin);
    cudaStreamDestroy(s2);
}

// round 14
// speedup vs baseline: 1.1160x; 1.0171x over previous
#include <cuda_runtime.h>
#include <cuda_bf16.h>
#include <mma.h>
#include <math.h>

using namespace nvcuda;

#define NN 50000
#define MP 50048   // padded rows: 391 * 128
#define NE 800000
#define NB1 196    // ceil(NN/256)
#define NBC 3125   // aggC grid = NN*16/256
#define TGA_SMEM 61440  // 3 stages * (A+B) * 128*20 floats * 4B

// ---------------- scratch ----------------
static __device__ int   d_cnt[NN];
static __device__ int   d_rowptr[NN + 1];
static __device__ int   d_cursor[NN];
static __device__ int   d_csrc[NE];
static __device__ int   d_part[256];
static __device__ float d_xp[(size_t)NN * 32];
static __device__ float d_mx[(size_t)MP * 48];
static __device__ float d_wc1[256 * 48];
static __device__ float d_h1[(size_t)MP * 256];
static __device__ float d_wc2[256 * 256];
static __device__ float d_pq2[(size_t)MP * 256];        // q half (128..255) fp32
static __device__ unsigned int d_p2h[(size_t)MP * 64];  // p as packed bf16x2
static __device__ float d_h2[(size_t)MP * 128];
static __device__ float d_wc3[128 * 128];
static __device__ float d_pq3[(size_t)MP * 128];  // [p(64)|q(64)]
static __device__ float d_h3[(size_t)MP * 64];
static __device__ float d_w1p[128 * 64];
static __device__ float d_m1[256 * 13 * 11 * 11];
static __device__ float d_xcol[(size_t)896 * 6912];
static __device__ float d_cg[896 * 128];
static __device__ float d_m2[128 * 891];
static __device__ float d_wmpart[8][64];
static __device__ float d_mnorm[64];
static __device__ float d_rvec[64];    // rb1 = W1 @ (hs1 + mnorm) + b1
static __device__ float d_pmin[NBC];
static __device__ float d_pmax[NBC];
static __device__ float d_hstats[4];
static __device__ int   d_koff[6912];
static __device__ int   d_poff[896];

// ---------------- merged weight packing + im2col tables ----------------
__global__ void k_packAll(const float* __restrict__ Wl1, const float* __restrict__ Wr1,
                          const float* __restrict__ Wl2, const float* __restrict__ Wr2,
                          const float* __restrict__ Wl3, const float* __restrict__ Wr3,
                          const float* __restrict__ W1) {
    int i = blockIdx.x * blockDim.x + threadIdx.x;
    if (i < 12288) {
        int n = i / 48, f = i % 48;
        float v = 0.f;
        if (f < 21) v = Wl1[n * 21 + f];
        else if (f < 42) v = Wr1[n * 21 + (f - 21)];
        d_wc1[i] = v;
    } else if (i < 77824) {
        int j = i - 12288;
        int n = j / 256, f = j % 256;
        d_wc2[j] = (n < 128) ? Wl2[n * 256 + f] : Wr2[(n - 128) * 256 + f];
    } else if (i < 94208) {
        int j = i - 77824;
        int n = j / 128, f = j % 128;
        d_wc3[j] = (n < 64) ? Wl3[n * 128 + f] : Wr3[(n - 64) * 128 + f];
    } else if (i < 102400) {
        int j = i - 94208;
        int n = j / 64;
        d_w1p[j] = (n < 64) ? W1[j] : 0.f;
    } else if (i < 109312) {
        int j = i - 102400;
        int ic = j / 27, tap = j % 27;
        int kd = tap / 9, r = tap % 9, kh = r / 3, kw = r % 3;
        d_koff[j] = ic * 1573 + kd * 121 + kh * 11 + kw;
    } else if (i < 110208) {
        int j = i - 109312;
        int v = 0;
        if (j < 891) {
            int od = j / 81, r2 = j % 81, oh = r2 / 9, ow = r2 % 9;
            v = od * 121 + oh * 11 + ow;
        }
        d_poff[j] = v;
    }
}

// ---------------- CSR build (xpad fused) ----------------
__global__ void k_degcnt(const int* __restrict__ ei, const float* __restrict__ x) {
    int e = blockIdx.x * blockDim.x + threadIdx.x;
    if (e < NE) atomicAdd(&d_cnt[ei[NE + e]], 1);
    if (e < NN * 32) {
        int n = e >> 5, f = e & 31;
        d_xp[e] = (f < 21) ? x[n * 21 + f] : 0.f;
    }
}
__global__ void k_scan1() {
    __shared__ int sh[256];
    int t = threadIdx.x;
    int i = blockIdx.x * 256 + t;
    int v = (i < NN) ? d_cnt[i] : 0;
    sh[t] = v;
    __syncthreads();
#pragma unroll
    for (int off = 1; off < 256; off <<= 1) {
        int a = (t >= off) ? sh[t - off] : 0;
        __syncthreads();
        sh[t] += a;
        __syncthreads();
    }
    if (i < NN) d_rowptr[i] = sh[t] - v;
    if (t == 255) d_part[blockIdx.x] = sh[255];
}
__global__ void k_scan3() {
    __shared__ int sh[256];
    int t = threadIdx.x;
    int v = (t < NB1) ? d_part[t] : 0;
    sh[t] = v;
    __syncthreads();
#pragma unroll
    for (int off = 1; off < 256; off <<= 1) {
        int a = (t >= off) ? sh[t - off] : 0;
        __syncthreads();
        sh[t] += a;
        __syncthreads();
    }
    int base = (blockIdx.x > 0) ? sh[blockIdx.x - 1] : 0;
    int i = blockIdx.x * 256 + t;
    if (i < NN) {
        int r = d_rowptr[i] + base;
        d_rowptr[i] = r;
        d_cursor[i] = r;
    }
    if (i == 0) d_rowptr[NN] = NE;
}
__global__ void k_scatter(const int* __restrict__ ei) {
    int e = blockIdx.x * blockDim.x + threadIdx.x;
    if (e >= NE) return;
    int s = ei[e], d = ei[NE + e];
    int pos = atomicAdd(&d_cursor[d], 1);
    d_csrc[pos] = s;
}

// ---------------- aggregation ----------------
__global__ void k_aggA() {
    int w = (blockIdx.x * blockDim.x + threadIdx.x) >> 5;
    int lane = threadIdx.x & 31;
    int sub = lane >> 3;
    int sl = lane & 7;
    if (w >= NN) return;
    int beg = d_rowptr[w], end = d_rowptr[w + 1];
    float4 acc = make_float4(0.f, 0.f, 0.f, 0.f);
#pragma unroll 2
    for (int e = beg + sub; e < end; e += 4) {
        int s = __ldg(&d_csrc[e]);
        float4 v = *(const float4*)&d_xp[(size_t)s * 32 + sl * 4];
        acc.x += v.x; acc.y += v.y; acc.z += v.z; acc.w += v.w;
    }
    acc.x += __shfl_xor_sync(0xffffffffu, acc.x, 8);
    acc.y += __shfl_xor_sync(0xffffffffu, acc.y, 8);
    acc.z += __shfl_xor_sync(0xffffffffu, acc.z, 8);
    acc.w += __shfl_xor_sync(0xffffffffu, acc.w, 8);
    acc.x += __shfl_xor_sync(0xffffffffu, acc.x, 16);
    acc.y += __shfl_xor_sync(0xffffffffu, acc.y, 16);
    acc.z += __shfl_xor_sync(0xffffffffu, acc.z, 16);
    acc.w += __shfl_xor_sync(0xffffffffu, acc.w, 16);
    float inv = 1.f / fmaxf((float)(end - beg), 1.0f);
    if (sub == 0) {
        float m[4] = {acc.x * inv, acc.y * inv, acc.z * inv, acc.w * inv};
#pragma unroll
        for (int c = 0; c < 4; c++) {
            int f = sl * 4 + c;
            if (f < 21) d_mx[(size_t)w * 48 + f] = m[c];
        }
    }
    float xo = d_xp[(size_t)w * 32 + lane];
    if (lane < 21) d_mx[(size_t)w * 48 + 21 + lane] = xo;
    else if (lane < 27) d_mx[(size_t)w * 48 + 21 + lane] = 0.f;
}
__global__ void k_aggB(const float* __restrict__ bl) {
    int w = (blockIdx.x * blockDim.x + threadIdx.x) >> 5;
    int lane = threadIdx.x & 31;
    int half = lane >> 4;
    int sl = lane & 15;
    if (w >= NN) return;
    int beg = d_rowptr[w], end = d_rowptr[w + 1];
    float4 a0 = make_float4(0.f, 0.f, 0.f, 0.f);
    float4 a1 = make_float4(0.f, 0.f, 0.f, 0.f);
#pragma unroll 2
    for (int e = beg + half; e < end; e += 2) {
        int s = __ldg(&d_csrc[e]);
        uint4 v = *(const uint4*)&d_p2h[(size_t)s * 64 + sl * 4];
        float2 f0 = __bfloat1622float2(*(__nv_bfloat162*)&v.x);
        float2 f1 = __bfloat1622float2(*(__nv_bfloat162*)&v.y);
        float2 f2 = __bfloat1622float2(*(__nv_bfloat162*)&v.z);
        float2 f3 = __bfloat1622float2(*(__nv_bfloat162*)&v.w);
        a0.x += f0.x; a0.y += f0.y; a0.z += f1.x; a0.w += f1.y;
        a1.x += f2.x; a1.y += f2.y; a1.z += f3.x; a1.w += f3.y;
    }
    a0.x += __shfl_xor_sync(0xffffffffu, a0.x, 16);
    a0.y += __shfl_xor_sync(0xffffffffu, a0.y, 16);
    a0.z += __shfl_xor_sync(0xffffffffu, a0.z, 16);
    a0.w += __shfl_xor_sync(0xffffffffu, a0.w, 16);
    a1.x += __shfl_xor_sync(0xffffffffu, a1.x, 16);
    a1.y += __shfl_xor_sync(0xffffffffu, a1.y, 16);
    a1.z += __shfl_xor_sync(0xffffffffu, a1.z, 16);
    a1.w += __shfl_xor_sync(0xffffffffu, a1.w, 16);
    if (half == 0) {
        float inv = 1.f / fmaxf((float)(end - beg), 1.0f);
        const float4* pq = (const float4*)d_pq2;
        float4 q0 = pq[(size_t)w * 64 + 32 + sl * 2];
        float4 q1 = pq[(size_t)w * 64 + 32 + sl * 2 + 1];
        float4 b0 = ((const float4*)bl)[sl * 2];
        float4 b1 = ((const float4*)bl)[sl * 2 + 1];
        float4 o0, o1;
        o0.x = fmaxf(a0.x * inv + b0.x + q0.x, 0.f);
        o0.y = fmaxf(a0.y * inv + b0.y + q0.y, 0.f);
        o0.z = fmaxf(a0.z * inv + b0.z + q0.z, 0.f);
        o0.w = fmaxf(a0.w * inv + b0.w + q0.w, 0.f);
        o1.x = fmaxf(a1.x * inv + b1.x + q1.x, 0.f);
        o1.y = fmaxf(a1.y * inv + b1.y + q1.y, 0.f);
        o1.z = fmaxf(a1.z * inv + b1.z + q1.z, 0.f);
        o1.w = fmaxf(a1.w * inv + b1.w + q1.w, 0.f);
        ((float4*)d_h2)[(size_t)w * 32 + sl * 2] = o0;
        ((float4*)d_h2)[(size_t)w * 32 + sl * 2 + 1] = o1;
    }
}
__global__ void k_aggC(const float* __restrict__ bl) {
    __shared__ float smn[256], smx[256];
    int tid = threadIdx.x;
    int g = (blockIdx.x * 256 + tid) >> 4;
    int lane = tid & 15;
    float lmn = 3.4e38f, lmx = -3.4e38f;
    if (g < NN) {
        int beg = d_rowptr[g], end = d_rowptr[g + 1];
        const float4* pq = (const float4*)d_pq3;
        float4 acc = make_float4(0.f, 0.f, 0.f, 0.f);
#pragma unroll 4
        for (int e = beg; e < end; e++) {
            int s = __ldg(&d_csrc[e]);
            float4 v = pq[(size_t)s * 32 + lane];
            acc.x += v.x; acc.y += v.y; acc.z += v.z; acc.w += v.w;
        }
        float inv = 1.f / fmaxf((float)(end - beg), 1.0f);
        float4 q = pq[(size_t)g * 32 + 16 + lane];
        float4 b = ((const float4*)bl)[lane];
        float4 o;
        o.x = acc.x * inv + b.x + q.x;
        o.y = acc.y * inv + b.y + q.y;
        o.z = acc.z * inv + b.z + q.z;
        o.w = acc.w * inv + b.w + q.w;
        ((float4*)d_h3)[(size_t)g * 16 + lane] = o;
        lmn = fminf(fminf(o.x, o.y), fminf(o.z, o.w));
        lmx = fmaxf(fmaxf(o.x, o.y), fmaxf(o.z, o.w));
    }
    smn[tid] = lmn; smx[tid] = lmx;
    __syncthreads();
    for (int st = 128; st > 0; st >>= 1) {
        if (tid < st) {
            smn[tid] = fminf(smn[tid], smn[tid + st]);
            smx[tid] = fmaxf(smx[tid], smx[tid + st]);
        }
        __syncthreads();
    }
    if (tid == 0) { d_pmin[blockIdx.x] = smn[0]; d_pmax[blockIdx.x] = smx[0]; }
}

// ---------------- cp.async pipelined tf32 GEMM (3-stage) ----------------
// mode 0: plain store   mode 1: bias+relu staged store
// mode 2: bfp (blockIdx.x==0 -> bf16 pack to d_p2h, else plain)
// mode 3: split-K atomicAdd     mode 4: fused head epilogue (grid.x must be 1)
#define CPA(dst, src) \
    asm volatile("cp.async.cg.shared.global [%0], [%1], 16;" :: "r"(dst), "l"(src))
#define CPCOMMIT() asm volatile("cp.async.commit_group;" ::: "memory")
#define CPWAIT1() asm volatile("cp.async.wait_group 1;" ::: "memory")
#define CPWAIT0() asm volatile("cp.async.wait_group 0;" ::: "memory")

__global__ void __launch_bounds__(256, 2) k_tgemmA(
    const float* __restrict__ A, const float* __restrict__ B, float* __restrict__ C,
    int N, int K, const float* __restrict__ bias, int mode,
    const float* __restrict__ W2p, const float* __restrict__ b2p) {
    extern __shared__ float sm[];
    float* Asm = sm;                 // [3][128][20]
    float* Bsm = sm + 3 * 2560;      // [3][128][20]
    int tid = threadIdx.x;
    int wid = tid >> 5;
    int lane = tid & 31;
    int bm = blockIdx.y * 128;
    int bn = blockIdx.x * 128;
    int wm = (wid >> 2) * 64;
    int wn = (wid & 3) * 32;
    int lrow = tid >> 1;
    int lcol = (tid & 1) * 8;
    int nkz = (K / 16) / gridDim.z;
    int kbase = blockIdx.z * nkz * 16;

    const float* Ap = A + (size_t)(bm + lrow) * K + kbase + lcol;
    const float* Bp = B + (size_t)(bn + lrow) * K + kbase + lcol;
    unsigned aS = (unsigned)__cvta_generic_to_shared(Asm + lrow * 20 + lcol);
    unsigned bS = (unsigned)__cvta_generic_to_shared(Bsm + lrow * 20 + lcol);

#define ISSUE(s, koff)                                      \
    do {                                                    \
        unsigned _ao = aS + (s) * 10240;                    \
        unsigned _bo = bS + (s) * 10240;                    \
        CPA(_ao, Ap + (koff)); CPA(_ao + 16, Ap + (koff) + 4); \
        CPA(_bo, Bp + (koff)); CPA(_bo + 16, Bp + (koff) + 4); \
    } while (0)

    wmma::fragment<wmma::accumulator, 16, 16, 8, float> cf[4][2];
#pragma unroll
    for (int i = 0; i < 4; i++)
#pragma unroll
        for (int j = 0; j < 2; j++) wmma::fill_fragment(cf[i][j], 0.f);

    ISSUE(0, 0); CPCOMMIT();
    if (nkz > 1) { ISSUE(1, 16); CPCOMMIT(); }
    else CPCOMMIT();

    for (int it = 0; it < nkz; it++) {
        CPWAIT1();
        __syncthreads();
        if (it + 2 < nkz) ISSUE((it + 2) % 3, (it + 2) * 16);
        CPCOMMIT();
        int buf = it % 3;
        float* Ab = Asm + buf * 2560;
        float* Bb = Bsm + buf * 2560;
#pragma unroll
        for (int ks = 0; ks < 16; ks += 8) {
            wmma::fragment<wmma::matrix_a, 16, 16, 8, wmma::precision::tf32, wmma::row_major> af[4];
            wmma::fragment<wmma::matrix_b, 16, 16, 8, wmma::precision::tf32, wmma::col_major> bf[2];
#pragma unroll
            for (int i = 0; i < 4; i++)
                wmma::load_matrix_sync(af[i], Ab + (wm + i * 16) * 20 + ks, 20);
#pragma unroll
            for (int j = 0; j < 2; j++)
                wmma::load_matrix_sync(bf[j], Bb + (wn + j * 16) * 20 + ks, 20);
#pragma unroll
            for (int i = 0; i < 4; i++)
#pragma unroll
                for (int j = 0; j < 2; j++)
                    wmma::mma_sync(cf[i][j], af[i], bf[j], cf[i][j]);
        }
    }
    CPWAIT0();
    __syncthreads();

    if (mode == 0 || (mode == 2 && blockIdx.x != 0)) {
#pragma unroll
        for (int i = 0; i < 4; i++)
#pragma unroll
            for (int j = 0; j < 2; j++)
                wmma::store_matrix_sync(&C[(size_t)(bm + wm + i * 16) * N + bn + wn + j * 16],
                                        cf[i][j], N, wmma::mem_row_major);
    } else if (mode == 1) {
        float* stage = Asm + wid * 320;
        int r = lane >> 1, c0 = (lane & 1) * 8;
#pragma unroll
        for (int i = 0; i < 4; i++)
#pragma unroll
            for (int j = 0; j < 2; j++) {
                wmma::store_matrix_sync(stage, cf[i][j], 20, wmma::mem_row_major);
                __syncwarp();
                const float* sp = stage + r * 20 + c0;
                const float* bp = bias + bn + wn + j * 16 + c0;
                float4 v0, v1;
                v0.x = fmaxf(sp[0] + bp[0], 0.f); v0.y = fmaxf(sp[1] + bp[1], 0.f);
                v0.z = fmaxf(sp[2] + bp[2], 0.f); v0.w = fmaxf(sp[3] + bp[3], 0.f);
                v1.x = fmaxf(sp[4] + bp[4], 0.f); v1.y = fmaxf(sp[5] + bp[5], 0.f);
                v1.z = fmaxf(sp[6] + bp[6], 0.f); v1.w = fmaxf(sp[7] + bp[7], 0.f);
                size_t off = (size_t)(bm + wm + i * 16 + r) * N + bn + wn + j * 16 + c0;
                *(float4*)&C[off] = v0;
                *(float4*)&C[off + 4] = v1;
                __syncwarp();
            }
    } else if (mode == 2) {
        float* stage = Asm + wid * 320;
        int r = lane >> 1, cu = (lane & 1) * 4;
#pragma unroll
        for (int i = 0; i < 4; i++)
#pragma unroll
            for (int j = 0; j < 2; j++) {
                wmma::store_matrix_sync(stage, cf[i][j], 20, wmma::mem_row_major);
                __syncwarp();
                const float* sp = stage + r * 20 + cu * 2;
                unsigned int o[4];
#pragma unroll
                for (int t = 0; t < 4; t++) {
                    __nv_bfloat162 h = __floats2bfloat162_rn(sp[2 * t], sp[2 * t + 1]);
                    o[t] = *(unsigned int*)&h;
                }
                *(uint4*)&d_p2h[(size_t)(bm + wm + i * 16 + r) * 64 +
                                ((wn + j * 16) >> 1) + cu] =
                    make_uint4(o[0], o[1], o[2], o[3]);
                __syncwarp();
            }
    } else if (mode == 3) {
        float* stage = Asm + wid * 320;
#pragma unroll
        for (int i = 0; i < 4; i++)
#pragma unroll
            for (int j = 0; j < 2; j++) {
                wmma::store_matrix_sync(stage, cf[i][j], 20, wmma::mem_row_major);
                __syncwarp();
                float* cp = &C[(size_t)(bm + wm + i * 16) * N + bn + wn + j * 16];
#pragma unroll
                for (int e = 0; e < 8; e++) {
                    int idx = lane * 8 + e;
                    int r2 = idx >> 4, c2 = idx & 15;
                    atomicAdd(&cp[(size_t)r2 * N + c2], stage[r2 * 20 + c2]);
                }
                __syncwarp();
            }
    } else {  // mode 4: fused head (grid.x==1; only cols 0..63 valid)
        float* ybuf = sm;             // [128][68]
        float* w2s = sm + 128 * 68;   // 192
        float* rv = w2s + 192;        // 64
        float* cts = rv + 64;         // a, b2[3]
        if (wn < 64) {
#pragma unroll
            for (int i = 0; i < 4; i++)
#pragma unroll
                for (int j = 0; j < 2; j++)
                    wmma::store_matrix_sync(ybuf + (wm + i * 16) * 68 + wn + j * 16,
                                            cf[i][j], 68, wmma::mem_row_major);
        }
        if (tid < 192) w2s[tid] = W2p[tid];
        else if (tid < 195) cts[1 + tid - 192] = b2p[tid - 192];
        else if (tid == 195) cts[0] = bias[0];
        if (tid >= 196 && tid < 260) {}  // nop
        if (tid < 64) rv[tid] = d_rvec[tid];
        __syncthreads();
        if (tid < 128) {
            int row = bm + tid;
            if (row < NN) {
                float a = cts[0];
                float s0 = cts[1], s1 = cts[2], s2 = cts[3];
                const float* yr = ybuf + tid * 68;
#pragma unroll
                for (int f = 0; f < 64; f++) {
                    float v = fmaxf(a * yr[f] + rv[f], 0.f);
                    s0 += v * w2s[f];
                    s1 += v * w2s[64 + f];
                    s2 += v * w2s[128 + f];
                }
                float m = fmaxf(s0, fmaxf(s1, s2));
                float e0 = expf(s0 - m), e1 = expf(s1 - m), e2 = expf(s2 - m);
                float inv = 1.f / (e0 + e1 + e2);
                C[(size_t)row * 3 + 0] = e0 * inv;
                C[(size_t)row * 3 + 1] = e1 * inv;
                C[(size_t)row * 3 + 2] = e2 * inv;
            }
        }
    }
#undef ISSUE
}

// ---------------- map encoder ----------------
__global__ void k_conv1(const float* __restrict__ in, const float* __restrict__ w,
                        const float* __restrict__ b) {
    int idx = blockIdx.x * blockDim.x + threadIdx.x;
    if (idx >= 256 * 1573) return;
    int oc = idx / 1573, p = idx % 1573;
    int od = p / 121, r = p % 121, oh = r / 11, ow = r % 11;
    const float* wp = w + oc * 75;
    float acc = 0.f;
#pragma unroll
    for (int kd = 0; kd < 3; kd++)
#pragma unroll
        for (int kh = 0; kh < 5; kh++)
#pragma unroll
            for (int kw = 0; kw < 5; kw++)
                acc += in[(od + kd) * 225 + (oh + kh) * 15 + (ow + kw)] *
                       wp[kd * 25 + kh * 5 + kw];
    d_m1[idx] = fmaxf(acc + b[oc], 0.f);
}

__global__ void k_im2col() {
    int k = blockIdx.x * 256 + threadIdx.x;
    int pos = blockIdx.y;
    d_xcol[(size_t)pos * 6912 + k] = d_m1[d_koff[k] + d_poff[pos]];
}

__global__ void k_m2fin(const float* __restrict__ cb2) {
    int idx = blockIdx.x * blockDim.x + threadIdx.x;
    if (idx >= 128 * 891) return;
    int oc = idx / 891, pos = idx % 891;
    d_m2[idx] = fmaxf(d_cg[(size_t)pos * 128 + oc] + cb2[oc], 0.f);
}

__global__ void k_wm(const float* __restrict__ Wm) {
    __shared__ float red[256];
    int o = blockIdx.x;
    int chunk = blockIdx.y;
    const int CH = 114048 / 8;
    int base = chunk * CH;
    const float* wr = Wm + (size_t)o * 114048 + base;
    const float* mv = d_m2 + base;
    float s = 0.f;
    for (int i = threadIdx.x * 4; i < CH; i += 256 * 4) {
        float4 a = *(const float4*)(wr + i);
        float4 v = *(const float4*)(mv + i);
        s += a.x * v.x + a.y * v.y + a.z * v.z + a.w * v.w;
    }
    red[threadIdx.x] = s;
    __syncthreads();
    for (int st = 128; st > 0; st >>= 1) {
        if (threadIdx.x < st) red[threadIdx.x] += red[threadIdx.x + st];
        __syncthreads();
    }
    if (threadIdx.x == 0) d_wmpart[chunk][o] = red[0];
}

// ---------------- final stats + rvec ----------------
__global__ void k_finstats(const float* __restrict__ bm, const float* __restrict__ b1) {
    __shared__ float smn[256], smx[256];
    __shared__ float mloc[64];
    int t = threadIdx.x;
    float mn = 3.4e38f, mx = -3.4e38f;
    for (int i = t; i < NBC; i += 256) {
        mn = fminf(mn, d_pmin[i]);
        mx = fmaxf(mx, d_pmax[i]);
    }
    smn[t] = mn; smx[t] = mx;
    __syncthreads();
    for (int st = 128; st > 0; st >>= 1) {
        if (t < st) {
            smn[t] = fminf(smn[t], smn[t + st]);
            smx[t] = fmaxf(smx[t], smx[t + st]);
        }
        __syncthreads();
    }
    float hs1v;
    {
        float lo = smn[0], hi = smx[0];
        float a = 0.35f / (hi - lo);
        hs1v = -lo * a;
        if (t == 0) {
            d_hstats[0] = a;
            d_hstats[1] = hs1v;
        }
    }
    __syncthreads();
    float v = 0.f;
    if (t < 64) {
        v = bm[t];
#pragma unroll
        for (int c = 0; c < 8; c++) v += d_wmpart[c][t];
    }
    smn[t] = (t < 64) ? v : 3.4e38f;
    smx[t] = (t < 64) ? v : -3.4e38f;
    __syncthreads();
    for (int st = 128; st > 0; st >>= 1) {
        if (t < st) {
            smn[t] = fminf(smn[t], smn[t + st]);
            smx[t] = fmaxf(smx[t], smx[t + st]);
        }
        __syncthreads();
    }
    if (t < 64) {
        float lo = smn[0], hi = smx[0];
        float m = 0.65f * (v - lo) / (hi - lo);
        d_mnorm[t] = m;
        mloc[t] = m;
    }
    __syncthreads();
    if (t < 64) {
        float s = b1[t];
        const float* wr = d_w1p + t * 64;
#pragma unroll 8
        for (int k = 0; k < 64; k++) s += wr[k] * (hs1v + mloc[k]);
        d_rvec[t] = s;
    }
}

// ---------------- launch ----------------
extern "C" void kernel_launch(void* const* d_in, const int* in_sizes, int n_in,
                              void* d_out, int out_size) {
    (void)in_sizes; (void)n_in; (void)out_size;
    const float* node = (const float*)d_in[0];
    const int* ei = (const int*)d_in[1];
    const float* mapd = (const float*)d_in[2];
    const float* bl1 = (const float*)d_in[4];
    const float* bl2 = (const float*)d_in[7];
    const float* bl3 = (const float*)d_in[10];
    const float* k1 = (const float*)d_in[12];
    const float* cb1 = (const float*)d_in[13];
    const float* k2 = (const float*)d_in[14];
    const float* cb2 = (const float*)d_in[15];
    const float* Wm = (const float*)d_in[16];
    const float* bm = (const float*)d_in[17];
    const float* b1 = (const float*)d_in[19];
    const float* W2 = (const float*)d_in[20];
    const float* b2 = (const float*)d_in[21];
    float* out = (float*)d_out;

    cudaFuncSetAttribute(k_tgemmA, cudaFuncAttributeMaxDynamicSharedMemorySize, TGA_SMEM);

    void *p_cnt, *p_cg;
    void *p_mx, *p_wc1, *p_h1, *p_wc2, *p_pq2, *p_h2, *p_wc3, *p_pq3, *p_h3;
    void *p_w1p, *p_xcol, *p_hstats;
    cudaGetSymbolAddress(&p_cnt, d_cnt);
    cudaGetSymbolAddress(&p_cg, d_cg);
    cudaGetSymbolAddress(&p_mx, d_mx);
    cudaGetSymbolAddress(&p_wc1, d_wc1);
    cudaGetSymbolAddress(&p_h1, d_h1);
    cudaGetSymbolAddress(&p_wc2, d_wc2);
    cudaGetSymbolAddress(&p_pq2, d_pq2);
    cudaGetSymbolAddress(&p_h2, d_h2);
    cudaGetSymbolAddress(&p_wc3, d_wc3);
    cudaGetSymbolAddress(&p_pq3, d_pq3);
    cudaGetSymbolAddress(&p_h3, d_h3);
    cudaGetSymbolAddress(&p_w1p, d_w1p);
    cudaGetSymbolAddress(&p_xcol, d_xcol);
    cudaGetSymbolAddress(&p_hstats, d_hstats);

    cudaStream_t s2;
    cudaStreamCreateWithFlags(&s2, cudaStreamNonBlocking);
    cudaEvent_t evFork, evJoin;
    cudaEventCreateWithFlags(&evFork, cudaEventDisableTiming);
    cudaEventCreateWithFlags(&evJoin, cudaEventDisableTiming);

    // 1: memset(cnt)  2: memset(cg)  3: packAll
    cudaMemsetAsync(p_cnt, 0, NN * sizeof(int));
    cudaMemsetAsync(p_cg, 0, 896 * 128 * sizeof(float));
    k_packAll<<<431, 256>>>((const float*)d_in[3], (const float*)d_in[5],
                            (const float*)d_in[6], (const float*)d_in[8],
                            (const float*)d_in[9], (const float*)d_in[11],
                            (const float*)d_in[18]);

    // fork conv path onto s2
    cudaEventRecord(evFork, 0);
    cudaStreamWaitEvent(s2, evFork, 0);

    // conv path on s2: 4 conv1, 5 im2col, 6 conv2 tgemmA (ncu target), 7 m2fin, 8 wm
    k_conv1<<<(256 * 1573 + 255) / 256, 256, 0, s2>>>(mapd, k1, cb1);
    k_im2col<<<dim3(27, 891), 256, 0, s2>>>();
    k_tgemmA<<<dim3(1, 7, 16), 256, TGA_SMEM, s2>>>((const float*)p_xcol, k2,
                                                    (float*)p_cg, 128, 6912,
                                                    nullptr, 3, nullptr, nullptr);
    k_m2fin<<<(128 * 891 + 255) / 256, 256, 0, s2>>>(cb2);
    k_wm<<<dim3(64, 8), 256, 0, s2>>>(Wm);
    cudaEventRecord(evJoin, s2);

    // GNN path on main stream
    k_degcnt<<<(NN * 32 + 255) / 256, 256>>>(ei, node);
    k_scan1<<<NB1, 256>>>();
    k_scan3<<<NB1, 256>>>();
    k_scatter<<<(NE + 255) / 256, 256>>>(ei);

    k_aggA<<<(NN * 32 + 255) / 256, 256>>>();
    k_tgemmA<<<dim3(2, 391, 1), 256, TGA_SMEM>>>((const float*)p_mx, (const float*)p_wc1,
                                                 (float*)p_h1, 256, 48, bl1, 1,
                                                 nullptr, nullptr);
    k_tgemmA<<<dim3(2, 391, 1), 256, TGA_SMEM>>>((const float*)p_h1, (const float*)p_wc2,
                                                 (float*)p_pq2, 256, 256, nullptr, 2,
                                                 nullptr, nullptr);
    k_aggB<<<(NN * 32 + 255) / 256, 256>>>(bl2);
    k_tgemmA<<<dim3(1, 391, 1), 256, TGA_SMEM>>>((const float*)p_h2, (const float*)p_wc3,
                                                 (float*)p_pq3, 128, 128, nullptr, 0,
                                                 nullptr, nullptr);
    k_aggC<<<NBC, 256>>>(bl3);

    // join conv path before finstats
    cudaStreamWaitEvent(0, evJoin, 0);
    k_finstats<<<1, 256>>>(bm, b1);
    // GEMM4 + fused head: G = h3 @ w1p^T, then out = softmax(relu(a*G + rvec) @ W2^T + b2)
    k_tgemmA<<<dim3(1, 391, 1), 256, TGA_SMEM>>>((const float*)p_h3, (const float*)p_w1p,
                                                 out, 128, 64, (const float*)p_hstats, 4,
                                                 W2, b2);

    cudaEventDestroy(evFork);
    cudaEventDestroy(evJoin);
    cudaStreamDestroy(s2);
}

// round 15
// speedup vs baseline: 1.5652x; 1.4025x over previous
#include <cuda_runtime.h>
#include <cuda_bf16.h>
#include <mma.h>
#include <math.h>

using namespace nvcuda;

#define NN 50000
#define MP 50048   // padded rows: 391 * 128
#define NE 800000
#define NB1 196    // ceil(NN/256)
#define NBC 3125   // aggC grid = NN*16/256
#define TGA_SMEM 61440

// ---------------- scratch ----------------
static __device__ int   d_cnt[NN];
static __device__ int   d_rowptr[NN + 1];
static __device__ int   d_cursor[NN];
static __device__ int   d_csrc[NE];
static __device__ int   d_part[256];
static __device__ float d_xp[(size_t)NN * 32];
static __device__ float d_mx[(size_t)MP * 48];
static __device__ float d_wc1[256 * 48];
static __device__ unsigned int d_h1h[(size_t)MP * 128];   // h1 as packed bf16x2
static __device__ __nv_bfloat16 d_wc2h[256 * 256];
static __device__ float d_pq2[(size_t)MP * 256];          // q half (128..255) fp32
static __device__ unsigned int d_p2h[(size_t)MP * 64];    // p as packed bf16x2
static __device__ unsigned int d_h2h[(size_t)MP * 64];    // h2 as packed bf16x2
static __device__ __nv_bfloat16 d_wc3h[128 * 128];
static __device__ float d_pq3[(size_t)MP * 128];  // [p(64)|q(64)]
static __device__ float d_h3[(size_t)MP * 64];
static __device__ float d_w1p[128 * 64];
static __device__ float d_m1[256 * 13 * 11 * 11];
static __device__ float d_xcol[(size_t)896 * 6912];
static __device__ float d_cg[896 * 128];
static __device__ float d_m2[128 * 891];
static __device__ float d_wmpart[8][64];
static __device__ float d_mnorm[64];
static __device__ float d_rvec[64];
static __device__ float d_pmin[NBC];
static __device__ float d_pmax[NBC];
static __device__ float d_hstats[4];
static __device__ int   d_koff[6912];
static __device__ int   d_poff[896];

// ---------------- merged weight packing + im2col tables ----------------
__global__ void k_packAll(const float* __restrict__ Wl1, const float* __restrict__ Wr1,
                          const float* __restrict__ Wl2, const float* __restrict__ Wr2,
                          const float* __restrict__ Wl3, const float* __restrict__ Wr3,
                          const float* __restrict__ W1) {
    int i = blockIdx.x * blockDim.x + threadIdx.x;
    if (i < 12288) {
        int n = i / 48, f = i % 48;
        float v = 0.f;
        if (f < 21) v = Wl1[n * 21 + f];
        else if (f < 42) v = Wr1[n * 21 + (f - 21)];
        d_wc1[i] = v;
    } else if (i < 77824) {
        int j = i - 12288;
        int n = j / 256, f = j % 256;
        float v = (n < 128) ? Wl2[n * 256 + f] : Wr2[(n - 128) * 256 + f];
        d_wc2h[j] = __float2bfloat16(v);
    } else if (i < 94208) {
        int j = i - 77824;
        int n = j / 128, f = j % 128;
        float v = (n < 64) ? Wl3[n * 128 + f] : Wr3[(n - 64) * 128 + f];
        d_wc3h[j] = __float2bfloat16(v);
    } else if (i < 102400) {
        int j = i - 94208;
        int n = j / 64;
        d_w1p[j] = (n < 64) ? W1[j] : 0.f;
    } else if (i < 109312) {
        int j = i - 102400;
        int ic = j / 27, tap = j % 27;
        int kd = tap / 9, r = tap % 9, kh = r / 3, kw = r % 3;
        d_koff[j] = ic * 1573 + kd * 121 + kh * 11 + kw;
    } else if (i < 110208) {
        int j = i - 109312;
        int v = 0;
        if (j < 891) {
            int od = j / 81, r2 = j % 81, oh = r2 / 9, ow = r2 % 9;
            v = od * 121 + oh * 11 + ow;
        }
        d_poff[j] = v;
    }
}

// ---------------- CSR build (xpad fused) ----------------
__global__ void k_degcnt(const int* __restrict__ ei, const float* __restrict__ x) {
    int e = blockIdx.x * blockDim.x + threadIdx.x;
    if (e < NE) atomicAdd(&d_cnt[ei[NE + e]], 1);
    if (e < NN * 32) {
        int n = e >> 5, f = e & 31;
        d_xp[e] = (f < 21) ? x[n * 21 + f] : 0.f;
    }
}
__global__ void k_scan1() {
    __shared__ int sh[256];
    int t = threadIdx.x;
    int i = blockIdx.x * 256 + t;
    int v = (i < NN) ? d_cnt[i] : 0;
    sh[t] = v;
    __syncthreads();
#pragma unroll
    for (int off = 1; off < 256; off <<= 1) {
        int a = (t >= off) ? sh[t - off] : 0;
        __syncthreads();
        sh[t] += a;
        __syncthreads();
    }
    if (i < NN) d_rowptr[i] = sh[t] - v;
    if (t == 255) d_part[blockIdx.x] = sh[255];
}
__global__ void k_scan3() {
    __shared__ int sh[256];
    int t = threadIdx.x;
    int v = (t < NB1) ? d_part[t] : 0;
    sh[t] = v;
    __syncthreads();
#pragma unroll
    for (int off = 1; off < 256; off <<= 1) {
        int a = (t >= off) ? sh[t - off] : 0;
        __syncthreads();
        sh[t] += a;
        __syncthreads();
    }
    int base = (blockIdx.x > 0) ? sh[blockIdx.x - 1] : 0;
    int i = blockIdx.x * 256 + t;
    if (i < NN) {
        int r = d_rowptr[i] + base;
        d_rowptr[i] = r;
        d_cursor[i] = r;
    }
    if (i == 0) d_rowptr[NN] = NE;
}
__global__ void k_scatter(const int* __restrict__ ei) {
    int e = blockIdx.x * blockDim.x + threadIdx.x;
    if (e >= NE) return;
    int s = ei[e], d = ei[NE + e];
    int pos = atomicAdd(&d_cursor[d], 1);
    d_csrc[pos] = s;
}

// ---------------- aggregation ----------------
__global__ void k_aggA() {
    int w = (blockIdx.x * blockDim.x + threadIdx.x) >> 5;
    int lane = threadIdx.x & 31;
    int sub = lane >> 3;
    int sl = lane & 7;
    if (w >= NN) return;
    int beg = d_rowptr[w], end = d_rowptr[w + 1];
    float4 acc = make_float4(0.f, 0.f, 0.f, 0.f);
#pragma unroll 2
    for (int e = beg + sub; e < end; e += 4) {
        int s = __ldg(&d_csrc[e]);
        float4 v = *(const float4*)&d_xp[(size_t)s * 32 + sl * 4];
        acc.x += v.x; acc.y += v.y; acc.z += v.z; acc.w += v.w;
    }
    acc.x += __shfl_xor_sync(0xffffffffu, acc.x, 8);
    acc.y += __shfl_xor_sync(0xffffffffu, acc.y, 8);
    acc.z += __shfl_xor_sync(0xffffffffu, acc.z, 8);
    acc.w += __shfl_xor_sync(0xffffffffu, acc.w, 8);
    acc.x += __shfl_xor_sync(0xffffffffu, acc.x, 16);
    acc.y += __shfl_xor_sync(0xffffffffu, acc.y, 16);
    acc.z += __shfl_xor_sync(0xffffffffu, acc.z, 16);
    acc.w += __shfl_xor_sync(0xffffffffu, acc.w, 16);
    float inv = 1.f / fmaxf((float)(end - beg), 1.0f);
    if (sub == 0) {
        float m[4] = {acc.x * inv, acc.y * inv, acc.z * inv, acc.w * inv};
#pragma unroll
        for (int c = 0; c < 4; c++) {
            int f = sl * 4 + c;
            if (f < 21) d_mx[(size_t)w * 48 + f] = m[c];
        }
    }
    float xo = d_xp[(size_t)w * 32 + lane];
    if (lane < 21) d_mx[(size_t)w * 48 + 21 + lane] = xo;
    else if (lane < 27) d_mx[(size_t)w * 48 + 21 + lane] = 0.f;
}
__global__ void k_aggB(const float* __restrict__ bl) {
    int w = (blockIdx.x * blockDim.x + threadIdx.x) >> 5;
    int lane = threadIdx.x & 31;
    int half = lane >> 4;
    int sl = lane & 15;
    if (w >= NN) return;
    int beg = d_rowptr[w], end = d_rowptr[w + 1];
    float4 a0 = make_float4(0.f, 0.f, 0.f, 0.f);
    float4 a1 = make_float4(0.f, 0.f, 0.f, 0.f);
#pragma unroll 2
    for (int e = beg + half; e < end; e += 2) {
        int s = __ldg(&d_csrc[e]);
        uint4 v = *(const uint4*)&d_p2h[(size_t)s * 64 + sl * 4];
        float2 f0 = __bfloat1622float2(*(__nv_bfloat162*)&v.x);
        float2 f1 = __bfloat1622float2(*(__nv_bfloat162*)&v.y);
        float2 f2 = __bfloat1622float2(*(__nv_bfloat162*)&v.z);
        float2 f3 = __bfloat1622float2(*(__nv_bfloat162*)&v.w);
        a0.x += f0.x; a0.y += f0.y; a0.z += f1.x; a0.w += f1.y;
        a1.x += f2.x; a1.y += f2.y; a1.z += f3.x; a1.w += f3.y;
    }
    a0.x += __shfl_xor_sync(0xffffffffu, a0.x, 16);
    a0.y += __shfl_xor_sync(0xffffffffu, a0.y, 16);
    a0.z += __shfl_xor_sync(0xffffffffu, a0.z, 16);
    a0.w += __shfl_xor_sync(0xffffffffu, a0.w, 16);
    a1.x += __shfl_xor_sync(0xffffffffu, a1.x, 16);
    a1.y += __shfl_xor_sync(0xffffffffu, a1.y, 16);
    a1.z += __shfl_xor_sync(0xffffffffu, a1.z, 16);
    a1.w += __shfl_xor_sync(0xffffffffu, a1.w, 16);
    if (half == 0) {
        float inv = 1.f / fmaxf((float)(end - beg), 1.0f);
        const float4* pq = (const float4*)d_pq2;
        float4 q0 = pq[(size_t)w * 64 + 32 + sl * 2];
        float4 q1 = pq[(size_t)w * 64 + 32 + sl * 2 + 1];
        float4 b0 = ((const float4*)bl)[sl * 2];
        float4 b1 = ((const float4*)bl)[sl * 2 + 1];
        float o[8];
        o[0] = fmaxf(a0.x * inv + b0.x + q0.x, 0.f);
        o[1] = fmaxf(a0.y * inv + b0.y + q0.y, 0.f);
        o[2] = fmaxf(a0.z * inv + b0.z + q0.z, 0.f);
        o[3] = fmaxf(a0.w * inv + b0.w + q0.w, 0.f);
        o[4] = fmaxf(a1.x * inv + b1.x + q1.x, 0.f);
        o[5] = fmaxf(a1.y * inv + b1.y + q1.y, 0.f);
        o[6] = fmaxf(a1.z * inv + b1.z + q1.z, 0.f);
        o[7] = fmaxf(a1.w * inv + b1.w + q1.w, 0.f);
        unsigned int u[4];
#pragma unroll
        for (int t = 0; t < 4; t++) {
            __nv_bfloat162 h = __floats2bfloat162_rn(o[2 * t], o[2 * t + 1]);
            u[t] = *(unsigned int*)&h;
        }
        *(uint4*)&d_h2h[(size_t)w * 64 + sl * 4] = make_uint4(u[0], u[1], u[2], u[3]);
    }
}
__global__ void k_aggC(const float* __restrict__ bl) {
    __shared__ float smn[256], smx[256];
    int tid = threadIdx.x;
    int g = (blockIdx.x * 256 + tid) >> 4;
    int lane = tid & 15;
    float lmn = 3.4e38f, lmx = -3.4e38f;
    if (g < NN) {
        int beg = d_rowptr[g], end = d_rowptr[g + 1];
        const float4* pq = (const float4*)d_pq3;
        float4 acc = make_float4(0.f, 0.f, 0.f, 0.f);
#pragma unroll 4
        for (int e = beg; e < end; e++) {
            int s = __ldg(&d_csrc[e]);
            float4 v = pq[(size_t)s * 32 + lane];
            acc.x += v.x; acc.y += v.y; acc.z += v.z; acc.w += v.w;
        }
        float inv = 1.f / fmaxf((float)(end - beg), 1.0f);
        float4 q = pq[(size_t)g * 32 + 16 + lane];
        float4 b = ((const float4*)bl)[lane];
        float4 o;
        o.x = acc.x * inv + b.x + q.x;
        o.y = acc.y * inv + b.y + q.y;
        o.z = acc.z * inv + b.z + q.z;
        o.w = acc.w * inv + b.w + q.w;
        ((float4*)d_h3)[(size_t)g * 16 + lane] = o;
        lmn = fminf(fminf(o.x, o.y), fminf(o.z, o.w));
        lmx = fmaxf(fmaxf(o.x, o.y), fmaxf(o.z, o.w));
    }
    smn[tid] = lmn; smx[tid] = lmx;
    __syncthreads();
    for (int st = 128; st > 0; st >>= 1) {
        if (tid < st) {
            smn[tid] = fminf(smn[tid], smn[tid + st]);
            smx[tid] = fmaxf(smx[tid], smx[tid + st]);
        }
        __syncthreads();
    }
    if (tid == 0) { d_pmin[blockIdx.x] = smn[0]; d_pmax[blockIdx.x] = smx[0]; }
}

#define CPA(dst, src) \
    asm volatile("cp.async.cg.shared.global [%0], [%1], 16;" :: "r"(dst), "l"(src))
#define CPCOMMIT() asm volatile("cp.async.commit_group;" ::: "memory")
#define CPWAIT1() asm volatile("cp.async.wait_group 1;" ::: "memory")
#define CPWAIT0() asm volatile("cp.async.wait_group 0;" ::: "memory")

// ---------------- cp.async tf32 GEMM (fp32 in) ----------------
// mode 3: split-K atomicAdd   mode 4: fused head   mode 5: bias+relu+bf16 pack -> d_h1h
__global__ void __launch_bounds__(256, 2) k_tgemmA(
    const float* __restrict__ A, const float* __restrict__ B, float* __restrict__ C,
    int N, int K, const float* __restrict__ bias, int mode,
    const float* __restrict__ W2p, const float* __restrict__ b2p) {
    extern __shared__ float sm[];
    float* Asm = sm;
    float* Bsm = sm + 3 * 2560;
    int tid = threadIdx.x;
    int wid = tid >> 5;
    int lane = tid & 31;
    int bm = blockIdx.y * 128;
    int bn = blockIdx.x * 128;
    int wm = (wid >> 2) * 64;
    int wn = (wid & 3) * 32;
    int lrow = tid >> 1;
    int lcol = (tid & 1) * 8;
    int nkz = (K / 16) / gridDim.z;
    int kbase = blockIdx.z * nkz * 16;

    const float* Ap = A + (size_t)(bm + lrow) * K + kbase + lcol;
    const float* Bp = B + (size_t)(bn + lrow) * K + kbase + lcol;
    unsigned aS = (unsigned)__cvta_generic_to_shared(Asm + lrow * 20 + lcol);
    unsigned bS = (unsigned)__cvta_generic_to_shared(Bsm + lrow * 20 + lcol);

#define ISSUE(s, koff)                                      \
    do {                                                    \
        unsigned _ao = aS + (s) * 10240;                    \
        unsigned _bo = bS + (s) * 10240;                    \
        CPA(_ao, Ap + (koff)); CPA(_ao + 16, Ap + (koff) + 4); \
        CPA(_bo, Bp + (koff)); CPA(_bo + 16, Bp + (koff) + 4); \
    } while (0)

    wmma::fragment<wmma::accumulator, 16, 16, 8, float> cf[4][2];
#pragma unroll
    for (int i = 0; i < 4; i++)
#pragma unroll
        for (int j = 0; j < 2; j++) wmma::fill_fragment(cf[i][j], 0.f);

    ISSUE(0, 0); CPCOMMIT();
    if (nkz > 1) { ISSUE(1, 16); CPCOMMIT(); }
    else CPCOMMIT();

    for (int it = 0; it < nkz; it++) {
        CPWAIT1();
        __syncthreads();
        if (it + 2 < nkz) ISSUE((it + 2) % 3, (it + 2) * 16);
        CPCOMMIT();
        int buf = it % 3;
        float* Ab = Asm + buf * 2560;
        float* Bb = Bsm + buf * 2560;
#pragma unroll
        for (int ks = 0; ks < 16; ks += 8) {
            wmma::fragment<wmma::matrix_a, 16, 16, 8, wmma::precision::tf32, wmma::row_major> af[4];
            wmma::fragment<wmma::matrix_b, 16, 16, 8, wmma::precision::tf32, wmma::col_major> bf[2];
#pragma unroll
            for (int i = 0; i < 4; i++)
                wmma::load_matrix_sync(af[i], Ab + (wm + i * 16) * 20 + ks, 20);
#pragma unroll
            for (int j = 0; j < 2; j++)
                wmma::load_matrix_sync(bf[j], Bb + (wn + j * 16) * 20 + ks, 20);
#pragma unroll
            for (int i = 0; i < 4; i++)
#pragma unroll
                for (int j = 0; j < 2; j++)
                    wmma::mma_sync(cf[i][j], af[i], bf[j], cf[i][j]);
        }
    }
    CPWAIT0();
    __syncthreads();

    if (mode == 0) {
#pragma unroll
        for (int i = 0; i < 4; i++)
#pragma unroll
            for (int j = 0; j < 2; j++)
                wmma::store_matrix_sync(&C[(size_t)(bm + wm + i * 16) * N + bn + wn + j * 16],
                                        cf[i][j], N, wmma::mem_row_major);
    } else if (mode == 5) {  // bias+relu, pack bf16 -> d_h1h
        float* stage = Asm + wid * 320;
        int r = lane >> 1, cu = (lane & 1) * 4;
#pragma unroll
        for (int i = 0; i < 4; i++)
#pragma unroll
            for (int j = 0; j < 2; j++) {
                wmma::store_matrix_sync(stage, cf[i][j], 20, wmma::mem_row_major);
                __syncwarp();
                const float* sp = stage + r * 20 + cu * 2;
                const float* bp = bias + bn + wn + j * 16 + cu * 2;
                unsigned int o[4];
#pragma unroll
                for (int t = 0; t < 4; t++) {
                    float v0 = fmaxf(sp[2 * t] + bp[2 * t], 0.f);
                    float v1 = fmaxf(sp[2 * t + 1] + bp[2 * t + 1], 0.f);
                    __nv_bfloat162 h = __floats2bfloat162_rn(v0, v1);
                    o[t] = *(unsigned int*)&h;
                }
                *(uint4*)&d_h1h[(size_t)(bm + wm + i * 16 + r) * 128 +
                                ((bn + wn + j * 16) >> 1) + cu] =
                    make_uint4(o[0], o[1], o[2], o[3]);
                __syncwarp();
            }
    } else if (mode == 3) {
        float* stage = Asm + wid * 320;
#pragma unroll
        for (int i = 0; i < 4; i++)
#pragma unroll
            for (int j = 0; j < 2; j++) {
                wmma::store_matrix_sync(stage, cf[i][j], 20, wmma::mem_row_major);
                __syncwarp();
                float* cp = &C[(size_t)(bm + wm + i * 16) * N + bn + wn + j * 16];
#pragma unroll
                for (int e = 0; e < 8; e++) {
                    int idx = lane * 8 + e;
                    int r2 = idx >> 4, c2 = idx & 15;
                    atomicAdd(&cp[(size_t)r2 * N + c2], stage[r2 * 20 + c2]);
                }
                __syncwarp();
            }
    } else {  // mode 4: fused head (grid.x==1; only cols 0..63 valid)
        float* ybuf = sm;
        float* w2s = sm + 128 * 68;
        float* rv = w2s + 192;
        float* cts = rv + 64;
        if (wn < 64) {
#pragma unroll
            for (int i = 0; i < 4; i++)
#pragma unroll
                for (int j = 0; j < 2; j++)
                    wmma::store_matrix_sync(ybuf + (wm + i * 16) * 68 + wn + j * 16,
                                            cf[i][j], 68, wmma::mem_row_major);
        }
        if (tid < 192) w2s[tid] = W2p[tid];
        else if (tid < 195) cts[1 + tid - 192] = b2p[tid - 192];
        else if (tid == 195) cts[0] = bias[0];
        if (tid < 64) rv[tid] = d_rvec[tid];
        __syncthreads();
        if (tid < 128) {
            int row = bm + tid;
            if (row < NN) {
                float a = cts[0];
                float s0 = cts[1], s1 = cts[2], s2 = cts[3];
                const float* yr = ybuf + tid * 68;
#pragma unroll
                for (int f = 0; f < 64; f++) {
                    float v = fmaxf(a * yr[f] + rv[f], 0.f);
                    s0 += v * w2s[f];
                    s1 += v * w2s[64 + f];
                    s2 += v * w2s[128 + f];
                }
                float m = fmaxf(s0, fmaxf(s1, s2));
                float e0 = expf(s0 - m), e1 = expf(s1 - m), e2 = expf(s2 - m);
                float inv = 1.f / (e0 + e1 + e2);
                C[(size_t)row * 3 + 0] = e0 * inv;
                C[(size_t)row * 3 + 1] = e1 * inv;
                C[(size_t)row * 3 + 2] = e2 * inv;
            }
        }
    }
#undef ISSUE
}

// ---------------- cp.async bf16 GEMM (BK=32, 3-stage) ----------------
// C[.,N] = A[.,K] @ B[N,K]^T, bf16 in, fp32 accum. K % 32 == 0.
// mode 0: fp32 store   mode 2: blockIdx.x==0 -> bf16 pack to d_p2h, else fp32
__global__ void __launch_bounds__(256, 2) k_tgemmH(
    const __nv_bfloat16* __restrict__ A, const __nv_bfloat16* __restrict__ B,
    float* __restrict__ C, int N, int K, int mode) {
    extern __shared__ float sm[];
    __nv_bfloat16* Asm = (__nv_bfloat16*)sm;                  // [3][128][40]
    __nv_bfloat16* Bsm = (__nv_bfloat16*)(sm + 3 * 2560);     // [3][128][40]
    int tid = threadIdx.x;
    int wid = tid >> 5;
    int lane = tid & 31;
    int bm = blockIdx.y * 128;
    int bn = blockIdx.x * 128;
    int wm = (wid >> 2) * 64;
    int wn = (wid & 3) * 32;
    int lrow = tid >> 1;
    int lcol = (tid & 1) * 16;   // bf16 elements
    int nkz = K / 32;

    const __nv_bfloat16* Ap = A + (size_t)(bm + lrow) * K + lcol;
    const __nv_bfloat16* Bp = B + (size_t)(bn + lrow) * K + lcol;
    unsigned aS = (unsigned)__cvta_generic_to_shared(Asm + lrow * 40 + lcol);
    unsigned bS = (unsigned)__cvta_generic_to_shared(Bsm + lrow * 40 + lcol);

#define ISSUEH(s, koff)                                     \
    do {                                                    \
        unsigned _ao = aS + (s) * 10240;                    \
        unsigned _bo = bS + (s) * 10240;                    \
        CPA(_ao, Ap + (koff)); CPA(_ao + 16, Ap + (koff) + 8); \
        CPA(_bo, Bp + (koff)); CPA(_bo + 16, Bp + (koff) + 8); \
    } while (0)

    wmma::fragment<wmma::accumulator, 16, 16, 16, float> cf[4][2];
#pragma unroll
    for (int i = 0; i < 4; i++)
#pragma unroll
        for (int j = 0; j < 2; j++) wmma::fill_fragment(cf[i][j], 0.f);

    ISSUEH(0, 0); CPCOMMIT();
    if (nkz > 1) { ISSUEH(1, 32); CPCOMMIT(); }
    else CPCOMMIT();

    for (int it = 0; it < nkz; it++) {
        CPWAIT1();
        __syncthreads();
        if (it + 2 < nkz) ISSUEH((it + 2) % 3, (it + 2) * 32);
        CPCOMMIT();
        int buf = it % 3;
        __nv_bfloat16* Ab = Asm + buf * 5120;
        __nv_bfloat16* Bb = Bsm + buf * 5120;
#pragma unroll
        for (int ks = 0; ks < 32; ks += 16) {
            wmma::fragment<wmma::matrix_a, 16, 16, 16, __nv_bfloat16, wmma::row_major> af[4];
            wmma::fragment<wmma::matrix_b, 16, 16, 16, __nv_bfloat16, wmma::col_major> bf[2];
#pragma unroll
            for (int i = 0; i < 4; i++)
                wmma::load_matrix_sync(af[i], Ab + (wm + i * 16) * 40 + ks, 40);
#pragma unroll
            for (int j = 0; j < 2; j++)
                wmma::load_matrix_sync(bf[j], Bb + (wn + j * 16) * 40 + ks, 40);
#pragma unroll
            for (int i = 0; i < 4; i++)
#pragma unroll
                for (int j = 0; j < 2; j++)
                    wmma::mma_sync(cf[i][j], af[i], bf[j], cf[i][j]);
        }
    }
    CPWAIT0();
    __syncthreads();

    if (mode == 0 || (mode == 2 && blockIdx.x != 0)) {
#pragma unroll
        for (int i = 0; i < 4; i++)
#pragma unroll
            for (int j = 0; j < 2; j++)
                wmma::store_matrix_sync(&C[(size_t)(bm + wm + i * 16) * N + bn + wn + j * 16],
                                        cf[i][j], N, wmma::mem_row_major);
    } else {  // mode 2, blockIdx.x == 0: pack p-half to d_p2h
        float* stage = sm + wid * 320;
        int r = lane >> 1, cu = (lane & 1) * 4;
#pragma unroll
        for (int i = 0; i < 4; i++)
#pragma unroll
            for (int j = 0; j < 2; j++) {
                wmma::store_matrix_sync(stage, cf[i][j], 20, wmma::mem_row_major);
                __syncwarp();
                const float* sp = stage + r * 20 + cu * 2;
                unsigned int o[4];
#pragma unroll
                for (int t = 0; t < 4; t++) {
                    __nv_bfloat162 h = __floats2bfloat162_rn(sp[2 * t], sp[2 * t + 1]);
                    o[t] = *(unsigned int*)&h;
                }
                *(uint4*)&d_p2h[(size_t)(bm + wm + i * 16 + r) * 64 +
                                ((wn + j * 16) >> 1) + cu] =
                    make_uint4(o[0], o[1], o[2], o[3]);
                __syncwarp();
            }
    }
#undef ISSUEH
}

// ---------------- map encoder ----------------
__global__ void k_conv1(const float* __restrict__ in, const float* __restrict__ w,
                        const float* __restrict__ b) {
    int idx = blockIdx.x * blockDim.x + threadIdx.x;
    if (idx >= 256 * 1573) return;
    int oc = idx / 1573, p = idx % 1573;
    int od = p / 121, r = p % 121, oh = r / 11, ow = r % 11;
    const float* wp = w + oc * 75;
    float acc = 0.f;
#pragma unroll
    for (int kd = 0; kd < 3; kd++)
#pragma unroll
        for (int kh = 0; kh < 5; kh++)
#pragma unroll
            for (int kw = 0; kw < 5; kw++)
                acc += in[(od + kd) * 225 + (oh + kh) * 15 + (ow + kw)] *
                       wp[kd * 25 + kh * 5 + kw];
    d_m1[idx] = fmaxf(acc + b[oc], 0.f);
}

__global__ void k_im2col() {
    int k = blockIdx.x * 256 + threadIdx.x;
    int pos = blockIdx.y;
    d_xcol[(size_t)pos * 6912 + k] = d_m1[d_koff[k] + d_poff[pos]];
}

__global__ void k_m2fin(const float* __restrict__ cb2) {
    int idx = blockIdx.x * blockDim.x + threadIdx.x;
    if (idx >= 128 * 891) return;
    int oc = idx / 891, pos = idx % 891;
    d_m2[idx] = fmaxf(d_cg[(size_t)pos * 128 + oc] + cb2[oc], 0.f);
}

__global__ void k_wm(const float* __restrict__ Wm) {
    __shared__ float red[256];
    int o = blockIdx.x;
    int chunk = blockIdx.y;
    const int CH = 114048 / 8;
    int base = chunk * CH;
    const float* wr = Wm + (size_t)o * 114048 + base;
    const float* mv = d_m2 + base;
    float s = 0.f;
    for (int i = threadIdx.x * 4; i < CH; i += 256 * 4) {
        float4 a = *(const float4*)(wr + i);
        float4 v = *(const float4*)(mv + i);
        s += a.x * v.x + a.y * v.y + a.z * v.z + a.w * v.w;
    }
    red[threadIdx.x] = s;
    __syncthreads();
    for (int st = 128; st > 0; st >>= 1) {
        if (threadIdx.x < st) red[threadIdx.x] += red[threadIdx.x + st];
        __syncthreads();
    }
    if (threadIdx.x == 0) d_wmpart[chunk][o] = red[0];
}

// ---------------- final stats + rvec ----------------
__global__ void k_finstats(const float* __restrict__ bm, const float* __restrict__ b1) {
    __shared__ float smn[256], smx[256];
    __shared__ float mloc[64];
    int t = threadIdx.x;
    float mn = 3.4e38f, mx = -3.4e38f;
    for (int i = t; i < NBC; i += 256) {
        mn = fminf(mn, d_pmin[i]);
        mx = fmaxf(mx, d_pmax[i]);
    }
    smn[t] = mn; smx[t] = mx;
    __syncthreads();
    for (int st = 128; st > 0; st >>= 1) {
        if (t < st) {
            smn[t] = fminf(smn[t], smn[t + st]);
            smx[t] = fmaxf(smx[t], smx[t + st]);
        }
        __syncthreads();
    }
    float hs1v;
    {
        float lo = smn[0], hi = smx[0];
        float a = 0.35f / (hi - lo);
        hs1v = -lo * a;
        if (t == 0) {
            d_hstats[0] = a;
            d_hstats[1] = hs1v;
        }
    }
    __syncthreads();
    float v = 0.f;
    if (t < 64) {
        v = bm[t];
#pragma unroll
        for (int c = 0; c < 8; c++) v += d_wmpart[c][t];
    }
    smn[t] = (t < 64) ? v : 3.4e38f;
    smx[t] = (t < 64) ? v : -3.4e38f;
    __syncthreads();
    for (int st = 128; st > 0; st >>= 1) {
        if (t < st) {
            smn[t] = fminf(smn[t], smn[t + st]);
            smx[t] = fmaxf(smx[t], smx[t + st]);
        }
        __syncthreads();
    }
    if (t < 64) {
        float lo = smn[0], hi = smx[0];
        float m = 0.65f * (v - lo) / (hi - lo);
        d_mnorm[t] = m;
        mloc[t] = m;
    }
    __syncthreads();
    if (t < 64) {
        float s = b1[t];
        const float* wr = d_w1p + t * 64;
#pragma unroll 8
        for (int k = 0; k < 64; k++) s += wr[k] * (hs1v + mloc[k]);
        d_rvec[t] = s;
    }
}

// ---------------- launch ----------------
extern "C" void kernel_launch(void* const* d_in, const int* in_sizes, int n_in,
                              void* d_out, int out_size) {
    (void)in_sizes; (void)n_in; (void)out_size;
    const float* node = (const float*)d_in[0];
    const int* ei = (const int*)d_in[1];
    const float* mapd = (const float*)d_in[2];
    const float* bl1 = (const float*)d_in[4];
    const float* bl2 = (const float*)d_in[7];
    const float* bl3 = (const float*)d_in[10];
    const float* k1 = (const float*)d_in[12];
    const float* cb1 = (const float*)d_in[13];
    const float* k2 = (const float*)d_in[14];
    const float* cb2 = (const float*)d_in[15];
    const float* Wm = (const float*)d_in[16];
    const float* bm = (const float*)d_in[17];
    const float* b1 = (const float*)d_in[19];
    const float* W2 = (const float*)d_in[20];
    const float* b2 = (const float*)d_in[21];
    float* out = (float*)d_out;

    cudaFuncSetAttribute(k_tgemmA, cudaFuncAttributeMaxDynamicSharedMemorySize, TGA_SMEM);
    cudaFuncSetAttribute(k_tgemmH, cudaFuncAttributeMaxDynamicSharedMemorySize, TGA_SMEM);

    void *p_cnt, *p_cg;
    void *p_mx, *p_wc1, *p_h1h, *p_wc2h, *p_pq2, *p_h2h, *p_wc3h, *p_pq3, *p_h3;
    void *p_w1p, *p_xcol, *p_hstats;
    cudaGetSymbolAddress(&p_cnt, d_cnt);
    cudaGetSymbolAddress(&p_cg, d_cg);
    cudaGetSymbolAddress(&p_mx, d_mx);
    cudaGetSymbolAddress(&p_wc1, d_wc1);
    cudaGetSymbolAddress(&p_h1h, d_h1h);
    cudaGetSymbolAddress(&p_wc2h, d_wc2h);
    cudaGetSymbolAddress(&p_pq2, d_pq2);
    cudaGetSymbolAddress(&p_h2h, d_h2h);
    cudaGetSymbolAddress(&p_wc3h, d_wc3h);
    cudaGetSymbolAddress(&p_pq3, d_pq3);
    cudaGetSymbolAddress(&p_h3, d_h3);
    cudaGetSymbolAddress(&p_w1p, d_w1p);
    cudaGetSymbolAddress(&p_xcol, d_xcol);
    cudaGetSymbolAddress(&p_hstats, d_hstats);

    cudaStream_t s2;
    cudaStreamCreateWithFlags(&s2, cudaStreamNonBlocking);
    cudaEvent_t evFork, evJoin;
    cudaEventCreateWithFlags(&evFork, cudaEventDisableTiming);
    cudaEventCreateWithFlags(&evJoin, cudaEventDisableTiming);

    // 1: memset(cnt)  2: memset(cg)  3: packAll
    cudaMemsetAsync(p_cnt, 0, NN * sizeof(int));
    cudaMemsetAsync(p_cg, 0, 896 * 128 * sizeof(float));
    k_packAll<<<431, 256>>>((const float*)d_in[3], (const float*)d_in[5],
                            (const float*)d_in[6], (const float*)d_in[8],
                            (const float*)d_in[9], (const float*)d_in[11],
                            (const float*)d_in[18]);

    // fork conv path onto s2
    cudaEventRecord(evFork, 0);
    cudaStreamWaitEvent(s2, evFork, 0);

    // conv path on s2
    k_conv1<<<(256 * 1573 + 255) / 256, 256, 0, s2>>>(mapd, k1, cb1);
    k_im2col<<<dim3(27, 891), 256, 0, s2>>>();
    k_tgemmA<<<dim3(1, 7, 16), 256, TGA_SMEM, s2>>>((const float*)p_xcol, k2,
                                                    (float*)p_cg, 128, 6912,
                                                    nullptr, 3, nullptr, nullptr);
    k_m2fin<<<(128 * 891 + 255) / 256, 256, 0, s2>>>(cb2);
    k_wm<<<dim3(64, 8), 256, 0, s2>>>(Wm);
    cudaEventRecord(evJoin, s2);

    // GNN path on main stream
    k_degcnt<<<(NN * 32 + 255) / 256, 256>>>(ei, node);
    k_scan1<<<NB1, 256>>>();
    k_scan3<<<NB1, 256>>>();
    k_scatter<<<(NE + 255) / 256, 256>>>(ei);

    k_aggA<<<(NN * 32 + 255) / 256, 256>>>();
    // GEMM1 (tf32): epilogue bias+relu+bf16 pack -> d_h1h
    k_tgemmA<<<dim3(2, 391, 1), 256, TGA_SMEM>>>((const float*)p_mx, (const float*)p_wc1,
                                                 nullptr, 256, 48, bl1, 5,
                                                 nullptr, nullptr);
    // GEMM2 (bf16): p-half packed to d_p2h, q-half fp32 to pq2
    k_tgemmH<<<dim3(2, 391, 1), 256, TGA_SMEM>>>((const __nv_bfloat16*)p_h1h,
                                                 (const __nv_bfloat16*)p_wc2h,
                                                 (float*)p_pq2, 256, 256, 2);
    k_aggB<<<(NN * 32 + 255) / 256, 256>>>(bl2);
    // GEMM3 (bf16): fp32 out
    k_tgemmH<<<dim3(1, 391, 1), 256, TGA_SMEM>>>((const __nv_bfloat16*)p_h2h,
                                                 (const __nv_bfloat16*)p_wc3h,
                                                 (float*)p_pq3, 128, 128, 0);
    k_aggC<<<NBC, 256>>>(bl3);

    // join conv path before finstats
    cudaStreamWaitEvent(0, evJoin, 0);
    k_finstats<<<1, 256>>>(bm, b1);
    // GEMM4 (tf32) + fused head
    k_tgemmA<<<dim3(1, 391, 1), 256, TGA_SMEM>>>((const float*)p_h3, (const float*)p_w1p,
                                                 out, 128, 64, (const float*)p_hstats, 4,
                                                 W2, b2);

    cudaEventDestroy(evFork);
    cudaEventDestroy(evJoin);
    cudaStreamDestroy(s2);
}

// round 16
// speedup vs baseline: 1.6218x; 1.0362x over previous
#include <cuda_runtime.h>
#include <cuda_bf16.h>
#include <mma.h>
#include <math.h>

using namespace nvcuda;

#define NN 50000
#define MP 50048   // padded rows: 391 * 128
#define NE 800000
#define NB1 196    // ceil(NN/256)
#define NBC 3125   // aggC grid = NN*16/256
#define TGA_SMEM 61440

// ---------------- scratch ----------------
static __device__ int   d_cnt[NN];
static __device__ int   d_rowptr[NN + 1];
static __device__ int   d_cursor[NN];
static __device__ int   d_csrc[NE];
static __device__ int   d_part[256];
static __device__ float d_xp[(size_t)NN * 32];
static __device__ unsigned int d_mxh[(size_t)MP * 32];    // [mean21|x21|0] bf16x2
static __device__ __nv_bfloat16 d_wc1h[256 * 64];
static __device__ unsigned int d_h1h[(size_t)MP * 128];   // h1 bf16x2
static __device__ __nv_bfloat16 d_wc2h[256 * 256];
static __device__ float d_pq2[(size_t)MP * 256];          // q half (128..255) fp32
static __device__ unsigned int d_p2h[(size_t)MP * 64];    // p bf16x2
static __device__ unsigned int d_h2h[(size_t)MP * 64];    // h2 bf16x2
static __device__ __nv_bfloat16 d_wc3h[128 * 128];
static __device__ float d_pq3[(size_t)MP * 128];  // [p(64)|q(64)]
static __device__ float d_h3[(size_t)MP * 64];
static __device__ float d_w1p[128 * 64];
static __device__ float d_m1[256 * 13 * 11 * 11];
static __device__ __nv_bfloat16 d_xcolh[(size_t)896 * 6912];
static __device__ __nv_bfloat16 d_k2h[(size_t)128 * 6912];
static __device__ float d_cg[896 * 128];
static __device__ float d_m2[128 * 891];
static __device__ float d_wmpart[8][64];
static __device__ float d_mnorm[64];
static __device__ float d_rvec[64];
static __device__ float d_pmin[NBC];
static __device__ float d_pmax[NBC];
static __device__ float d_hstats[4];
static __device__ int   d_koff[6912];
static __device__ int   d_poff[896];

// ---------------- merged weight packing + im2col tables ----------------
// [0,16384):wc1h  [16384,81920):wc2h  [81920,98304):wc3h  [98304,106496):w1p
// [106496,113408):koff  [113408,114304):poff
__global__ void k_packAll(const float* __restrict__ Wl1, const float* __restrict__ Wr1,
                          const float* __restrict__ Wl2, const float* __restrict__ Wr2,
                          const float* __restrict__ Wl3, const float* __restrict__ Wr3,
                          const float* __restrict__ W1) {
    int i = blockIdx.x * blockDim.x + threadIdx.x;
    if (i < 16384) {
        int n = i / 64, f = i % 64;
        float v = 0.f;
        if (f < 21) v = Wl1[n * 21 + f];
        else if (f < 42) v = Wr1[n * 21 + (f - 21)];
        d_wc1h[i] = __float2bfloat16(v);
    } else if (i < 81920) {
        int j = i - 16384;
        int n = j / 256, f = j % 256;
        float v = (n < 128) ? Wl2[n * 256 + f] : Wr2[(n - 128) * 256 + f];
        d_wc2h[j] = __float2bfloat16(v);
    } else if (i < 98304) {
        int j = i - 81920;
        int n = j / 128, f = j % 128;
        float v = (n < 64) ? Wl3[n * 128 + f] : Wr3[(n - 64) * 128 + f];
        d_wc3h[j] = __float2bfloat16(v);
    } else if (i < 106496) {
        int j = i - 98304;
        int n = j / 64;
        d_w1p[j] = (n < 64) ? W1[j] : 0.f;
    } else if (i < 113408) {
        int j = i - 106496;
        int ic = j / 27, tap = j % 27;
        int kd = tap / 9, r = tap % 9, kh = r / 3, kw = r % 3;
        d_koff[j] = ic * 1573 + kd * 121 + kh * 11 + kw;
    } else if (i < 114304) {
        int j = i - 113408;
        int v = 0;
        if (j < 891) {
            int od = j / 81, r2 = j % 81, oh = r2 / 9, ow = r2 % 9;
            v = od * 121 + oh * 11 + ow;
        }
        d_poff[j] = v;
    }
}
// pack conv2 weights to bf16 (runs on s2)
__global__ void k_packK2(const float* __restrict__ k2) {
    int i = blockIdx.x * blockDim.x + threadIdx.x;
    if (i < 128 * 6912) d_k2h[i] = __float2bfloat16(k2[i]);
}

// ---------------- CSR build (xpad fused) ----------------
__global__ void k_degcnt(const int* __restrict__ ei, const float* __restrict__ x) {
    int e = blockIdx.x * blockDim.x + threadIdx.x;
    if (e < NE) atomicAdd(&d_cnt[ei[NE + e]], 1);
    if (e < NN * 32) {
        int n = e >> 5, f = e & 31;
        d_xp[e] = (f < 21) ? x[n * 21 + f] : 0.f;
    }
}
__global__ void k_scan1() {
    __shared__ int sh[256];
    int t = threadIdx.x;
    int i = blockIdx.x * 256 + t;
    int v = (i < NN) ? d_cnt[i] : 0;
    sh[t] = v;
    __syncthreads();
#pragma unroll
    for (int off = 1; off < 256; off <<= 1) {
        int a = (t >= off) ? sh[t - off] : 0;
        __syncthreads();
        sh[t] += a;
        __syncthreads();
    }
    if (i < NN) d_rowptr[i] = sh[t] - v;
    if (t == 255) d_part[blockIdx.x] = sh[255];
}
__global__ void k_scan3() {
    __shared__ int sh[256];
    int t = threadIdx.x;
    int v = (t < NB1) ? d_part[t] : 0;
    sh[t] = v;
    __syncthreads();
#pragma unroll
    for (int off = 1; off < 256; off <<= 1) {
        int a = (t >= off) ? sh[t - off] : 0;
        __syncthreads();
        sh[t] += a;
        __syncthreads();
    }
    int base = (blockIdx.x > 0) ? sh[blockIdx.x - 1] : 0;
    int i = blockIdx.x * 256 + t;
    if (i < NN) {
        int r = d_rowptr[i] + base;
        d_rowptr[i] = r;
        d_cursor[i] = r;
    }
    if (i == 0) d_rowptr[NN] = NE;
}
__global__ void k_scatter(const int* __restrict__ ei) {
    int e = blockIdx.x * blockDim.x + threadIdx.x;
    if (e >= NE) return;
    int s = ei[e], d = ei[NE + e];
    int pos = atomicAdd(&d_cursor[d], 1);
    d_csrc[pos] = s;
}

// ---------------- aggregation ----------------
// warp per node; output: 64-wide bf16 row [mean21|x21|0..0] in d_mxh
__global__ void k_aggA() {
    __shared__ float st[8][64];
    int warp = threadIdx.x >> 5;
    int w = (blockIdx.x * blockDim.x + threadIdx.x) >> 5;
    int lane = threadIdx.x & 31;
    int sub = lane >> 3;
    int sl = lane & 7;
    if (w >= NN) return;
    int beg = d_rowptr[w], end = d_rowptr[w + 1];
    float4 acc = make_float4(0.f, 0.f, 0.f, 0.f);
#pragma unroll 2
    for (int e = beg + sub; e < end; e += 4) {
        int s = __ldg(&d_csrc[e]);
        float4 v = *(const float4*)&d_xp[(size_t)s * 32 + sl * 4];
        acc.x += v.x; acc.y += v.y; acc.z += v.z; acc.w += v.w;
    }
    acc.x += __shfl_xor_sync(0xffffffffu, acc.x, 8);
    acc.y += __shfl_xor_sync(0xffffffffu, acc.y, 8);
    acc.z += __shfl_xor_sync(0xffffffffu, acc.z, 8);
    acc.w += __shfl_xor_sync(0xffffffffu, acc.w, 8);
    acc.x += __shfl_xor_sync(0xffffffffu, acc.x, 16);
    acc.y += __shfl_xor_sync(0xffffffffu, acc.y, 16);
    acc.z += __shfl_xor_sync(0xffffffffu, acc.z, 16);
    acc.w += __shfl_xor_sync(0xffffffffu, acc.w, 16);
    float inv = 1.f / fmaxf((float)(end - beg), 1.0f);
    float* row = st[warp];
    if (sub == 0) {
        float m[4] = {acc.x * inv, acc.y * inv, acc.z * inv, acc.w * inv};
#pragma unroll
        for (int c = 0; c < 4; c++) {
            int f = sl * 4 + c;
            if (f < 21) row[f] = m[c];
        }
    }
    float xo = d_xp[(size_t)w * 32 + lane];
    if (lane < 21) row[21 + lane] = xo;
    if (lane < 22) row[42 + lane] = 0.f;
    __syncwarp();
    if (lane < 16) {
        const float* rp = row + lane * 4;
        __nv_bfloat162 h0 = __floats2bfloat162_rn(rp[0], rp[1]);
        __nv_bfloat162 h1 = __floats2bfloat162_rn(rp[2], rp[3]);
        ((uint2*)d_mxh)[(size_t)w * 16 + lane] =
            make_uint2(*(unsigned int*)&h0, *(unsigned int*)&h1);
    }
}
__global__ void k_aggB(const float* __restrict__ bl) {
    int w = (blockIdx.x * blockDim.x + threadIdx.x) >> 5;
    int lane = threadIdx.x & 31;
    int half = lane >> 4;
    int sl = lane & 15;
    if (w >= NN) return;
    int beg = d_rowptr[w], end = d_rowptr[w + 1];
    float4 a0 = make_float4(0.f, 0.f, 0.f, 0.f);
    float4 a1 = make_float4(0.f, 0.f, 0.f, 0.f);
#pragma unroll 2
    for (int e = beg + half; e < end; e += 2) {
        int s = __ldg(&d_csrc[e]);
        uint4 v = *(const uint4*)&d_p2h[(size_t)s * 64 + sl * 4];
        float2 f0 = __bfloat1622float2(*(__nv_bfloat162*)&v.x);
        float2 f1 = __bfloat1622float2(*(__nv_bfloat162*)&v.y);
        float2 f2 = __bfloat1622float2(*(__nv_bfloat162*)&v.z);
        float2 f3 = __bfloat1622float2(*(__nv_bfloat162*)&v.w);
        a0.x += f0.x; a0.y += f0.y; a0.z += f1.x; a0.w += f1.y;
        a1.x += f2.x; a1.y += f2.y; a1.z += f3.x; a1.w += f3.y;
    }
    a0.x += __shfl_xor_sync(0xffffffffu, a0.x, 16);
    a0.y += __shfl_xor_sync(0xffffffffu, a0.y, 16);
    a0.z += __shfl_xor_sync(0xffffffffu, a0.z, 16);
    a0.w += __shfl_xor_sync(0xffffffffu, a0.w, 16);
    a1.x += __shfl_xor_sync(0xffffffffu, a1.x, 16);
    a1.y += __shfl_xor_sync(0xffffffffu, a1.y, 16);
    a1.z += __shfl_xor_sync(0xffffffffu, a1.z, 16);
    a1.w += __shfl_xor_sync(0xffffffffu, a1.w, 16);
    if (half == 0) {
        float inv = 1.f / fmaxf((float)(end - beg), 1.0f);
        const float4* pq = (const float4*)d_pq2;
        float4 q0 = pq[(size_t)w * 64 + 32 + sl * 2];
        float4 q1 = pq[(size_t)w * 64 + 32 + sl * 2 + 1];
        float4 b0 = ((const float4*)bl)[sl * 2];
        float4 b1 = ((const float4*)bl)[sl * 2 + 1];
        float o[8];
        o[0] = fmaxf(a0.x * inv + b0.x + q0.x, 0.f);
        o[1] = fmaxf(a0.y * inv + b0.y + q0.y, 0.f);
        o[2] = fmaxf(a0.z * inv + b0.z + q0.z, 0.f);
        o[3] = fmaxf(a0.w * inv + b0.w + q0.w, 0.f);
        o[4] = fmaxf(a1.x * inv + b1.x + q1.x, 0.f);
        o[5] = fmaxf(a1.y * inv + b1.y + q1.y, 0.f);
        o[6] = fmaxf(a1.z * inv + b1.z + q1.z, 0.f);
        o[7] = fmaxf(a1.w * inv + b1.w + q1.w, 0.f);
        unsigned int u[4];
#pragma unroll
        for (int t = 0; t < 4; t++) {
            __nv_bfloat162 h = __floats2bfloat162_rn(o[2 * t], o[2 * t + 1]);
            u[t] = *(unsigned int*)&h;
        }
        *(uint4*)&d_h2h[(size_t)w * 64 + sl * 4] = make_uint4(u[0], u[1], u[2], u[3]);
    }
}
__global__ void k_aggC(const float* __restrict__ bl) {
    __shared__ float smn[256], smx[256];
    int tid = threadIdx.x;
    int g = (blockIdx.x * 256 + tid) >> 4;
    int lane = tid & 15;
    float lmn = 3.4e38f, lmx = -3.4e38f;
    if (g < NN) {
        int beg = d_rowptr[g], end = d_rowptr[g + 1];
        const float4* pq = (const float4*)d_pq3;
        float4 acc = make_float4(0.f, 0.f, 0.f, 0.f);
#pragma unroll 4
        for (int e = beg; e < end; e++) {
            int s = __ldg(&d_csrc[e]);
            float4 v = pq[(size_t)s * 32 + lane];
            acc.x += v.x; acc.y += v.y; acc.z += v.z; acc.w += v.w;
        }
        float inv = 1.f / fmaxf((float)(end - beg), 1.0f);
        float4 q = pq[(size_t)g * 32 + 16 + lane];
        float4 b = ((const float4*)bl)[lane];
        float4 o;
        o.x = acc.x * inv + b.x + q.x;
        o.y = acc.y * inv + b.y + q.y;
        o.z = acc.z * inv + b.z + q.z;
        o.w = acc.w * inv + b.w + q.w;
        ((float4*)d_h3)[(size_t)g * 16 + lane] = o;
        lmn = fminf(fminf(o.x, o.y), fminf(o.z, o.w));
        lmx = fmaxf(fmaxf(o.x, o.y), fmaxf(o.z, o.w));
    }
    smn[tid] = lmn; smx[tid] = lmx;
    __syncthreads();
    for (int st = 128; st > 0; st >>= 1) {
        if (tid < st) {
            smn[tid] = fminf(smn[tid], smn[tid + st]);
            smx[tid] = fmaxf(smx[tid], smx[tid + st]);
        }
        __syncthreads();
    }
    if (tid == 0) { d_pmin[blockIdx.x] = smn[0]; d_pmax[blockIdx.x] = smx[0]; }
}

#define CPA(dst, src) \
    asm volatile("cp.async.cg.shared.global [%0], [%1], 16;" :: "r"(dst), "l"(src))
#define CPCOMMIT() asm volatile("cp.async.commit_group;" ::: "memory")
#define CPWAIT1() asm volatile("cp.async.wait_group 1;" ::: "memory")
#define CPWAIT0() asm volatile("cp.async.wait_group 0;" ::: "memory")

// ---------------- cp.async tf32 GEMM (fp32 in): GEMM4 + fused head ----------
// mode 0: plain store   mode 4: fused head (grid.x==1, cols 0..63 valid)
__global__ void __launch_bounds__(256, 2) k_tgemmA(
    const float* __restrict__ A, const float* __restrict__ B, float* __restrict__ C,
    int N, int K, const float* __restrict__ bias, int mode,
    const float* __restrict__ W2p, const float* __restrict__ b2p) {
    extern __shared__ float sm[];
    float* Asm = sm;
    float* Bsm = sm + 3 * 2560;
    int tid = threadIdx.x;
    int wid = tid >> 5;
    int bm = blockIdx.y * 128;
    int bn = blockIdx.x * 128;
    int wm = (wid >> 2) * 64;
    int wn = (wid & 3) * 32;
    int lrow = tid >> 1;
    int lcol = (tid & 1) * 8;
    int nkz = K / 16;

    const float* Ap = A + (size_t)(bm + lrow) * K + lcol;
    const float* Bp = B + (size_t)(bn + lrow) * K + lcol;
    unsigned aS = (unsigned)__cvta_generic_to_shared(Asm + lrow * 20 + lcol);
    unsigned bS = (unsigned)__cvta_generic_to_shared(Bsm + lrow * 20 + lcol);

#define ISSUE(s, koff)                                      \
    do {                                                    \
        unsigned _ao = aS + (s) * 10240;                    \
        unsigned _bo = bS + (s) * 10240;                    \
        CPA(_ao, Ap + (koff)); CPA(_ao + 16, Ap + (koff) + 4); \
        CPA(_bo, Bp + (koff)); CPA(_bo + 16, Bp + (koff) + 4); \
    } while (0)

    wmma::fragment<wmma::accumulator, 16, 16, 8, float> cf[4][2];
#pragma unroll
    for (int i = 0; i < 4; i++)
#pragma unroll
        for (int j = 0; j < 2; j++) wmma::fill_fragment(cf[i][j], 0.f);

    ISSUE(0, 0); CPCOMMIT();
    if (nkz > 1) { ISSUE(1, 16); CPCOMMIT(); }
    else CPCOMMIT();

    for (int it = 0; it < nkz; it++) {
        CPWAIT1();
        __syncthreads();
        if (it + 2 < nkz) ISSUE((it + 2) % 3, (it + 2) * 16);
        CPCOMMIT();
        int buf = it % 3;
        float* Ab = Asm + buf * 2560;
        float* Bb = Bsm + buf * 2560;
#pragma unroll
        for (int ks = 0; ks < 16; ks += 8) {
            wmma::fragment<wmma::matrix_a, 16, 16, 8, wmma::precision::tf32, wmma::row_major> af[4];
            wmma::fragment<wmma::matrix_b, 16, 16, 8, wmma::precision::tf32, wmma::col_major> bf[2];
#pragma unroll
            for (int i = 0; i < 4; i++)
                wmma::load_matrix_sync(af[i], Ab + (wm + i * 16) * 20 + ks, 20);
#pragma unroll
            for (int j = 0; j < 2; j++)
                wmma::load_matrix_sync(bf[j], Bb + (wn + j * 16) * 20 + ks, 20);
#pragma unroll
            for (int i = 0; i < 4; i++)
#pragma unroll
                for (int j = 0; j < 2; j++)
                    wmma::mma_sync(cf[i][j], af[i], bf[j], cf[i][j]);
        }
    }
    CPWAIT0();
    __syncthreads();

    if (mode == 0) {
#pragma unroll
        for (int i = 0; i < 4; i++)
#pragma unroll
            for (int j = 0; j < 2; j++)
                wmma::store_matrix_sync(&C[(size_t)(bm + wm + i * 16) * N + bn + wn + j * 16],
                                        cf[i][j], N, wmma::mem_row_major);
    } else {  // mode 4
        float* ybuf = sm;
        float* w2s = sm + 128 * 68;
        float* rv = w2s + 192;
        float* cts = rv + 64;
        if (wn < 64) {
#pragma unroll
            for (int i = 0; i < 4; i++)
#pragma unroll
                for (int j = 0; j < 2; j++)
                    wmma::store_matrix_sync(ybuf + (wm + i * 16) * 68 + wn + j * 16,
                                            cf[i][j], 68, wmma::mem_row_major);
        }
        if (tid < 192) w2s[tid] = W2p[tid];
        else if (tid < 195) cts[1 + tid - 192] = b2p[tid - 192];
        else if (tid == 195) cts[0] = bias[0];
        if (tid < 64) rv[tid] = d_rvec[tid];
        __syncthreads();
        if (tid < 128) {
            int row = bm + tid;
            if (row < NN) {
                float a = cts[0];
                float s0 = cts[1], s1 = cts[2], s2 = cts[3];
                const float* yr = ybuf + tid * 68;
#pragma unroll
                for (int f = 0; f < 64; f++) {
                    float v = fmaxf(a * yr[f] + rv[f], 0.f);
                    s0 += v * w2s[f];
                    s1 += v * w2s[64 + f];
                    s2 += v * w2s[128 + f];
                }
                float m = fmaxf(s0, fmaxf(s1, s2));
                float e0 = expf(s0 - m), e1 = expf(s1 - m), e2 = expf(s2 - m);
                float inv = 1.f / (e0 + e1 + e2);
                C[(size_t)row * 3 + 0] = e0 * inv;
                C[(size_t)row * 3 + 1] = e1 * inv;
                C[(size_t)row * 3 + 2] = e2 * inv;
            }
        }
    }
#undef ISSUE
}

// ---------------- cp.async bf16 GEMM (BK=32, 3-stage, split-K capable) --------
// mode 0: fp32 store   mode 2: blockIdx.x==0 -> bf16 pack to d_p2h, else fp32
// mode 3: split-K atomicAdd   mode 5: bias+relu+bf16 pack -> d_h1h
__global__ void __launch_bounds__(256, 2) k_tgemmH(
    const __nv_bfloat16* __restrict__ A, const __nv_bfloat16* __restrict__ B,
    float* __restrict__ C, int N, int K, const float* __restrict__ bias, int mode) {
    extern __shared__ float sm[];
    __nv_bfloat16* Asm = (__nv_bfloat16*)sm;                  // [3][128][40]
    __nv_bfloat16* Bsm = (__nv_bfloat16*)(sm + 3 * 2560);     // [3][128][40]
    int tid = threadIdx.x;
    int wid = tid >> 5;
    int lane = tid & 31;
    int bm = blockIdx.y * 128;
    int bn = blockIdx.x * 128;
    int wm = (wid >> 2) * 64;
    int wn = (wid & 3) * 32;
    int lrow = tid >> 1;
    int lcol = (tid & 1) * 16;
    int nkz = (K / 32) / gridDim.z;
    int kbase = blockIdx.z * nkz * 32;

    const __nv_bfloat16* Ap = A + (size_t)(bm + lrow) * K + kbase + lcol;
    const __nv_bfloat16* Bp = B + (size_t)(bn + lrow) * K + kbase + lcol;
    unsigned aS = (unsigned)__cvta_generic_to_shared(Asm + lrow * 40 + lcol);
    unsigned bS = (unsigned)__cvta_generic_to_shared(Bsm + lrow * 40 + lcol);

#define ISSUEH(s, koff)                                     \
    do {                                                    \
        unsigned _ao = aS + (s) * 10240;                    \
        unsigned _bo = bS + (s) * 10240;                    \
        CPA(_ao, Ap + (koff)); CPA(_ao + 16, Ap + (koff) + 8); \
        CPA(_bo, Bp + (koff)); CPA(_bo + 16, Bp + (koff) + 8); \
    } while (0)

    wmma::fragment<wmma::accumulator, 16, 16, 16, float> cf[4][2];
#pragma unroll
    for (int i = 0; i < 4; i++)
#pragma unroll
        for (int j = 0; j < 2; j++) wmma::fill_fragment(cf[i][j], 0.f);

    ISSUEH(0, 0); CPCOMMIT();
    if (nkz > 1) { ISSUEH(1, 32); CPCOMMIT(); }
    else CPCOMMIT();

    for (int it = 0; it < nkz; it++) {
        CPWAIT1();
        __syncthreads();
        if (it + 2 < nkz) ISSUEH((it + 2) % 3, (it + 2) * 32);
        CPCOMMIT();
        int buf = it % 3;
        __nv_bfloat16* Ab = Asm + buf * 5120;
        __nv_bfloat16* Bb = Bsm + buf * 5120;
#pragma unroll
        for (int ks = 0; ks < 32; ks += 16) {
            wmma::fragment<wmma::matrix_a, 16, 16, 16, __nv_bfloat16, wmma::row_major> af[4];
            wmma::fragment<wmma::matrix_b, 16, 16, 16, __nv_bfloat16, wmma::col_major> bf[2];
#pragma unroll
            for (int i = 0; i < 4; i++)
                wmma::load_matrix_sync(af[i], Ab + (wm + i * 16) * 40 + ks, 40);
#pragma unroll
            for (int j = 0; j < 2; j++)
                wmma::load_matrix_sync(bf[j], Bb + (wn + j * 16) * 40 + ks, 40);
#pragma unroll
            for (int i = 0; i < 4; i++)
#pragma unroll
                for (int j = 0; j < 2; j++)
                    wmma::mma_sync(cf[i][j], af[i], bf[j], cf[i][j]);
        }
    }
    CPWAIT0();
    __syncthreads();

    if (mode == 0 || (mode == 2 && blockIdx.x != 0)) {
#pragma unroll
        for (int i = 0; i < 4; i++)
#pragma unroll
            for (int j = 0; j < 2; j++)
                wmma::store_matrix_sync(&C[(size_t)(bm + wm + i * 16) * N + bn + wn + j * 16],
                                        cf[i][j], N, wmma::mem_row_major);
    } else if (mode == 2) {  // blockIdx.x == 0: pack p-half to d_p2h
        float* stage = sm + wid * 320;
        int r = lane >> 1, cu = (lane & 1) * 4;
#pragma unroll
        for (int i = 0; i < 4; i++)
#pragma unroll
            for (int j = 0; j < 2; j++) {
                wmma::store_matrix_sync(stage, cf[i][j], 20, wmma::mem_row_major);
                __syncwarp();
                const float* sp = stage + r * 20 + cu * 2;
                unsigned int o[4];
#pragma unroll
                for (int t = 0; t < 4; t++) {
                    __nv_bfloat162 h = __floats2bfloat162_rn(sp[2 * t], sp[2 * t + 1]);
                    o[t] = *(unsigned int*)&h;
                }
                *(uint4*)&d_p2h[(size_t)(bm + wm + i * 16 + r) * 64 +
                                ((wn + j * 16) >> 1) + cu] =
                    make_uint4(o[0], o[1], o[2], o[3]);
                __syncwarp();
            }
    } else if (mode == 3) {  // split-K atomic
        float* stage = sm + wid * 320;
#pragma unroll
        for (int i = 0; i < 4; i++)
#pragma unroll
            for (int j = 0; j < 2; j++) {
                wmma::store_matrix_sync(stage, cf[i][j], 20, wmma::mem_row_major);
                __syncwarp();
                float* cp = &C[(size_t)(bm + wm + i * 16) * N + bn + wn + j * 16];
#pragma unroll
                for (int e = 0; e < 8; e++) {
                    int idx = lane * 8 + e;
                    int r2 = idx >> 4, c2 = idx & 15;
                    atomicAdd(&cp[(size_t)r2 * N + c2], stage[r2 * 20 + c2]);
                }
                __syncwarp();
            }
    } else {  // mode 5: bias+relu, pack bf16 -> d_h1h
        float* stage = sm + wid * 320;
        int r = lane >> 1, cu = (lane & 1) * 4;
#pragma unroll
        for (int i = 0; i < 4; i++)
#pragma unroll
            for (int j = 0; j < 2; j++) {
                wmma::store_matrix_sync(stage, cf[i][j], 20, wmma::mem_row_major);
                __syncwarp();
                const float* sp = stage + r * 20 + cu * 2;
                const float* bp = bias + bn + wn + j * 16 + cu * 2;
                unsigned int o[4];
#pragma unroll
                for (int t = 0; t < 4; t++) {
                    float v0 = fmaxf(sp[2 * t] + bp[2 * t], 0.f);
                    float v1 = fmaxf(sp[2 * t + 1] + bp[2 * t + 1], 0.f);
                    __nv_bfloat162 h = __floats2bfloat162_rn(v0, v1);
                    o[t] = *(unsigned int*)&h;
                }
                *(uint4*)&d_h1h[(size_t)(bm + wm + i * 16 + r) * 128 +
                                ((bn + wn + j * 16) >> 1) + cu] =
                    make_uint4(o[0], o[1], o[2], o[3]);
                __syncwarp();
            }
    }
#undef ISSUEH
}

// ---------------- map encoder ----------------
__global__ void k_conv1(const float* __restrict__ in, const float* __restrict__ w,
                        const float* __restrict__ b) {
    int idx = blockIdx.x * blockDim.x + threadIdx.x;
    if (idx >= 256 * 1573) return;
    int oc = idx / 1573, p = idx % 1573;
    int od = p / 121, r = p % 121, oh = r / 11, ow = r % 11;
    const float* wp = w + oc * 75;
    float acc = 0.f;
#pragma unroll
    for (int kd = 0; kd < 3; kd++)
#pragma unroll
        for (int kh = 0; kh < 5; kh++)
#pragma unroll
            for (int kw = 0; kw < 5; kw++)
                acc += in[(od + kd) * 225 + (oh + kh) * 15 + (ow + kw)] *
                       wp[kd * 25 + kh * 5 + kw];
    d_m1[idx] = fmaxf(acc + b[oc], 0.f);
}

__global__ void k_im2col() {
    int k = blockIdx.x * 256 + threadIdx.x;
    int pos = blockIdx.y;
    d_xcolh[(size_t)pos * 6912 + k] = __float2bfloat16(d_m1[d_koff[k] + d_poff[pos]]);
}

__global__ void k_m2fin(const float* __restrict__ cb2) {
    int idx = blockIdx.x * blockDim.x + threadIdx.x;
    if (idx >= 128 * 891) return;
    int oc = idx / 891, pos = idx % 891;
    d_m2[idx] = fmaxf(d_cg[(size_t)pos * 128 + oc] + cb2[oc], 0.f);
}

__global__ void k_wm(const float* __restrict__ Wm) {
    __shared__ float red[256];
    int o = blockIdx.x;
    int chunk = blockIdx.y;
    const int CH = 114048 / 8;
    int base = chunk * CH;
    const float* wr = Wm + (size_t)o * 114048 + base;
    const float* mv = d_m2 + base;
    float s = 0.f;
    for (int i = threadIdx.x * 4; i < CH; i += 256 * 4) {
        float4 a = *(const float4*)(wr + i);
        float4 v = *(const float4*)(mv + i);
        s += a.x * v.x + a.y * v.y + a.z * v.z + a.w * v.w;
    }
    red[threadIdx.x] = s;
    __syncthreads();
    for (int st = 128; st > 0; st >>= 1) {
        if (threadIdx.x < st) red[threadIdx.x] += red[threadIdx.x + st];
        __syncthreads();
    }
    if (threadIdx.x == 0) d_wmpart[chunk][o] = red[0];
}

// ---------------- final stats + rvec ----------------
__global__ void k_finstats(const float* __restrict__ bm, const float* __restrict__ b1) {
    __shared__ float smn[256], smx[256];
    __shared__ float mloc[64];
    int t = threadIdx.x;
    float mn = 3.4e38f, mx = -3.4e38f;
    for (int i = t; i < NBC; i += 256) {
        mn = fminf(mn, d_pmin[i]);
        mx = fmaxf(mx, d_pmax[i]);
    }
    smn[t] = mn; smx[t] = mx;
    __syncthreads();
    for (int st = 128; st > 0; st >>= 1) {
        if (t < st) {
            smn[t] = fminf(smn[t], smn[t + st]);
            smx[t] = fmaxf(smx[t], smx[t + st]);
        }
        __syncthreads();
    }
    float hs1v;
    {
        float lo = smn[0], hi = smx[0];
        float a = 0.35f / (hi - lo);
        hs1v = -lo * a;
        if (t == 0) {
            d_hstats[0] = a;
            d_hstats[1] = hs1v;
        }
    }
    __syncthreads();
    float v = 0.f;
    if (t < 64) {
        v = bm[t];
#pragma unroll
        for (int c = 0; c < 8; c++) v += d_wmpart[c][t];
    }
    smn[t] = (t < 64) ? v : 3.4e38f;
    smx[t] = (t < 64) ? v : -3.4e38f;
    __syncthreads();
    for (int st = 128; st > 0; st >>= 1) {
        if (t < st) {
            smn[t] = fminf(smn[t], smn[t + st]);
            smx[t] = fmaxf(smx[t], smx[t + st]);
        }
        __syncthreads();
    }
    if (t < 64) {
        float lo = smn[0], hi = smx[0];
        float m = 0.65f * (v - lo) / (hi - lo);
        d_mnorm[t] = m;
        mloc[t] = m;
    }
    __syncthreads();
    if (t < 64) {
        float s = b1[t];
        const float* wr = d_w1p + t * 64;
#pragma unroll 8
        for (int k = 0; k < 64; k++) s += wr[k] * (hs1v + mloc[k]);
        d_rvec[t] = s;
    }
}

// ---------------- launch ----------------
extern "C" void kernel_launch(void* const* d_in, const int* in_sizes, int n_in,
                              void* d_out, int out_size) {
    (void)in_sizes; (void)n_in; (void)out_size;
    const float* node = (const float*)d_in[0];
    const int* ei = (const int*)d_in[1];
    const float* mapd = (const float*)d_in[2];
    const float* bl1 = (const float*)d_in[4];
    const float* bl2 = (const float*)d_in[7];
    const float* bl3 = (const float*)d_in[10];
    const float* k1 = (const float*)d_in[12];
    const float* cb1 = (const float*)d_in[13];
    const float* k2 = (const float*)d_in[14];
    const float* cb2 = (const float*)d_in[15];
    const float* Wm = (const float*)d_in[16];
    const float* bm = (const float*)d_in[17];
    const float* b1 = (const float*)d_in[19];
    const float* W2 = (const float*)d_in[20];
    const float* b2 = (const float*)d_in[21];
    float* out = (float*)d_out;

    cudaFuncSetAttribute(k_tgemmA, cudaFuncAttributeMaxDynamicSharedMemorySize, TGA_SMEM);
    cudaFuncSetAttribute(k_tgemmH, cudaFuncAttributeMaxDynamicSharedMemorySize, TGA_SMEM);

    void *p_cnt, *p_cg;
    void *p_mxh, *p_wc1h, *p_h1h, *p_wc2h, *p_pq2, *p_h2h, *p_wc3h, *p_pq3, *p_h3;
    void *p_w1p, *p_xcolh, *p_k2h, *p_hstats;
    cudaGetSymbolAddress(&p_cnt, d_cnt);
    cudaGetSymbolAddress(&p_cg, d_cg);
    cudaGetSymbolAddress(&p_mxh, d_mxh);
    cudaGetSymbolAddress(&p_wc1h, d_wc1h);
    cudaGetSymbolAddress(&p_h1h, d_h1h);
    cudaGetSymbolAddress(&p_wc2h, d_wc2h);
    cudaGetSymbolAddress(&p_pq2, d_pq2);
    cudaGetSymbolAddress(&p_h2h, d_h2h);
    cudaGetSymbolAddress(&p_wc3h, d_wc3h);
    cudaGetSymbolAddress(&p_pq3, d_pq3);
    cudaGetSymbolAddress(&p_h3, d_h3);
    cudaGetSymbolAddress(&p_w1p, d_w1p);
    cudaGetSymbolAddress(&p_xcolh, d_xcolh);
    cudaGetSymbolAddress(&p_k2h, d_k2h);
    cudaGetSymbolAddress(&p_hstats, d_hstats);

    cudaStream_t s2;
    cudaStreamCreateWithFlags(&s2, cudaStreamNonBlocking);
    cudaEvent_t evFork, evJoin;
    cudaEventCreateWithFlags(&evFork, cudaEventDisableTiming);
    cudaEventCreateWithFlags(&evJoin, cudaEventDisableTiming);

    // 1: memset(cnt)  2: memset(cg)  3: packAll
    cudaMemsetAsync(p_cnt, 0, NN * sizeof(int));
    cudaMemsetAsync(p_cg, 0, 896 * 128 * sizeof(float));
    k_packAll<<<447, 256>>>((const float*)d_in[3], (const float*)d_in[5],
                            (const float*)d_in[6], (const float*)d_in[8],
                            (const float*)d_in[9], (const float*)d_in[11],
                            (const float*)d_in[18]);

    // fork conv path onto s2
    cudaEventRecord(evFork, 0);
    cudaStreamWaitEvent(s2, evFork, 0);

    // conv path on s2
    k_packK2<<<(128 * 6912 + 255) / 256, 256, 0, s2>>>(k2);
    k_conv1<<<(256 * 1573 + 255) / 256, 256, 0, s2>>>(mapd, k1, cb1);
    k_im2col<<<dim3(27, 891), 256, 0, s2>>>();
    k_tgemmH<<<dim3(1, 7, 24), 256, TGA_SMEM, s2>>>((const __nv_bfloat16*)p_xcolh,
                                                    (const __nv_bfloat16*)p_k2h,
                                                    (float*)p_cg, 128, 6912,
                                                    nullptr, 3);
    k_m2fin<<<(128 * 891 + 255) / 256, 256, 0, s2>>>(cb2);
    k_wm<<<dim3(64, 8), 256, 0, s2>>>(Wm);
    cudaEventRecord(evJoin, s2);

    // GNN path on main stream
    k_degcnt<<<(NN * 32 + 255) / 256, 256>>>(ei, node);
    k_scan1<<<NB1, 256>>>();
    k_scan3<<<NB1, 256>>>();
    k_scatter<<<(NE + 255) / 256, 256>>>(ei);

    k_aggA<<<(NN * 32 + 255) / 256, 256>>>();
    // GEMM1 (bf16, K=64): epilogue bias+relu+bf16 pack -> d_h1h
    k_tgemmH<<<dim3(2, 391, 1), 256, TGA_SMEM>>>((const __nv_bfloat16*)p_mxh,
                                                 (const __nv_bfloat16*)p_wc1h,
                                                 nullptr, 256, 64, bl1, 5);
    // GEMM2 (bf16): p-half packed to d_p2h, q-half fp32 to pq2
    k_tgemmH<<<dim3(2, 391, 1), 256, TGA_SMEM>>>((const __nv_bfloat16*)p_h1h,
                                                 (const __nv_bfloat16*)p_wc2h,
                                                 (float*)p_pq2, 256, 256, nullptr, 2);
    k_aggB<<<(NN * 32 + 255) / 256, 256>>>(bl2);
    // GEMM3 (bf16): fp32 out
    k_tgemmH<<<dim3(1, 391, 1), 256, TGA_SMEM>>>((const __nv_bfloat16*)p_h2h,
                                                 (const __nv_bfloat16*)p_wc3h,
                                                 (float*)p_pq3, 128, 128, nullptr, 0);
    k_aggC<<<NBC, 256>>>(bl3);

    // join conv path before finstats
    cudaStreamWaitEvent(0, evJoin, 0);
    k_finstats<<<1, 256>>>(bm, b1);
    // GEMM4 (tf32) + fused head
    k_tgemmA<<<dim3(1, 391, 1), 256, TGA_SMEM>>>((const float*)p_h3, (const float*)p_w1p,
                                                 out, 128, 64, (const float*)p_hstats, 4,
                                                 W2, b2);

    cudaEventDestroy(evFork);
    cudaEventDestroy(evJoin);
    cudaStreamDestroy(s2);
}